// round 1
// baseline (speedup 1.0000x reference)
#include <cuda_runtime.h>
#include <math.h>

// Problem shape (fixed for this dataset entry)
#define Bb 4
#define Ll 16384
#define Cc 512
#define Hh 8
#define Dd 64
#define MM (Bb*Ll)      // 65536 rows
#define BH (Bb*Hh)      // 32 (batch,head) pairs

// Scratch: feature-mapped Q, K and raw V in [B,L,H,D] == [M, C] row-major
__device__ float g_Q[(size_t)MM*Cc];
__device__ float g_K[(size_t)MM*Cc];
__device__ float g_V[(size_t)MM*Cc];
__device__ float g_KV[BH*Dd*Dd];
__device__ float g_Ksum[BH*Dd];

// ---------------------------------------------------------------------------
// Zero accumulators (must rerun every graph replay)
// ---------------------------------------------------------------------------
__global__ void zero_acc_kernel() {
    int i = blockIdx.x * blockDim.x + threadIdx.x;
    if (i < BH*Dd*Dd) g_KV[i] = 0.f;
    if (i < BH*Dd)    g_Ksum[i] = 0.f;
}

// ---------------------------------------------------------------------------
// Stage 1: fused QKV projection GEMM.
// grid = (M/128, C/128, 3); z selects W/bias/output + feature-map epilogue.
// 128x128 tile, BK=8, 256 threads, 8x8 register tile.
// ---------------------------------------------------------------------------
__global__ __launch_bounds__(256) void qkv_gemm(
    const float* __restrict__ X,
    const float* __restrict__ Wq, const float* __restrict__ bq,
    const float* __restrict__ Wk, const float* __restrict__ bk,
    const float* __restrict__ Wv, const float* __restrict__ bv)
{
    const int z = blockIdx.z;
    const float* __restrict__ W    = (z == 0) ? Wq : ((z == 1) ? Wk : Wv);
    const float* __restrict__ bias = (z == 0) ? bq : ((z == 1) ? bk : bv);
    float* __restrict__ outp       = (z == 0) ? g_Q : ((z == 1) ? g_K : g_V);

    __shared__ float As[8][128];   // transposed: As[k][m]
    __shared__ float Bs[8][128];   // Bs[k][n]

    const int tid = threadIdx.x;
    const int tx = tid & 15;       // n direction (x8)
    const int ty = tid >> 4;       // m direction (x8)
    const int row0 = blockIdx.x * 128;
    const int col0 = blockIdx.y * 128;

    // A tile load mapping: 128 rows x 8 k -> one float4 per thread
    const int a_m = tid >> 1;
    const int a_k = (tid & 1) << 2;
    // B tile load mapping: 8 k x 128 n -> one float4 per thread
    const int b_k = tid >> 5;
    const int b_n = (tid & 31) << 2;

    float acc[8][8];
#pragma unroll
    for (int i = 0; i < 8; i++)
#pragma unroll
        for (int j = 0; j < 8; j++) acc[i][j] = 0.f;

    const float* Aptr  = X + (size_t)(row0 + a_m) * Cc + a_k;
    const float* Bptr0 = W + (size_t)b_k * Cc + col0 + b_n;

    for (int k0 = 0; k0 < Cc; k0 += 8) {
        float4 av  = *reinterpret_cast<const float4*>(Aptr + k0);
        float4 bv4 = *reinterpret_cast<const float4*>(Bptr0 + (size_t)k0 * Cc);
        As[a_k + 0][a_m] = av.x;
        As[a_k + 1][a_m] = av.y;
        As[a_k + 2][a_m] = av.z;
        As[a_k + 3][a_m] = av.w;
        *reinterpret_cast<float4*>(&Bs[b_k][b_n]) = bv4;
        __syncthreads();
#pragma unroll
        for (int k = 0; k < 8; ++k) {
            float a[8], bb[8];
            *reinterpret_cast<float4*>(a)      = *reinterpret_cast<const float4*>(&As[k][ty * 8]);
            *reinterpret_cast<float4*>(a + 4)  = *reinterpret_cast<const float4*>(&As[k][ty * 8 + 4]);
            *reinterpret_cast<float4*>(bb)     = *reinterpret_cast<const float4*>(&Bs[k][tx * 8]);
            *reinterpret_cast<float4*>(bb + 4) = *reinterpret_cast<const float4*>(&Bs[k][tx * 8 + 4]);
#pragma unroll
            for (int i = 0; i < 8; i++)
#pragma unroll
                for (int j = 0; j < 8; j++)
                    acc[i][j] = fmaf(a[i], bb[j], acc[i][j]);
        }
        __syncthreads();
    }

    // Epilogue: +bias, feature map (elu(x)+1) for Q and K
#pragma unroll
    for (int i = 0; i < 8; i++) {
        const int m = row0 + ty * 8 + i;
        float* orow = outp + (size_t)m * Cc + col0 + tx * 8;
#pragma unroll
        for (int j = 0; j < 8; j += 4) {
            float4 val;
            float* vp = &val.x;
#pragma unroll
            for (int q = 0; q < 4; q++) {
                float vfull = acc[i][j + q] + bias[col0 + tx * 8 + j + q];
                if (z < 2) vfull = (vfull > 0.f) ? (vfull + 1.f) : expf(vfull);
                vp[q] = vfull;
            }
            *reinterpret_cast<float4*>(orow + j) = val;
        }
    }
}

// ---------------------------------------------------------------------------
// Stage 2: KV[b,h][d][v] = sum_s K[b,s,h,d] * V[b,s,h,v]; Ksum[b,h][d] = sum_s K.
// grid = (BH, L/128); each block accumulates a 128-step chunk and atomicAdds.
// ---------------------------------------------------------------------------
__global__ __launch_bounds__(256) void kv_reduce() {
    const int bh = blockIdx.x;
    const int chunk = blockIdx.y;
    const int b = bh >> 3, h = bh & 7;
    const float* __restrict__ Kbase = g_K + ((size_t)b * Ll) * Cc + h * Dd;
    const float* __restrict__ Vbase = g_V + ((size_t)b * Ll) * Cc + h * Dd;

    __shared__ float Ks[8][64];
    __shared__ float Vs[8][64];

    const int tid = threadIdx.x;
    const int d  = tid >> 2;          // 0..63
    const int v0 = (tid & 3) << 4;    // 0,16,32,48

    // load mapping: 8 rows x 64 floats for K and V = 256 float4
    const int mat = tid >> 7;         // 0:K 1:V
    const int li  = tid & 127;
    const int lr  = li >> 4;          // row 0..7
    const int lc  = (li & 15) << 2;   // col

    float acc[16];
#pragma unroll
    for (int j = 0; j < 16; j++) acc[j] = 0.f;
    float ksum = 0.f;

    const int s0 = chunk * 128;
    for (int st = 0; st < 128; st += 8) {
        const float* src = (mat ? Vbase : Kbase) + (size_t)(s0 + st + lr) * Cc + lc;
        float4 val = *reinterpret_cast<const float4*>(src);
        float* dst = mat ? &Vs[lr][lc] : &Ks[lr][lc];
        *reinterpret_cast<float4*>(dst) = val;
        __syncthreads();
#pragma unroll
        for (int r = 0; r < 8; ++r) {
            float kd = Ks[r][d];
            ksum += kd;
#pragma unroll
            for (int j = 0; j < 16; j++)
                acc[j] = fmaf(kd, Vs[r][v0 + j], acc[j]);
        }
        __syncthreads();
    }

    float* KVp = g_KV + (size_t)bh * Dd * Dd + d * Dd + v0;
#pragma unroll
    for (int j = 0; j < 16; j++) atomicAdd(KVp + j, acc[j]);
    if ((tid & 3) == 0) atomicAdd(g_Ksum + bh * Dd + d, ksum);
}

// ---------------------------------------------------------------------------
// Stage 3: out[b,l,h,:] = (Q[b,l,h,:] @ KV[b,h]) * Z,  Z = 1/(Q·Ksum + eps).
// grid = (BH, L/64); KV + Q tile staged in shared, 4x4 register tile / thread.
// ---------------------------------------------------------------------------
__global__ __launch_bounds__(256) void out_kernel(float* __restrict__ out) {
    const int bh = blockIdx.x;
    const int lt = blockIdx.y;
    const int b = bh >> 3, h = bh & 7;
    const int l0 = lt * 64;

    __shared__ float KVs[64][64];
    __shared__ float Qs[64][64];
    __shared__ float Ksum_s[64];
    __shared__ float Zs[64];

    const int tid = threadIdx.x;

    // load KV tile: 4096 floats = 1024 float4
    {
        const float* src = g_KV + (size_t)bh * 4096;
#pragma unroll
        for (int i = 0; i < 4; i++) {
            int idx = (tid + i * 256) * 4;
            float4 v = *reinterpret_cast<const float4*>(src + idx);
            *reinterpret_cast<float4*>(&KVs[0][0] + idx) = v;
        }
        if (tid < 64) Ksum_s[tid] = g_Ksum[bh * 64 + tid];
    }
    // load Q tile: 64 rows x 64 floats
    {
        const float* qb = g_Q + ((size_t)b * Ll + l0) * Cc + h * Dd;
#pragma unroll
        for (int i = 0; i < 4; i++) {
            int fi = tid + i * 256;        // float4 index 0..1023
            int r  = fi >> 4;              // 16 float4 per row
            int c  = (fi & 15) << 2;
            float4 v = *reinterpret_cast<const float4*>(qb + (size_t)r * Cc + c);
            *reinterpret_cast<float4*>(&Qs[r][c]) = v;
        }
    }
    __syncthreads();

    // per-row normalizer
    if (tid < 64) {
        float s = 0.f;
#pragma unroll
        for (int dd = 0; dd < 64; dd++) s = fmaf(Qs[tid][dd], Ksum_s[dd], s);
        Zs[tid] = 1.f / (s + 1e-6f);
    }
    __syncthreads();

    const int tv = tid & 15;   // v direction (x4)
    const int tl = tid >> 4;   // l direction (x4)
    float acc[4][4];
#pragma unroll
    for (int i = 0; i < 4; i++)
#pragma unroll
        for (int j = 0; j < 4; j++) acc[i][j] = 0.f;

#pragma unroll 8
    for (int dd = 0; dd < 64; dd++) {
        float bb[4];
        *reinterpret_cast<float4*>(bb) = *reinterpret_cast<const float4*>(&KVs[dd][tv * 4]);
#pragma unroll
        for (int i = 0; i < 4; i++) {
            float a = Qs[tl * 4 + i][dd];
#pragma unroll
            for (int j = 0; j < 4; j++)
                acc[i][j] = fmaf(a, bb[j], acc[i][j]);
        }
    }

#pragma unroll
    for (int i = 0; i < 4; i++) {
        int l = tl * 4 + i;
        float zz = Zs[l];
        float4 o;
        o.x = acc[i][0] * zz;
        o.y = acc[i][1] * zz;
        o.z = acc[i][2] * zz;
        o.w = acc[i][3] * zz;
        float* op = out + ((size_t)b * Ll + l0 + l) * Cc + h * Dd + tv * 4;
        *reinterpret_cast<float4*>(op) = o;
    }
}

// ---------------------------------------------------------------------------
extern "C" void kernel_launch(void* const* d_in, const int* in_sizes, int n_in,
                              void* d_out, int out_size) {
    const float* x  = (const float*)d_in[0];
    const float* Wq = (const float*)d_in[1];
    const float* bq = (const float*)d_in[2];
    const float* Wk = (const float*)d_in[3];
    const float* bk = (const float*)d_in[4];
    const float* Wv = (const float*)d_in[5];
    const float* bv = (const float*)d_in[6];
    float* out = (float*)d_out;

    zero_acc_kernel<<<(BH * Dd * Dd + 255) / 256, 256>>>();
    qkv_gemm<<<dim3(MM / 128, Cc / 128, 3), 256>>>(x, Wq, bq, Wk, bk, Wv, bv);
    kv_reduce<<<dim3(BH, Ll / 128), 256>>>();
    out_kernel<<<dim3(BH, Ll / 64), 256>>>(out);
}

// round 3
// speedup vs baseline: 2.6552x; 2.6552x over previous
#include <cuda_runtime.h>
#include <cuda_bf16.h>
#include <cstdint>
#include <math.h>

#define Bb 4
#define Ll 16384
#define Cc 512
#define Hh 8
#define Dd 64
#define MM (Bb*Ll)      // 65536
#define BHn (Bb*Hh)     // 32

#define BM 128
#define BN 128
#define BK 64           // bf16 elems per k-chunk
#define STAGES 3
#define STAGE_BYTES 65536           // Ah 16K | Al 16K | Bh 16K | Bl 16K
#define SMEM_TOTAL (STAGES*STAGE_BYTES)

// Scratch
__device__ __nv_bfloat16 g_Xh[(size_t)MM*Cc];
__device__ __nv_bfloat16 g_Xl[(size_t)MM*Cc];
__device__ __nv_bfloat16 g_Wth[3*(size_t)Cc*Cc];  // W^T hi, [z][n][k]
__device__ __nv_bfloat16 g_Wtl[3*(size_t)Cc*Cc];  // W^T lo
__device__ float g_Q [(size_t)MM*Cc];             // feature-mapped Q row-major
__device__ float g_K [(size_t)MM*Cc];             // feature-mapped K row-major
__device__ float g_V [(size_t)MM*Cc];             // raw V row-major
__device__ float g_Qt[(size_t)BHn*Dd*Ll];         // Q transposed [bh][d][l]
__device__ float g_KV[BHn*Dd*Dd];
__device__ float g_Ksum[BHn*Dd];

// ---------------------------------------------------------------------------
__device__ __forceinline__ uint32_t smem_u32(const void* p) {
    uint32_t a;
    asm("{ .reg .u64 t; cvta.to.shared.u64 t, %1; cvt.u32.u64 %0, t; }" : "=r"(a) : "l"(p));
    return a;
}
#define SWZ128(o) ((o) ^ (((o) >> 3) & 0x70))

__device__ __forceinline__ void cpa16(uint32_t d, const void* s) {
    uint64_t gp;
    asm("cvta.to.global.u64 %0, %1;" : "=l"(gp) : "l"(s));
    asm volatile("cp.async.cg.shared.global [%0], [%1], 16;" :: "r"(d), "l"(gp) : "memory");
}
__device__ __forceinline__ void cp_commit() {
    asm volatile("cp.async.commit_group;" ::: "memory");
}
template<int N> __device__ __forceinline__ void cp_wait() {
    asm volatile("cp.async.wait_group %0;" :: "n"(N) : "memory");
}
__device__ __forceinline__ void ldm4(uint32_t* r, uint32_t a) {
    asm volatile("ldmatrix.sync.aligned.m8n8.x4.shared.b16 {%0,%1,%2,%3}, [%4];"
        : "=r"(r[0]), "=r"(r[1]), "=r"(r[2]), "=r"(r[3]) : "r"(a));
}
__device__ __forceinline__ void mma16816(float* c, const uint32_t* a, const uint32_t* b) {
    asm volatile("mma.sync.aligned.m16n8k16.row.col.f32.bf16.bf16.f32 "
        "{%0,%1,%2,%3}, {%4,%5,%6,%7}, {%8,%9}, {%0,%1,%2,%3};"
        : "+f"(c[0]), "+f"(c[1]), "+f"(c[2]), "+f"(c[3])
        : "r"(a[0]), "r"(a[1]), "r"(a[2]), "r"(a[3]), "r"(b[0]), "r"(b[1]));
}
__device__ __forceinline__ uint32_t pack_bf16(__nv_bfloat16 a, __nv_bfloat16 b) {
    __nv_bfloat162 t(a, b);
    return *reinterpret_cast<uint32_t*>(&t);
}

// ---------------------------------------------------------------------------
__global__ void zero_acc_kernel() {
    int i = blockIdx.x * blockDim.x + threadIdx.x;
    if (i < BHn * Dd * Dd) g_KV[i] = 0.f;
    if (i < BHn * Dd)      g_Ksum[i] = 0.f;
}

// Split X -> bf16 hi/lo
__global__ void prep_x(const float* __restrict__ X) {
    size_t i = ((size_t)blockIdx.x * 256 + threadIdx.x) * 4;
    float4 v = *reinterpret_cast<const float4*>(X + i);
    const float* vp = &v.x;
    __nv_bfloat16 h[4], l[4];
#pragma unroll
    for (int q = 0; q < 4; q++) {
        h[q] = __float2bfloat16(vp[q]);
        l[q] = __float2bfloat16(vp[q] - __bfloat162float(h[q]));
    }
    *reinterpret_cast<uint2*>(g_Xh + i) = make_uint2(pack_bf16(h[0], h[1]), pack_bf16(h[2], h[3]));
    *reinterpret_cast<uint2*>(g_Xl + i) = make_uint2(pack_bf16(l[0], l[1]), pack_bf16(l[2], l[3]));
}

// Split W -> bf16 hi/lo, transposed [z][n][k]
__global__ void prep_w(const float* __restrict__ Wq, const float* __restrict__ Wk,
                       const float* __restrict__ Wv) {
    const int z = blockIdx.x, n = blockIdx.y;
    const float* W = (z == 0) ? Wq : ((z == 1) ? Wk : Wv);
    __nv_bfloat16* dh = g_Wth + ((size_t)z * Cc + n) * Cc;
    __nv_bfloat16* dl = g_Wtl + ((size_t)z * Cc + n) * Cc;
    int k0 = threadIdx.x * 4;
#pragma unroll
    for (int j = 0; j < 4; j++) {
        float x = W[(size_t)(k0 + j) * Cc + n];
        __nv_bfloat16 h = __float2bfloat16(x);
        __nv_bfloat16 l = __float2bfloat16(x - __bfloat162float(h));
        dh[k0 + j] = h;
        dl[k0 + j] = l;
    }
}

// ---------------------------------------------------------------------------
// QKV projection: bf16 3-pass split GEMM via mma.sync + cp.async pipeline.
// grid=(12, MM/128): x = ntile(4) x z(3) so adjacent blocks share A slab in L2.
// ---------------------------------------------------------------------------
__global__ __launch_bounds__(256, 1) void qkv_gemm_tc(
    const float* __restrict__ bq, const float* __restrict__ bk,
    const float* __restrict__ bv)
{
    extern __shared__ char smem[];
    const uint32_t sbase = smem_u32(smem);
    const int tid = threadIdx.x;
    const int nz = blockIdx.x;
    const int z = nz >> 2;
    const int col0 = (nz & 3) * BN;
    const int row0 = blockIdx.y * BM;

    const __nv_bfloat16* __restrict__ Bh_g = g_Wth + (size_t)z * Cc * Cc;
    const __nv_bfloat16* __restrict__ Bl_g = g_Wtl + (size_t)z * Cc * Cc;
    const float* __restrict__ bias = (z == 0) ? bq : ((z == 1) ? bk : bv);
    float* __restrict__ outp = (z == 0) ? g_Q : ((z == 1) ? g_K : g_V);

    auto issue = [&](int kidx, int buf) {
        uint32_t sb = sbase + buf * STAGE_BYTES;
        int k0 = kidx * BK;
#pragma unroll
        for (int r = 0; r < 4; r++) {
            int q = tid + r * 256;            // 0..1023
            int m = q >> 3, c = q & 7;
            uint32_t off = SWZ128((uint32_t)(m * 128 + c * 16));
            size_t asrc = (size_t)(row0 + m) * Cc + k0 + c * 8;
            size_t bsrc = (size_t)(col0 + m) * Cc + k0 + c * 8;
            cpa16(sb + off,         g_Xh + asrc);
            cpa16(sb + 16384 + off, g_Xl + asrc);
            cpa16(sb + 32768 + off, Bh_g + bsrc);
            cpa16(sb + 49152 + off, Bl_g + bsrc);
        }
        cp_commit();
    };

    issue(0, 0);
    issue(1, 1);

    const int lane = tid & 31, wid = tid >> 5;
    const int wm = (wid & 3) * 32;
    const int wn = (wid >> 2) * 64;
    const int arow = wm + (lane & 15);
    const uint32_t a_base = (uint32_t)arow * 128;
    const uint32_t a_xor  = (uint32_t)((arow & 7) * 16);
    const uint32_t a_k    = (uint32_t)((lane >> 4) * 16);
    const int brow = wn + (lane & 7) + ((lane >> 4) << 3);
    const uint32_t b_base = (uint32_t)brow * 128 + 32768;
    const uint32_t b_xor  = (uint32_t)((brow & 7) * 16);
    const uint32_t b_k    = (uint32_t)(((lane >> 3) & 1) * 16);

    float acc[2][8][4];
#pragma unroll
    for (int i = 0; i < 2; i++)
#pragma unroll
        for (int j = 0; j < 8; j++)
#pragma unroll
            for (int q = 0; q < 4; q++) acc[i][j][q] = 0.f;

    const int NIT = Cc / BK;  // 8
    for (int it = 0; it < NIT; it++) {
        cp_wait<1>();
        __syncthreads();
        if (it + 2 < NIT) issue(it + 2, (it + 2) % STAGES);
        else cp_commit();

        uint32_t sb = sbase + (it % STAGES) * STAGE_BYTES;
#pragma unroll
        for (int ks = 0; ks < 4; ks++) {
            uint32_t ka = ((uint32_t)(ks * 32) + a_k) ^ a_xor;
            uint32_t kb = ((uint32_t)(ks * 32) + b_k) ^ b_xor;
            uint32_t ah0[4], ah1[4], al0[4], al1[4];
            ldm4(ah0, sb + a_base + ka);
            ldm4(ah1, sb + a_base + 2048 + ka);
            ldm4(al0, sb + 16384 + a_base + ka);
            ldm4(al1, sb + 16384 + a_base + 2048 + ka);
            uint32_t bhf[4][4], blf[4][4];
#pragma unroll
            for (int g = 0; g < 4; g++) {
                ldm4(bhf[g], sb + b_base + g * 2048 + kb);
                ldm4(blf[g], sb + 16384 + b_base + g * 2048 + kb);
            }
#pragma unroll
            for (int j = 0; j < 8; j++) {
                const uint32_t* bh = &bhf[j >> 1][(j & 1) * 2];
                const uint32_t* bl = &blf[j >> 1][(j & 1) * 2];
                mma16816(acc[0][j], ah0, bh);   // Ah*Bh
                mma16816(acc[1][j], ah1, bh);
                mma16816(acc[0][j], al0, bh);   // Al*Bh
                mma16816(acc[1][j], al1, bh);
                mma16816(acc[0][j], ah0, bl);   // Ah*Bl
                mma16816(acc[1][j], ah1, bl);
            }
        }
        __syncthreads();
    }

    // Epilogue: bias + feature map (Q,K), row-major float2 stores
    const int gq = lane >> 2, tq = lane & 3;
#pragma unroll
    for (int im = 0; im < 2; im++) {
#pragma unroll
        for (int hh = 0; hh < 2; hh++) {
            int mg = row0 + wm + im * 16 + gq + hh * 8;
            float* orow = outp + (size_t)mg * Cc;
#pragma unroll
            for (int j = 0; j < 8; j++) {
                int cg = col0 + wn + j * 8 + tq * 2;
                float v0 = acc[im][j][hh * 2 + 0] + __ldg(bias + cg);
                float v1 = acc[im][j][hh * 2 + 1] + __ldg(bias + cg + 1);
                if (z < 2) {
                    v0 = (v0 > 0.f) ? (v0 + 1.f) : __expf(v0);
                    v1 = (v1 > 0.f) ? (v1 + 1.f) : __expf(v1);
                }
                *reinterpret_cast<float2*>(orow + cg) = make_float2(v0, v1);
            }
        }
    }
}

// ---------------------------------------------------------------------------
// Transpose Q row-major [b,l,h,d] -> g_Qt [bh][d][l]
// ---------------------------------------------------------------------------
__global__ __launch_bounds__(256) void q_transpose() {
    const int bh = blockIdx.x, l0 = blockIdx.y * 64;
    const int b = bh >> 3, h = bh & 7;
    __shared__ float t[64 * 65];
    const int tid = threadIdx.x;
    const float* src = g_Q + ((size_t)b * Ll + l0) * Cc + h * Dd;
#pragma unroll
    for (int i = 0; i < 4; i++) {
        int f = tid + i * 256;
        int r = f >> 4, c = (f & 15) * 4;
        float4 v = *reinterpret_cast<const float4*>(src + (size_t)r * Cc + c);
        t[r * 65 + c + 0] = v.x;
        t[r * 65 + c + 1] = v.y;
        t[r * 65 + c + 2] = v.z;
        t[r * 65 + c + 3] = v.w;
    }
    __syncthreads();
    float* dst = g_Qt + (size_t)bh * Dd * Ll + l0;
#pragma unroll
    for (int i = 0; i < 4; i++) {
        int f = tid + i * 256;
        int d = f >> 4, lc = (f & 15) * 4;
        float4 o = make_float4(t[(lc + 0) * 65 + d], t[(lc + 1) * 65 + d],
                               t[(lc + 2) * 65 + d], t[(lc + 3) * 65 + d]);
        *reinterpret_cast<float4*>(dst + (size_t)d * Ll + lc) = o;
    }
}

// ---------------------------------------------------------------------------
// KV[bh] += K_chunk^T @ V_chunk; Ksum[bh] += sum K. 1 warp, 8x16 reg tile.
// ---------------------------------------------------------------------------
__global__ __launch_bounds__(32) void kv_reduce() {
    const int bh = blockIdx.x;
    const int s0 = blockIdx.y * 256;
    const int b = bh >> 3, h = bh & 7;
    const float* __restrict__ Kb = g_K + (size_t)b * Ll * Cc + h * Dd;
    const float* __restrict__ Vb = g_V + (size_t)b * Ll * Cc + h * Dd;

    __shared__ float Ks[16][64];
    __shared__ float Vs[16][64];

    const int tid = threadIdx.x;
    const int tx = tid & 3;
    const int ty = tid >> 2;

    float acc[8][16];
#pragma unroll
    for (int i = 0; i < 8; i++)
#pragma unroll
        for (int j = 0; j < 16; j++) acc[i][j] = 0.f;
    float ksum[8];
#pragma unroll
    for (int i = 0; i < 8; i++) ksum[i] = 0.f;

    for (int sc = 0; sc < 256; sc += 16) {
#pragma unroll
        for (int i = 0; i < 16; i++) {
            int f = tid + i * 32;
            int mat = f >> 8, r = (f >> 4) & 15, c = (f & 15) * 4;
            const float* src = (mat ? Vb : Kb) + (size_t)(s0 + sc + r) * Cc + c;
            float4 v = *reinterpret_cast<const float4*>(src);
            *reinterpret_cast<float4*>(mat ? &Vs[r][c] : &Ks[r][c]) = v;
        }
        __syncwarp();
#pragma unroll
        for (int r = 0; r < 16; r++) {
            float a[8], bb[16];
            *reinterpret_cast<float4*>(a)     = *reinterpret_cast<const float4*>(&Ks[r][ty * 8]);
            *reinterpret_cast<float4*>(a + 4) = *reinterpret_cast<const float4*>(&Ks[r][ty * 8 + 4]);
#pragma unroll
            for (int q = 0; q < 4; q++)
                *reinterpret_cast<float4*>(bb + q * 4) =
                    *reinterpret_cast<const float4*>(&Vs[r][tx * 16 + q * 4]);
            if (tx == 0) {
#pragma unroll
                for (int i = 0; i < 8; i++) ksum[i] += a[i];
            }
#pragma unroll
            for (int i = 0; i < 8; i++)
#pragma unroll
                for (int j = 0; j < 16; j++)
                    acc[i][j] = fmaf(a[i], bb[j], acc[i][j]);
        }
        __syncwarp();
    }

    float* KVp = g_KV + (size_t)bh * Dd * Dd;
#pragma unroll
    for (int i = 0; i < 8; i++)
#pragma unroll
        for (int j = 0; j < 16; j++)
            atomicAdd(KVp + (ty * 8 + i) * Dd + tx * 16 + j, acc[i][j]);
    if (tx == 0) {
#pragma unroll
        for (int i = 0; i < 8; i++)
            atomicAdd(g_Ksum + bh * Dd + ty * 8 + i, ksum[i]);
    }
}

// ---------------------------------------------------------------------------
// out[b,l,h,:] = (Q[l]@KV) / (Q[l]·Ksum + eps). 1 warp, 8x16 reg tile.
// ---------------------------------------------------------------------------
__global__ __launch_bounds__(32) void out_fin(float* __restrict__ out) {
    const int bh = blockIdx.x;
    const int l0 = blockIdx.y * 64;
    const int b = bh >> 3, h = bh & 7;

    __shared__ float KVs[64][64];
    __shared__ float Qst[64][64];   // [dd][l]
    __shared__ float Ksum_s[64];
    __shared__ float Zs[64];

    const int tid = threadIdx.x;

    const float* kvsrc = g_KV + (size_t)bh * Dd * Dd;
#pragma unroll
    for (int i = 0; i < 32; i++) {
        int f = tid + i * 32;
        *reinterpret_cast<float4*>(&KVs[0][0] + f * 4) =
            *reinterpret_cast<const float4*>(kvsrc + f * 4);
    }
    const float* qsrc = g_Qt + (size_t)bh * Dd * Ll + l0;
#pragma unroll
    for (int i = 0; i < 32; i++) {
        int f = tid + i * 32;
        int dd = f >> 4, c = (f & 15) * 4;
        *reinterpret_cast<float4*>(&Qst[dd][c]) =
            *reinterpret_cast<const float4*>(qsrc + (size_t)dd * Ll + c);
    }
    Ksum_s[tid]      = g_Ksum[bh * Dd + tid];
    Ksum_s[tid + 32] = g_Ksum[bh * Dd + tid + 32];
    __syncwarp();

#pragma unroll
    for (int ii = 0; ii < 2; ii++) {
        int l = tid + ii * 32;
        float s = 0.f;
#pragma unroll 8
        for (int dd = 0; dd < 64; dd++) s = fmaf(Qst[dd][l], Ksum_s[dd], s);
        Zs[l] = 1.f / (s + 1e-6f);
    }
    __syncwarp();

    const int tx = tid & 3;
    const int tl = tid >> 2;
    float acc[8][16];
#pragma unroll
    for (int i = 0; i < 8; i++)
#pragma unroll
        for (int j = 0; j < 16; j++) acc[i][j] = 0.f;

#pragma unroll 4
    for (int dd = 0; dd < 64; dd++) {
        float a[8], bb[16];
        *reinterpret_cast<float4*>(a)     = *reinterpret_cast<const float4*>(&Qst[dd][tl * 8]);
        *reinterpret_cast<float4*>(a + 4) = *reinterpret_cast<const float4*>(&Qst[dd][tl * 8 + 4]);
#pragma unroll
        for (int q = 0; q < 4; q++)
            *reinterpret_cast<float4*>(bb + q * 4) =
                *reinterpret_cast<const float4*>(&KVs[dd][tx * 16 + q * 4]);
#pragma unroll
        for (int i = 0; i < 8; i++)
#pragma unroll
            for (int j = 0; j < 16; j++)
                acc[i][j] = fmaf(a[i], bb[j], acc[i][j]);
    }

#pragma unroll
    for (int i = 0; i < 8; i++) {
        int l = tl * 8 + i;
        float zz = Zs[l];
        float* dst = out + ((size_t)b * Ll + l0 + l) * Cc + h * Dd + tx * 16;
#pragma unroll
        for (int q = 0; q < 4; q++) {
            float4 o;
            o.x = acc[i][q * 4 + 0] * zz;
            o.y = acc[i][q * 4 + 1] * zz;
            o.z = acc[i][q * 4 + 2] * zz;
            o.w = acc[i][q * 4 + 3] * zz;
            *reinterpret_cast<float4*>(dst + q * 4) = o;
        }
    }
}

// ---------------------------------------------------------------------------
extern "C" void kernel_launch(void* const* d_in, const int* in_sizes, int n_in,
                              void* d_out, int out_size) {
    const float* x  = (const float*)d_in[0];
    const float* Wq = (const float*)d_in[1];
    const float* bq = (const float*)d_in[2];
    const float* Wk = (const float*)d_in[3];
    const float* bk = (const float*)d_in[4];
    const float* Wv = (const float*)d_in[5];
    const float* bv = (const float*)d_in[6];
    float* out = (float*)d_out;

    cudaFuncSetAttribute(qkv_gemm_tc, cudaFuncAttributeMaxDynamicSharedMemorySize, SMEM_TOTAL);

    zero_acc_kernel<<<512, 256>>>();
    prep_x<<<(int)(((size_t)MM * Cc) / 1024), 256>>>(x);
    prep_w<<<dim3(3, Cc), 128>>>(Wq, Wk, Wv);
    qkv_gemm_tc<<<dim3(12, MM / BM), 256, SMEM_TOTAL>>>(bq, bk, bv);
    q_transpose<<<dim3(BHn, Ll / 64), 256>>>();
    kv_reduce<<<dim3(BHn, Ll / 256), 32>>>();
    out_fin<<<dim3(BHn, Ll / 64), 32>>>(out);
}

// round 4
// speedup vs baseline: 3.1269x; 1.1776x over previous
#include <cuda_runtime.h>
#include <cuda_bf16.h>
#include <cstdint>
#include <math.h>

#define Bb 4
#define Ll 16384
#define Cc 512
#define Hh 8
#define Dd 64
#define MM (Bb*Ll)      // 65536
#define BHn (Bb*Hh)     // 32

#define BM 128
#define BN 128
#define BK 64
#define STAGES 3
#define STAGE_BYTES 65536           // Ah 16K | Al 16K | Bh 16K | Bl 16K
#define SMEM_TOTAL (STAGES*STAGE_BYTES)

// kv_tc smem: stage = Kh 8K | Kl 8K | Vh 8K | Vl 8K = 32K, 3 stages
#define KV_STAGE 32768
#define KV_SMEM (3*KV_STAGE)
// out_tc smem: Qh 16K | Ql 16K | Bh 10K | Bl 10K
#define OUT_SMEM (16384*2 + 10240*2)

// Scratch
__device__ __nv_bfloat16 g_Xh[(size_t)MM*Cc];
__device__ __nv_bfloat16 g_Xl[(size_t)MM*Cc];
__device__ __nv_bfloat16 g_Wth[3*(size_t)Cc*Cc];  // W^T hi, [z][n][k]
__device__ __nv_bfloat16 g_Wtl[3*(size_t)Cc*Cc];  // W^T lo
__device__ __nv_bfloat16 g_Qh[(size_t)MM*Cc];
__device__ __nv_bfloat16 g_Ql[(size_t)MM*Cc];
__device__ __nv_bfloat16 g_Kh[(size_t)MM*Cc];
__device__ __nv_bfloat16 g_Kl[(size_t)MM*Cc];
__device__ __nv_bfloat16 g_Vh[(size_t)MM*Cc];
__device__ __nv_bfloat16 g_Vl[(size_t)MM*Cc];
__device__ float g_KV[BHn*Dd*Dd];
__device__ float g_Ksum[BHn*Dd];
__device__ __nv_bfloat16 g_KVth[(size_t)BHn*80*64];  // [bh][v-row(80)][d], row64=Ksum
__device__ __nv_bfloat16 g_KVtl[(size_t)BHn*80*64];

// ---------------------------------------------------------------------------
__device__ __forceinline__ uint32_t smem_u32(const void* p) {
    uint32_t a;
    asm("{ .reg .u64 t; cvta.to.shared.u64 t, %1; cvt.u32.u64 %0, t; }" : "=r"(a) : "l"(p));
    return a;
}
#define SWZ128(o) ((o) ^ (((o) >> 3) & 0x70))

__device__ __forceinline__ void cpa16(uint32_t d, const void* s) {
    uint64_t gp;
    asm("cvta.to.global.u64 %0, %1;" : "=l"(gp) : "l"(s));
    asm volatile("cp.async.cg.shared.global [%0], [%1], 16;" :: "r"(d), "l"(gp) : "memory");
}
__device__ __forceinline__ void cp_commit() {
    asm volatile("cp.async.commit_group;" ::: "memory");
}
template<int N> __device__ __forceinline__ void cp_wait() {
    asm volatile("cp.async.wait_group %0;" :: "n"(N) : "memory");
}
__device__ __forceinline__ void ldm4(uint32_t* r, uint32_t a) {
    asm volatile("ldmatrix.sync.aligned.m8n8.x4.shared.b16 {%0,%1,%2,%3}, [%4];"
        : "=r"(r[0]), "=r"(r[1]), "=r"(r[2]), "=r"(r[3]) : "r"(a));
}
__device__ __forceinline__ void ldm4t(uint32_t* r, uint32_t a) {
    asm volatile("ldmatrix.sync.aligned.m8n8.x4.trans.shared.b16 {%0,%1,%2,%3}, [%4];"
        : "=r"(r[0]), "=r"(r[1]), "=r"(r[2]), "=r"(r[3]) : "r"(a));
}
__device__ __forceinline__ void mma16816(float* c, const uint32_t* a, const uint32_t* b) {
    asm volatile("mma.sync.aligned.m16n8k16.row.col.f32.bf16.bf16.f32 "
        "{%0,%1,%2,%3}, {%4,%5,%6,%7}, {%8,%9}, {%0,%1,%2,%3};"
        : "+f"(c[0]), "+f"(c[1]), "+f"(c[2]), "+f"(c[3])
        : "r"(a[0]), "r"(a[1]), "r"(a[2]), "r"(a[3]), "r"(b[0]), "r"(b[1]));
}
__device__ __forceinline__ uint32_t pack_bf16(__nv_bfloat16 a, __nv_bfloat16 b) {
    __nv_bfloat162 t(a, b);
    return *reinterpret_cast<uint32_t*>(&t);
}
__device__ __forceinline__ void split2(float v, __nv_bfloat16& h, __nv_bfloat16& l) {
    h = __float2bfloat16(v);
    l = __float2bfloat16(v - __bfloat162float(h));
}

// ---------------------------------------------------------------------------
__global__ void zero_acc_kernel() {
    int i = blockIdx.x * blockDim.x + threadIdx.x;
    if (i < BHn * Dd * Dd) g_KV[i] = 0.f;
    if (i < BHn * Dd)      g_Ksum[i] = 0.f;
}

__global__ void prep_x(const float* __restrict__ X) {
    size_t i = ((size_t)blockIdx.x * 256 + threadIdx.x) * 4;
    float4 v = *reinterpret_cast<const float4*>(X + i);
    const float* vp = &v.x;
    __nv_bfloat16 h[4], l[4];
#pragma unroll
    for (int q = 0; q < 4; q++) split2(vp[q], h[q], l[q]);
    *reinterpret_cast<uint2*>(g_Xh + i) = make_uint2(pack_bf16(h[0], h[1]), pack_bf16(h[2], h[3]));
    *reinterpret_cast<uint2*>(g_Xl + i) = make_uint2(pack_bf16(l[0], l[1]), pack_bf16(l[2], l[3]));
}

__global__ void prep_w(const float* __restrict__ Wq, const float* __restrict__ Wk,
                       const float* __restrict__ Wv) {
    const int z = blockIdx.x, n = blockIdx.y;
    const float* W = (z == 0) ? Wq : ((z == 1) ? Wk : Wv);
    __nv_bfloat16* dh = g_Wth + ((size_t)z * Cc + n) * Cc;
    __nv_bfloat16* dl = g_Wtl + ((size_t)z * Cc + n) * Cc;
    int k0 = threadIdx.x * 4;
#pragma unroll
    for (int j = 0; j < 4; j++) {
        __nv_bfloat16 h, l;
        split2(W[(size_t)(k0 + j) * Cc + n], h, l);
        dh[k0 + j] = h;
        dl[k0 + j] = l;
    }
}

// ---------------------------------------------------------------------------
// Stage 1: QKV bf16 3-pass split GEMM, register-pipelined fragments.
// ---------------------------------------------------------------------------
__global__ __launch_bounds__(256, 1) void qkv_gemm_tc(
    const float* __restrict__ bq, const float* __restrict__ bk,
    const float* __restrict__ bv)
{
    extern __shared__ char smem[];
    const uint32_t sbase = smem_u32(smem);
    const int tid = threadIdx.x;
    const int nz = blockIdx.x;
    const int z = nz >> 2;
    const int col0 = (nz & 3) * BN;
    const int row0 = blockIdx.y * BM;

    const __nv_bfloat16* __restrict__ Bh_g = g_Wth + (size_t)z * Cc * Cc;
    const __nv_bfloat16* __restrict__ Bl_g = g_Wtl + (size_t)z * Cc * Cc;
    const float* __restrict__ bias = (z == 0) ? bq : ((z == 1) ? bk : bv);

    auto issue = [&](int kidx, int buf) {
        uint32_t sb = sbase + buf * STAGE_BYTES;
        int k0 = kidx * BK;
#pragma unroll
        for (int r = 0; r < 4; r++) {
            int q = tid + r * 256;
            int m = q >> 3, c = q & 7;
            uint32_t off = SWZ128((uint32_t)(m * 128 + c * 16));
            size_t asrc = (size_t)(row0 + m) * Cc + k0 + c * 8;
            size_t bsrc = (size_t)(col0 + m) * Cc + k0 + c * 8;
            cpa16(sb + off,         g_Xh + asrc);
            cpa16(sb + 16384 + off, g_Xl + asrc);
            cpa16(sb + 32768 + off, Bh_g + bsrc);
            cpa16(sb + 49152 + off, Bl_g + bsrc);
        }
        cp_commit();
    };

    issue(0, 0);
    issue(1, 1);

    const int lane = tid & 31, wid = tid >> 5;
    const int wm = (wid & 3) * 32;
    const int wn = (wid >> 2) * 64;
    const int arow = wm + (lane & 15);
    const uint32_t a_base = (uint32_t)arow * 128;
    const uint32_t a_xor  = (uint32_t)((arow & 7) * 16);
    const uint32_t a_k    = (uint32_t)((lane >> 4) * 16);
    const int brow = wn + (lane & 7) + ((lane >> 4) << 3);
    const uint32_t b_base = (uint32_t)brow * 128 + 32768;
    const uint32_t b_xor  = (uint32_t)((brow & 7) * 16);
    const uint32_t b_k    = (uint32_t)(((lane >> 3) & 1) * 16);

    float acc[2][8][4];
#pragma unroll
    for (int i = 0; i < 2; i++)
#pragma unroll
        for (int j = 0; j < 8; j++)
#pragma unroll
            for (int q = 0; q < 4; q++) acc[i][j][q] = 0.f;

    // fragment double buffers
    uint32_t fah[2][8], fal[2][8], fbh[2][4][4], fbl[2][4][4];

    auto load_frags = [&](uint32_t sb, int ks, int buf) {
        uint32_t ka = ((uint32_t)(ks * 32) + a_k) ^ a_xor;
        uint32_t kb = ((uint32_t)(ks * 32) + b_k) ^ b_xor;
        ldm4(&fah[buf][0], sb + a_base + ka);
        ldm4(&fah[buf][4], sb + a_base + 2048 + ka);
        ldm4(&fal[buf][0], sb + 16384 + a_base + ka);
        ldm4(&fal[buf][4], sb + 16384 + a_base + 2048 + ka);
#pragma unroll
        for (int g = 0; g < 4; g++) {
            ldm4(fbh[buf][g], sb + b_base + g * 2048 + kb);
            ldm4(fbl[buf][g], sb + 16384 + b_base + g * 2048 + kb);
        }
    };

    const int NIT = Cc / BK;  // 8
    for (int it = 0; it < NIT; it++) {
        cp_wait<1>();
        __syncthreads();
        if (it + 2 < NIT) issue(it + 2, (it + 2) % STAGES);
        else cp_commit();

        uint32_t sb = sbase + (it % STAGES) * STAGE_BYTES;
        load_frags(sb, 0, 0);
#pragma unroll
        for (int ks = 0; ks < 4; ks++) {
            const int cur = ks & 1;
            if (ks < 3) load_frags(sb, ks + 1, cur ^ 1);
#pragma unroll
            for (int j = 0; j < 8; j++) {
                const uint32_t* bh = &fbh[cur][j >> 1][(j & 1) * 2];
                const uint32_t* bl = &fbl[cur][j >> 1][(j & 1) * 2];
                mma16816(acc[0][j], &fah[cur][0], bh);
                mma16816(acc[1][j], &fah[cur][4], bh);
                mma16816(acc[0][j], &fal[cur][0], bh);
                mma16816(acc[1][j], &fal[cur][4], bh);
                mma16816(acc[0][j], &fah[cur][0], bl);
                mma16816(acc[1][j], &fah[cur][4], bl);
            }
        }
    }

    // Epilogue: bias + feature map (Q,K), store bf16 hi/lo pairs
    __nv_bfloat16* outH = (z == 0) ? g_Qh : ((z == 1) ? g_Kh : g_Vh);
    __nv_bfloat16* outL = (z == 0) ? g_Ql : ((z == 1) ? g_Kl : g_Vl);
    const int gq = lane >> 2, tq = lane & 3;
#pragma unroll
    for (int im = 0; im < 2; im++) {
#pragma unroll
        for (int hh = 0; hh < 2; hh++) {
            int mg = row0 + wm + im * 16 + gq + hh * 8;
#pragma unroll
            for (int j = 0; j < 8; j++) {
                int cg = col0 + wn + j * 8 + tq * 2;
                float v0 = acc[im][j][hh * 2 + 0] + __ldg(bias + cg);
                float v1 = acc[im][j][hh * 2 + 1] + __ldg(bias + cg + 1);
                if (z < 2) {
                    v0 = (v0 > 0.f) ? (v0 + 1.f) : __expf(v0);
                    v1 = (v1 > 0.f) ? (v1 + 1.f) : __expf(v1);
                }
                __nv_bfloat16 h0, l0, h1, l1;
                split2(v0, h0, l0);
                split2(v1, h1, l1);
                size_t o = (size_t)mg * Cc + cg;
                *reinterpret_cast<uint32_t*>(outH + o) = pack_bf16(h0, h1);
                *reinterpret_cast<uint32_t*>(outL + o) = pack_bf16(l0, l1);
            }
        }
    }
}

// ---------------------------------------------------------------------------
// Stage 2: KV[bh] += K^T V via tensor cores, Ksum via ones-column MMA.
// grid (32, 16), 128 threads (4 warps). S-chunk = 1024, staged 64 rows.
// ---------------------------------------------------------------------------
__global__ __launch_bounds__(128) void kv_tc() {
    extern __shared__ char smem[];
    const uint32_t sbase = smem_u32(smem);
    const int bh = blockIdx.x;
    const int b = bh >> 3, h = bh & 7;
    const int s0 = blockIdx.y * 1024;
    const int tid = threadIdx.x;
    const int lane = tid & 31, w = tid >> 5;

    const __nv_bfloat16* __restrict__ kh = g_Kh + ((size_t)(b * Ll + s0)) * Cc + h * 64;
    const __nv_bfloat16* __restrict__ kl = g_Kl + ((size_t)(b * Ll + s0)) * Cc + h * 64;
    const __nv_bfloat16* __restrict__ vh = g_Vh + ((size_t)(b * Ll + s0)) * Cc + h * 64;
    const __nv_bfloat16* __restrict__ vl = g_Vl + ((size_t)(b * Ll + s0)) * Cc + h * 64;

    auto issue = [&](int st, int buf) {
        uint32_t sb = sbase + buf * KV_STAGE;
#pragma unroll
        for (int i = 0; i < 4; i++) {
            int idx = tid + i * 128;         // 0..511
            int row = idx >> 3, c16 = idx & 7;
            uint32_t off = SWZ128((uint32_t)(row * 128 + c16 * 16));
            size_t src = (size_t)(st * 64 + row) * Cc + c16 * 8;
            cpa16(sb + off,         kh + src);
            cpa16(sb + 8192 + off,  kl + src);
            cpa16(sb + 16384 + off, vh + src);
            cpa16(sb + 24576 + off, vl + src);
        }
        cp_commit();
    };

    issue(0, 0);
    issue(1, 1);

    float accK[8][4], accS[4];
#pragma unroll
    for (int t = 0; t < 8; t++)
#pragma unroll
        for (int q = 0; q < 4; q++) accK[t][q] = 0.f;
#pragma unroll
    for (int q = 0; q < 4; q++) accS[q] = 0.f;

    const uint32_t ones = ((lane >> 2) == 0) ? 0x3F803F80u : 0u;
    uint32_t onef[2] = {ones, ones};

    const uint32_t a_col = (uint32_t)((w * 16 + ((lane >> 4) << 3)) * 2);

    for (int st = 0; st < 16; st++) {
        cp_wait<1>();
        __syncthreads();
        if (st + 2 < 16) issue(st + 2, (st + 2) % 3);
        else cp_commit();

        uint32_t sb = sbase + (st % 3) * KV_STAGE;
#pragma unroll
        for (int s16 = 0; s16 < 4; s16++) {
            uint32_t rowb = (uint32_t)((s16 * 16 + (lane & 15)) * 128);
            uint32_t offA = SWZ128(rowb + a_col);
            uint32_t rh[4], rl[4];
            ldm4t(rh, sb + offA);
            ldm4t(rl, sb + 8192 + offA);
            uint32_t Ah[4] = {rh[0], rh[2], rh[1], rh[3]};
            uint32_t Al[4] = {rl[0], rl[2], rl[1], rl[3]};
            uint32_t bhf[4][4], blf[4][4];
#pragma unroll
            for (int g = 0; g < 4; g++) {
                uint32_t offV = SWZ128(rowb + (uint32_t)((g * 16 + ((lane >> 4) << 3)) * 2));
                ldm4t(bhf[g], sb + 16384 + offV);
                ldm4t(blf[g], sb + 24576 + offV);
            }
#pragma unroll
            for (int t = 0; t < 8; t++) {
                const uint32_t* bhr = &bhf[t >> 1][(t & 1) * 2];
                const uint32_t* blr = &blf[t >> 1][(t & 1) * 2];
                mma16816(accK[t], Ah, bhr);
                mma16816(accK[t], Al, bhr);
                mma16816(accK[t], Ah, blr);
            }
            mma16816(accS, Ah, onef);
            mma16816(accS, Al, onef);
        }
    }

    const int d0 = w * 16 + (lane >> 2);
    float* KVp = g_KV + (size_t)bh * 4096;
#pragma unroll
    for (int t = 0; t < 8; t++) {
        int v = t * 8 + (lane & 3) * 2;
        atomicAdd(KVp + d0 * 64 + v,           accK[t][0]);
        atomicAdd(KVp + d0 * 64 + v + 1,       accK[t][1]);
        atomicAdd(KVp + (d0 + 8) * 64 + v,     accK[t][2]);
        atomicAdd(KVp + (d0 + 8) * 64 + v + 1, accK[t][3]);
    }
    if ((lane & 3) == 0) {
        atomicAdd(g_Ksum + bh * 64 + d0,     accS[0]);
        atomicAdd(g_Ksum + bh * 64 + d0 + 8, accS[2]);
    }
}

// ---------------------------------------------------------------------------
// Finalize: KVt[bh][v][d] = KV[bh][d][v] as bf16 hi/lo; row 64 = Ksum; 65-79 = 0.
// ---------------------------------------------------------------------------
__global__ void kv_finalize() {
    const int bh = blockIdx.x;
    const int v = threadIdx.x;   // 0..63
    __nv_bfloat16* oh = g_KVth + (size_t)bh * 80 * 64;
    __nv_bfloat16* ol = g_KVtl + (size_t)bh * 80 * 64;
    const float* kv = g_KV + (size_t)bh * 4096;
#pragma unroll 8
    for (int d = 0; d < 64; d++) {
        __nv_bfloat16 h, l;
        split2(kv[d * 64 + v], h, l);
        oh[v * 64 + d] = h;
        ol[v * 64 + d] = l;
    }
    __nv_bfloat16 h, l;
    split2(g_Ksum[bh * 64 + v], h, l);
    oh[64 * 64 + v] = h;
    ol[64 * 64 + v] = l;
#pragma unroll
    for (int r = 65; r < 80; r++) {
        oh[r * 64 + v] = __float2bfloat16(0.f);
        ol[r * 64 + v] = __float2bfloat16(0.f);
    }
}

// ---------------------------------------------------------------------------
// Stage 3: out = (Q @ KVext) with normalizer from column 64 (Ksum row of KVt).
// grid (32, 128), 128 threads (4 warps), each warp 32 rows x 72 cols.
// ---------------------------------------------------------------------------
__global__ __launch_bounds__(128) void out_tc(float* __restrict__ out) {
    extern __shared__ char smem[];
    const uint32_t sbase = smem_u32(smem);
    const int bh = blockIdx.x;
    const int b = bh >> 3, h = bh & 7;
    const int l0 = blockIdx.y * 128;
    const int tid = threadIdx.x;
    const int lane = tid & 31, w = tid >> 5;

    // load Q tile (128 x 64, hi/lo) and B tile (80 x 64, hi/lo)
    {
        const __nv_bfloat16* qh = g_Qh + ((size_t)(b * Ll + l0)) * Cc + h * 64;
        const __nv_bfloat16* ql = g_Ql + ((size_t)(b * Ll + l0)) * Cc + h * 64;
#pragma unroll
        for (int i = 0; i < 8; i++) {
            int idx = tid + i * 128;        // 0..1023
            int row = idx >> 3, c16 = idx & 7;
            uint32_t off = SWZ128((uint32_t)(row * 128 + c16 * 16));
            size_t src = (size_t)row * Cc + c16 * 8;
            cpa16(sbase + off, qh + src);
            cpa16(sbase + 16384 + off, ql + src);
        }
        const __nv_bfloat16* bhp = g_KVth + (size_t)bh * 80 * 64;
        const __nv_bfloat16* blp = g_KVtl + (size_t)bh * 80 * 64;
#pragma unroll
        for (int i = 0; i < 5; i++) {
            int idx = tid + i * 128;        // 0..639
            int row = idx >> 3, c16 = idx & 7;
            uint32_t off = SWZ128((uint32_t)(row * 128 + c16 * 16));
            size_t src = (size_t)row * 64 + c16 * 8;
            cpa16(sbase + 32768 + off, bhp + src);
            cpa16(sbase + 43008 + off, blp + src);
        }
        cp_commit();
        cp_wait<0>();
        __syncthreads();
    }

    float acc[2][9][4];
#pragma unroll
    for (int im = 0; im < 2; im++)
#pragma unroll
        for (int t = 0; t < 9; t++)
#pragma unroll
            for (int q = 0; q < 4; q++) acc[im][t][q] = 0.f;

    const uint32_t a_k = (uint32_t)((lane >> 4) * 16);
    const int brow = (lane & 7) + ((lane >> 4) << 3);
    const uint32_t b_k = (uint32_t)(((lane >> 3) & 1) * 16);

#pragma unroll
    for (int ks = 0; ks < 4; ks++) {
        uint32_t aH[2][4], aL[2][4];
#pragma unroll
        for (int im = 0; im < 2; im++) {
            int ar = w * 32 + im * 16 + (lane & 15);
            uint32_t ka = ((uint32_t)(ks * 32) + a_k) ^ ((uint32_t)((ar & 7) * 16));
            ldm4(aH[im], sbase + (uint32_t)ar * 128 + ka);
            ldm4(aL[im], sbase + 16384 + (uint32_t)ar * 128 + ka);
        }
        uint32_t bH[5][4], bL[5][4];
#pragma unroll
        for (int g = 0; g < 5; g++) {
            int br = g * 16 + brow;
            uint32_t kb = ((uint32_t)(ks * 32) + b_k) ^ ((uint32_t)((br & 7) * 16));
            ldm4(bH[g], sbase + 32768 + (uint32_t)br * 128 + kb);
            ldm4(bL[g], sbase + 43008 + (uint32_t)br * 128 + kb);
        }
#pragma unroll
        for (int im = 0; im < 2; im++) {
#pragma unroll
            for (int t = 0; t < 9; t++) {
                const uint32_t* bhr = &bH[t >> 1][(t & 1) * 2];
                const uint32_t* blr = &bL[t >> 1][(t & 1) * 2];
                mma16816(acc[im][t], aH[im], bhr);
                mma16816(acc[im][t], aL[im], bhr);
                mma16816(acc[im][t], aH[im], blr);
            }
        }
    }

    // epilogue: Z from column 64 (tile 8), scale and store
#pragma unroll
    for (int im = 0; im < 2; im++) {
        float den0 = __shfl_sync(0xffffffffu, acc[im][8][0], lane & ~3);
        float den1 = __shfl_sync(0xffffffffu, acc[im][8][2], lane & ~3);
        float z0 = 1.f / (den0 + 1e-6f);
        float z1 = 1.f / (den1 + 1e-6f);
        int r0 = w * 32 + im * 16 + (lane >> 2);
        float* o0 = out + ((size_t)(b * Ll + l0 + r0)) * Cc + h * 64 + (lane & 3) * 2;
        float* o1 = out + ((size_t)(b * Ll + l0 + r0 + 8)) * Cc + h * 64 + (lane & 3) * 2;
#pragma unroll
        for (int t = 0; t < 8; t++) {
            *reinterpret_cast<float2*>(o0 + t * 8) =
                make_float2(acc[im][t][0] * z0, acc[im][t][1] * z0);
            *reinterpret_cast<float2*>(o1 + t * 8) =
                make_float2(acc[im][t][2] * z1, acc[im][t][3] * z1);
        }
    }
}

// ---------------------------------------------------------------------------
extern "C" void kernel_launch(void* const* d_in, const int* in_sizes, int n_in,
                              void* d_out, int out_size) {
    const float* x  = (const float*)d_in[0];
    const float* Wq = (const float*)d_in[1];
    const float* bq = (const float*)d_in[2];
    const float* Wk = (const float*)d_in[3];
    const float* bk = (const float*)d_in[4];
    const float* Wv = (const float*)d_in[5];
    const float* bv = (const float*)d_in[6];
    float* out = (float*)d_out;

    cudaFuncSetAttribute(qkv_gemm_tc, cudaFuncAttributeMaxDynamicSharedMemorySize, SMEM_TOTAL);
    cudaFuncSetAttribute(kv_tc, cudaFuncAttributeMaxDynamicSharedMemorySize, KV_SMEM);
    cudaFuncSetAttribute(out_tc, cudaFuncAttributeMaxDynamicSharedMemorySize, OUT_SMEM);

    zero_acc_kernel<<<512, 256>>>();
    prep_x<<<(int)(((size_t)MM * Cc) / 1024), 256>>>(x);
    prep_w<<<dim3(3, Cc), 128>>>(Wq, Wk, Wv);
    qkv_gemm_tc<<<dim3(12, MM / BM), 256, SMEM_TOTAL>>>(bq, bk, bv);
    kv_tc<<<dim3(BHn, 16), 128, KV_SMEM>>>();
    kv_finalize<<<BHn, 64>>>();
    out_tc<<<dim3(BHn, Ll / 128), 128, OUT_SMEM>>>(out);
}

// round 5
// speedup vs baseline: 3.3119x; 1.0592x over previous
#include <cuda_runtime.h>
#include <cuda_bf16.h>
#include <cstdint>
#include <math.h>

#define Bb 4
#define Ll 16384
#define Cc 512
#define Hh 8
#define Dd 64
#define MM (Bb*Ll)      // 65536
#define BHn (Bb*Hh)     // 32

// Stage-1 tiling: 128x128 tile, BK=32, hi/lo interleaved rows, 3 stages, 2 CTA/SM
#define QSTAGE 32768
#define QSMEM (3*QSTAGE)
#define QNIT 16          // 512/32

// kv_tc smem: stage = Kh 8K | Kl 8K | Vh 8K | Vl 8K = 32K, 3 stages
#define KV_STAGE 32768
#define KV_SMEM (3*KV_STAGE)
// out_tc smem: Qh 16K | Ql 16K | Bh 10K | Bl 10K
#define OUT_SMEM (16384*2 + 10240*2)

// Scratch
__device__ __nv_bfloat16 g_Xh[(size_t)MM*Cc];
__device__ __nv_bfloat16 g_Xl[(size_t)MM*Cc];
__device__ __nv_bfloat16 g_Wth[3*(size_t)Cc*Cc];  // W^T hi, [z][n][k]
__device__ __nv_bfloat16 g_Wtl[3*(size_t)Cc*Cc];  // W^T lo
__device__ __nv_bfloat16 g_Qh[(size_t)MM*Cc];
__device__ __nv_bfloat16 g_Ql[(size_t)MM*Cc];
__device__ __nv_bfloat16 g_Kh[(size_t)MM*Cc];
__device__ __nv_bfloat16 g_Kl[(size_t)MM*Cc];
__device__ __nv_bfloat16 g_Vh[(size_t)MM*Cc];
__device__ __nv_bfloat16 g_Vl[(size_t)MM*Cc];
__device__ float g_KV[BHn*Dd*Dd];
__device__ float g_Ksum[BHn*Dd];
__device__ __nv_bfloat16 g_KVth[(size_t)BHn*80*64];  // [bh][v-row(80)][d], row64=Ksum
__device__ __nv_bfloat16 g_KVtl[(size_t)BHn*80*64];

// ---------------------------------------------------------------------------
__device__ __forceinline__ uint32_t smem_u32(const void* p) {
    uint32_t a;
    asm("{ .reg .u64 t; cvta.to.shared.u64 t, %1; cvt.u32.u64 %0, t; }" : "=r"(a) : "l"(p));
    return a;
}
#define SWZ128(o) ((o) ^ (((o) >> 3) & 0x70))

__device__ __forceinline__ void cpa16(uint32_t d, const void* s) {
    uint64_t gp;
    asm("cvta.to.global.u64 %0, %1;" : "=l"(gp) : "l"(s));
    asm volatile("cp.async.cg.shared.global [%0], [%1], 16;" :: "r"(d), "l"(gp) : "memory");
}
__device__ __forceinline__ void cp_commit() {
    asm volatile("cp.async.commit_group;" ::: "memory");
}
template<int N> __device__ __forceinline__ void cp_wait() {
    asm volatile("cp.async.wait_group %0;" :: "n"(N) : "memory");
}
__device__ __forceinline__ void ldm4(uint32_t* r, uint32_t a) {
    asm volatile("ldmatrix.sync.aligned.m8n8.x4.shared.b16 {%0,%1,%2,%3}, [%4];"
        : "=r"(r[0]), "=r"(r[1]), "=r"(r[2]), "=r"(r[3]) : "r"(a));
}
__device__ __forceinline__ void ldm4t(uint32_t* r, uint32_t a) {
    asm volatile("ldmatrix.sync.aligned.m8n8.x4.trans.shared.b16 {%0,%1,%2,%3}, [%4];"
        : "=r"(r[0]), "=r"(r[1]), "=r"(r[2]), "=r"(r[3]) : "r"(a));
}
__device__ __forceinline__ void mma16816(float* c, const uint32_t* a, const uint32_t* b) {
    asm volatile("mma.sync.aligned.m16n8k16.row.col.f32.bf16.bf16.f32 "
        "{%0,%1,%2,%3}, {%4,%5,%6,%7}, {%8,%9}, {%0,%1,%2,%3};"
        : "+f"(c[0]), "+f"(c[1]), "+f"(c[2]), "+f"(c[3])
        : "r"(a[0]), "r"(a[1]), "r"(a[2]), "r"(a[3]), "r"(b[0]), "r"(b[1]));
}
__device__ __forceinline__ uint32_t pack_bf16(__nv_bfloat16 a, __nv_bfloat16 b) {
    __nv_bfloat162 t(a, b);
    return *reinterpret_cast<uint32_t*>(&t);
}
__device__ __forceinline__ void split2(float v, __nv_bfloat16& h, __nv_bfloat16& l) {
    h = __float2bfloat16(v);
    l = __float2bfloat16(v - __bfloat162float(h));
}

// ---------------------------------------------------------------------------
__global__ void zero_acc_kernel() {
    int i = blockIdx.x * blockDim.x + threadIdx.x;
    if (i < BHn * Dd * Dd) g_KV[i] = 0.f;
    if (i < BHn * Dd)      g_Ksum[i] = 0.f;
}

__global__ void prep_x(const float* __restrict__ X) {
    size_t i = ((size_t)blockIdx.x * 256 + threadIdx.x) * 4;
    float4 v = *reinterpret_cast<const float4*>(X + i);
    const float* vp = &v.x;
    __nv_bfloat16 h[4], l[4];
#pragma unroll
    for (int q = 0; q < 4; q++) split2(vp[q], h[q], l[q]);
    *reinterpret_cast<uint2*>(g_Xh + i) = make_uint2(pack_bf16(h[0], h[1]), pack_bf16(h[2], h[3]));
    *reinterpret_cast<uint2*>(g_Xl + i) = make_uint2(pack_bf16(l[0], l[1]), pack_bf16(l[2], l[3]));
}

__global__ void prep_w(const float* __restrict__ Wq, const float* __restrict__ Wk,
                       const float* __restrict__ Wv) {
    const int z = blockIdx.x, n = blockIdx.y;
    const float* W = (z == 0) ? Wq : ((z == 1) ? Wk : Wv);
    __nv_bfloat16* dh = g_Wth + ((size_t)z * Cc + n) * Cc;
    __nv_bfloat16* dl = g_Wtl + ((size_t)z * Cc + n) * Cc;
    int k0 = threadIdx.x * 4;
#pragma unroll
    for (int j = 0; j < 4; j++) {
        __nv_bfloat16 h, l;
        split2(W[(size_t)(k0 + j) * Cc + n], h, l);
        dh[k0 + j] = h;
        dl[k0 + j] = l;
    }
}

// ---------------------------------------------------------------------------
// Stage 1: QKV bf16 3-pass split GEMM.
// 128-thread CTAs, warp tile 64x64, BK=32, hi/lo interleaved in 128B rows,
// 3-stage cp.async ring, 2 CTAs/SM.
// ---------------------------------------------------------------------------
__global__ __launch_bounds__(128, 2) void qkv_gemm_tc(
    const float* __restrict__ bq, const float* __restrict__ bk,
    const float* __restrict__ bv)
{
    extern __shared__ char smem[];
    const uint32_t sbase = smem_u32(smem);
    const int tid = threadIdx.x;
    const int z = blockIdx.x >> 2;
    const int col0 = (blockIdx.x & 3) * 128;
    const int row0 = blockIdx.y * 128;
    const int lane = tid & 31, wid = tid >> 5;
    const int wm = (wid & 1) * 64;
    const int wn = (wid >> 1) * 64;

    const __nv_bfloat16* __restrict__ Bh_g = g_Wth + (size_t)z * Cc * Cc;
    const __nv_bfloat16* __restrict__ Bl_g = g_Wtl + (size_t)z * Cc * Cc;
    const float* __restrict__ bias = (z == 0) ? bq : ((z == 1) ? bk : bv);

    // stage layout: A rows [hi(64B) | lo(64B)] at 0, B rows same at 16384
    auto issue = [&](int kidx, int buf) {
        uint32_t sb = sbase + buf * QSTAGE;
        int k0 = kidx * 32;
#pragma unroll
        for (int i = 0; i < 16; i++) {
            int idx = tid + i * 128;          // 0..2047
            int mat = idx >> 10;              // 0=A, 1=B
            int r = (idx >> 3) & 127;
            int c = idx & 7;                  // 0-3 hi, 4-7 lo
            uint32_t off = SWZ128((uint32_t)(r * 128 + c * 16)) + (uint32_t)mat * 16384;
            const __nv_bfloat16* src;
            if (mat == 0)
                src = ((c < 4) ? g_Xh : g_Xl) + (size_t)(row0 + r) * Cc + k0 + (c & 3) * 8;
            else
                src = ((c < 4) ? Bh_g : Bl_g) + (size_t)(col0 + r) * Cc + k0 + (c & 3) * 8;
            cpa16(sb + off, src);
        }
        cp_commit();
    };

    issue(0, 0);
    issue(1, 1);

    float acc[4][8][4];
#pragma unroll
    for (int i = 0; i < 4; i++)
#pragma unroll
        for (int j = 0; j < 8; j++)
#pragma unroll
            for (int q = 0; q < 4; q++) acc[i][j][q] = 0.f;

    const uint32_t a_k = (uint32_t)((lane >> 4) * 16);
    const int a_row_in = lane & 15;
    const int b_row_in = (lane & 7) + ((lane >> 4) << 3);
    const uint32_t b_k = (uint32_t)(((lane >> 3) & 1) * 16);

    for (int it = 0; it < QNIT; it++) {
        cp_wait<1>();
        __syncthreads();
        if (it + 2 < QNIT) issue(it + 2, (it + 2) % 3);
        else cp_commit();

        uint32_t sb = sbase + (it % 3) * QSTAGE;
#pragma unroll
        for (int kk = 0; kk < 2; kk++) {
            uint32_t ah[4][4], al[4][4], bh[4][4], bl[4][4];
#pragma unroll
            for (int mf = 0; mf < 4; mf++) {
                int ar = wm + mf * 16 + a_row_in;
                uint32_t base = (uint32_t)(ar * 128) + (uint32_t)(kk * 32) + a_k;
                ldm4(ah[mf], sb + SWZ128(base));
                ldm4(al[mf], sb + SWZ128(base + 64));
            }
#pragma unroll
            for (int g = 0; g < 4; g++) {
                int br = wn + g * 16 + b_row_in;
                uint32_t base = (uint32_t)(br * 128) + (uint32_t)(kk * 32) + b_k;
                ldm4(bh[g], sb + 16384 + SWZ128(base));
                ldm4(bl[g], sb + 16384 + SWZ128(base + 64));
            }
#pragma unroll
            for (int mf = 0; mf < 4; mf++) {
#pragma unroll
                for (int j = 0; j < 8; j++) {
                    const uint32_t* bhr = &bh[j >> 1][(j & 1) * 2];
                    const uint32_t* blr = &bl[j >> 1][(j & 1) * 2];
                    mma16816(acc[mf][j], ah[mf], bhr);
                    mma16816(acc[mf][j], al[mf], bhr);
                    mma16816(acc[mf][j], ah[mf], blr);
                }
            }
        }
    }

    // Epilogue: bias + feature map (Q,K), store bf16 hi/lo pairs
    __nv_bfloat16* outH = (z == 0) ? g_Qh : ((z == 1) ? g_Kh : g_Vh);
    __nv_bfloat16* outL = (z == 0) ? g_Ql : ((z == 1) ? g_Kl : g_Vl);
    const int gq = lane >> 2, tq = lane & 3;
#pragma unroll
    for (int mf = 0; mf < 4; mf++) {
#pragma unroll
        for (int hh = 0; hh < 2; hh++) {
            int mg = row0 + wm + mf * 16 + gq + hh * 8;
#pragma unroll
            for (int j = 0; j < 8; j++) {
                int cg = col0 + wn + j * 8 + tq * 2;
                float v0 = acc[mf][j][hh * 2 + 0] + __ldg(bias + cg);
                float v1 = acc[mf][j][hh * 2 + 1] + __ldg(bias + cg + 1);
                if (z < 2) {
                    v0 = (v0 > 0.f) ? (v0 + 1.f) : __expf(v0);
                    v1 = (v1 > 0.f) ? (v1 + 1.f) : __expf(v1);
                }
                __nv_bfloat16 h0, l0, h1, l1;
                split2(v0, h0, l0);
                split2(v1, h1, l1);
                size_t o = (size_t)mg * Cc + cg;
                *reinterpret_cast<uint32_t*>(outH + o) = pack_bf16(h0, h1);
                *reinterpret_cast<uint32_t*>(outL + o) = pack_bf16(l0, l1);
            }
        }
    }
}

// ---------------------------------------------------------------------------
// Stage 2: KV[bh] += K^T V via tensor cores, Ksum via ones-column MMA.
// ---------------------------------------------------------------------------
__global__ __launch_bounds__(128) void kv_tc() {
    extern __shared__ char smem[];
    const uint32_t sbase = smem_u32(smem);
    const int bh = blockIdx.x;
    const int b = bh >> 3, h = bh & 7;
    const int s0 = blockIdx.y * 1024;
    const int tid = threadIdx.x;
    const int lane = tid & 31, w = tid >> 5;

    const __nv_bfloat16* __restrict__ kh = g_Kh + ((size_t)(b * Ll + s0)) * Cc + h * 64;
    const __nv_bfloat16* __restrict__ kl = g_Kl + ((size_t)(b * Ll + s0)) * Cc + h * 64;
    const __nv_bfloat16* __restrict__ vh = g_Vh + ((size_t)(b * Ll + s0)) * Cc + h * 64;
    const __nv_bfloat16* __restrict__ vl = g_Vl + ((size_t)(b * Ll + s0)) * Cc + h * 64;

    auto issue = [&](int st, int buf) {
        uint32_t sb = sbase + buf * KV_STAGE;
#pragma unroll
        for (int i = 0; i < 4; i++) {
            int idx = tid + i * 128;
            int row = idx >> 3, c16 = idx & 7;
            uint32_t off = SWZ128((uint32_t)(row * 128 + c16 * 16));
            size_t src = (size_t)(st * 64 + row) * Cc + c16 * 8;
            cpa16(sb + off,         kh + src);
            cpa16(sb + 8192 + off,  kl + src);
            cpa16(sb + 16384 + off, vh + src);
            cpa16(sb + 24576 + off, vl + src);
        }
        cp_commit();
    };

    issue(0, 0);
    issue(1, 1);

    float accK[8][4], accS[4];
#pragma unroll
    for (int t = 0; t < 8; t++)
#pragma unroll
        for (int q = 0; q < 4; q++) accK[t][q] = 0.f;
#pragma unroll
    for (int q = 0; q < 4; q++) accS[q] = 0.f;

    const uint32_t ones = ((lane >> 2) == 0) ? 0x3F803F80u : 0u;
    uint32_t onef[2] = {ones, ones};

    const uint32_t a_col = (uint32_t)((w * 16 + ((lane >> 4) << 3)) * 2);

    for (int st = 0; st < 16; st++) {
        cp_wait<1>();
        __syncthreads();
        if (st + 2 < 16) issue(st + 2, (st + 2) % 3);
        else cp_commit();

        uint32_t sb = sbase + (st % 3) * KV_STAGE;
#pragma unroll
        for (int s16 = 0; s16 < 4; s16++) {
            uint32_t rowb = (uint32_t)((s16 * 16 + (lane & 15)) * 128);
            uint32_t offA = SWZ128(rowb + a_col);
            uint32_t rh[4], rl[4];
            ldm4t(rh, sb + offA);
            ldm4t(rl, sb + 8192 + offA);
            uint32_t Ah[4] = {rh[0], rh[2], rh[1], rh[3]};
            uint32_t Al[4] = {rl[0], rl[2], rl[1], rl[3]};
            uint32_t bhf[4][4], blf[4][4];
#pragma unroll
            for (int g = 0; g < 4; g++) {
                uint32_t offV = SWZ128(rowb + (uint32_t)((g * 16 + ((lane >> 4) << 3)) * 2));
                ldm4t(bhf[g], sb + 16384 + offV);
                ldm4t(blf[g], sb + 24576 + offV);
            }
#pragma unroll
            for (int t = 0; t < 8; t++) {
                const uint32_t* bhr = &bhf[t >> 1][(t & 1) * 2];
                const uint32_t* blr = &blf[t >> 1][(t & 1) * 2];
                mma16816(accK[t], Ah, bhr);
                mma16816(accK[t], Al, bhr);
                mma16816(accK[t], Ah, blr);
            }
            mma16816(accS, Ah, onef);
            mma16816(accS, Al, onef);
        }
    }

    const int d0 = w * 16 + (lane >> 2);
    float* KVp = g_KV + (size_t)bh * 4096;
#pragma unroll
    for (int t = 0; t < 8; t++) {
        int v = t * 8 + (lane & 3) * 2;
        atomicAdd(KVp + d0 * 64 + v,           accK[t][0]);
        atomicAdd(KVp + d0 * 64 + v + 1,       accK[t][1]);
        atomicAdd(KVp + (d0 + 8) * 64 + v,     accK[t][2]);
        atomicAdd(KVp + (d0 + 8) * 64 + v + 1, accK[t][3]);
    }
    if ((lane & 3) == 0) {
        atomicAdd(g_Ksum + bh * 64 + d0,     accS[0]);
        atomicAdd(g_Ksum + bh * 64 + d0 + 8, accS[2]);
    }
}

// ---------------------------------------------------------------------------
// Finalize: KVt[bh][v][d] = KV[bh][d][v] as bf16 hi/lo; row 64 = Ksum; 65-79 = 0.
// ---------------------------------------------------------------------------
__global__ void kv_finalize() {
    const int bh = blockIdx.x;
    const int v = threadIdx.x;   // 0..63
    __nv_bfloat16* oh = g_KVth + (size_t)bh * 80 * 64;
    __nv_bfloat16* ol = g_KVtl + (size_t)bh * 80 * 64;
    const float* kv = g_KV + (size_t)bh * 4096;
#pragma unroll 8
    for (int d = 0; d < 64; d++) {
        __nv_bfloat16 h, l;
        split2(kv[d * 64 + v], h, l);
        oh[v * 64 + d] = h;
        ol[v * 64 + d] = l;
    }
    __nv_bfloat16 h, l;
    split2(g_Ksum[bh * 64 + v], h, l);
    oh[64 * 64 + v] = h;
    ol[64 * 64 + v] = l;
#pragma unroll
    for (int r = 65; r < 80; r++) {
        oh[r * 64 + v] = __float2bfloat16(0.f);
        ol[r * 64 + v] = __float2bfloat16(0.f);
    }
}

// ---------------------------------------------------------------------------
// Stage 3: out = (Q @ KVext) with normalizer from column 64 (Ksum row of KVt).
// ---------------------------------------------------------------------------
__global__ __launch_bounds__(128) void out_tc(float* __restrict__ out) {
    extern __shared__ char smem[];
    const uint32_t sbase = smem_u32(smem);
    const int bh = blockIdx.x;
    const int b = bh >> 3, h = bh & 7;
    const int l0 = blockIdx.y * 128;
    const int tid = threadIdx.x;
    const int lane = tid & 31, w = tid >> 5;

    {
        const __nv_bfloat16* qh = g_Qh + ((size_t)(b * Ll + l0)) * Cc + h * 64;
        const __nv_bfloat16* ql = g_Ql + ((size_t)(b * Ll + l0)) * Cc + h * 64;
#pragma unroll
        for (int i = 0; i < 8; i++) {
            int idx = tid + i * 128;
            int row = idx >> 3, c16 = idx & 7;
            uint32_t off = SWZ128((uint32_t)(row * 128 + c16 * 16));
            size_t src = (size_t)row * Cc + c16 * 8;
            cpa16(sbase + off, qh + src);
            cpa16(sbase + 16384 + off, ql + src);
        }
        const __nv_bfloat16* bhp = g_KVth + (size_t)bh * 80 * 64;
        const __nv_bfloat16* blp = g_KVtl + (size_t)bh * 80 * 64;
#pragma unroll
        for (int i = 0; i < 5; i++) {
            int idx = tid + i * 128;
            int row = idx >> 3, c16 = idx & 7;
            uint32_t off = SWZ128((uint32_t)(row * 128 + c16 * 16));
            size_t src = (size_t)row * 64 + c16 * 8;
            cpa16(sbase + 32768 + off, bhp + src);
            cpa16(sbase + 43008 + off, blp + src);
        }
        cp_commit();
        cp_wait<0>();
        __syncthreads();
    }

    float acc[2][9][4];
#pragma unroll
    for (int im = 0; im < 2; im++)
#pragma unroll
        for (int t = 0; t < 9; t++)
#pragma unroll
            for (int q = 0; q < 4; q++) acc[im][t][q] = 0.f;

    const uint32_t a_k = (uint32_t)((lane >> 4) * 16);
    const int brow = (lane & 7) + ((lane >> 4) << 3);
    const uint32_t b_k = (uint32_t)(((lane >> 3) & 1) * 16);

#pragma unroll
    for (int ks = 0; ks < 4; ks++) {
        uint32_t aH[2][4], aL[2][4];
#pragma unroll
        for (int im = 0; im < 2; im++) {
            int ar = w * 32 + im * 16 + (lane & 15);
            uint32_t ka = ((uint32_t)(ks * 32) + a_k) ^ ((uint32_t)((ar & 7) * 16));
            ldm4(aH[im], sbase + (uint32_t)ar * 128 + ka);
            ldm4(aL[im], sbase + 16384 + (uint32_t)ar * 128 + ka);
        }
        uint32_t bH[5][4], bL[5][4];
#pragma unroll
        for (int g = 0; g < 5; g++) {
            int br = g * 16 + brow;
            uint32_t kb = ((uint32_t)(ks * 32) + b_k) ^ ((uint32_t)((br & 7) * 16));
            ldm4(bH[g], sbase + 32768 + (uint32_t)br * 128 + kb);
            ldm4(bL[g], sbase + 43008 + (uint32_t)br * 128 + kb);
        }
#pragma unroll
        for (int im = 0; im < 2; im++) {
#pragma unroll
            for (int t = 0; t < 9; t++) {
                const uint32_t* bhr = &bH[t >> 1][(t & 1) * 2];
                const uint32_t* blr = &bL[t >> 1][(t & 1) * 2];
                mma16816(acc[im][t], aH[im], bhr);
                mma16816(acc[im][t], aL[im], bhr);
                mma16816(acc[im][t], aH[im], blr);
            }
        }
    }

#pragma unroll
    for (int im = 0; im < 2; im++) {
        float den0 = __shfl_sync(0xffffffffu, acc[im][8][0], lane & ~3);
        float den1 = __shfl_sync(0xffffffffu, acc[im][8][2], lane & ~3);
        float z0 = 1.f / (den0 + 1e-6f);
        float z1 = 1.f / (den1 + 1e-6f);
        int r0 = w * 32 + im * 16 + (lane >> 2);
        float* o0 = out + ((size_t)(b * Ll + l0 + r0)) * Cc + h * 64 + (lane & 3) * 2;
        float* o1 = out + ((size_t)(b * Ll + l0 + r0 + 8)) * Cc + h * 64 + (lane & 3) * 2;
#pragma unroll
        for (int t = 0; t < 8; t++) {
            *reinterpret_cast<float2*>(o0 + t * 8) =
                make_float2(acc[im][t][0] * z0, acc[im][t][1] * z0);
            *reinterpret_cast<float2*>(o1 + t * 8) =
                make_float2(acc[im][t][2] * z1, acc[im][t][3] * z1);
        }
    }
}

// ---------------------------------------------------------------------------
extern "C" void kernel_launch(void* const* d_in, const int* in_sizes, int n_in,
                              void* d_out, int out_size) {
    const float* x  = (const float*)d_in[0];
    const float* Wq = (const float*)d_in[1];
    const float* bq = (const float*)d_in[2];
    const float* Wk = (const float*)d_in[3];
    const float* bk = (const float*)d_in[4];
    const float* Wv = (const float*)d_in[5];
    const float* bv = (const float*)d_in[6];
    float* out = (float*)d_out;

    cudaFuncSetAttribute(qkv_gemm_tc, cudaFuncAttributeMaxDynamicSharedMemorySize, QSMEM);
    cudaFuncSetAttribute(kv_tc, cudaFuncAttributeMaxDynamicSharedMemorySize, KV_SMEM);
    cudaFuncSetAttribute(out_tc, cudaFuncAttributeMaxDynamicSharedMemorySize, OUT_SMEM);

    zero_acc_kernel<<<512, 256>>>();
    prep_x<<<(int)(((size_t)MM * Cc) / 1024), 256>>>(x);
    prep_w<<<dim3(3, Cc), 128>>>(Wq, Wk, Wv);
    qkv_gemm_tc<<<dim3(12, MM / 128), 128, QSMEM>>>(bq, bk, bv);
    kv_tc<<<dim3(BHn, 16), 128, KV_SMEM>>>();
    kv_finalize<<<BHn, 64>>>();
    out_tc<<<dim3(BHn, Ll / 128), 128, OUT_SMEM>>>(out);
}

// round 6
// speedup vs baseline: 3.5228x; 1.0637x over previous
#include <cuda_runtime.h>
#include <cuda_bf16.h>
#include <cstdint>
#include <math.h>

#define Bb 4
#define Ll 16384
#define Cc 512
#define Hh 8
#define Dd 64
#define MM (Bb*Ll)      // 65536
#define BHn (Bb*Hh)     // 32

// Stage-1 tiling: 128x128 tile, BK=32, hi/lo interleaved rows, 3 stages, 2 CTA/SM
#define QSTAGE 32768
#define QSMEM (3*QSTAGE)
#define QNIT 16          // 512/32

// kv_tc smem: stage = Kh 8K | Kl 8K | Vh 8K | Vl 8K = 32K, 3 stages
#define KV_STAGE 32768
#define KV_SMEM (3*KV_STAGE)
// out_tc smem: Qh 16K | Ql 16K | Bh 10K | Bl 10K
#define OUT_SMEM (16384*2 + 10240*2)

// Scratch
__device__ __nv_bfloat16 g_Xh[(size_t)MM*Cc];
__device__ __nv_bfloat16 g_Xl[(size_t)MM*Cc];
__device__ __nv_bfloat16 g_Wth[3*(size_t)Cc*Cc];  // W^T hi, [z][n][k]
__device__ __nv_bfloat16 g_Wtl[3*(size_t)Cc*Cc];  // W^T lo
__device__ __nv_bfloat16 g_Qh[(size_t)MM*Cc];
__device__ __nv_bfloat16 g_Ql[(size_t)MM*Cc];
__device__ __nv_bfloat16 g_Kh[(size_t)MM*Cc];
__device__ __nv_bfloat16 g_Kl[(size_t)MM*Cc];
__device__ __nv_bfloat16 g_Vh[(size_t)MM*Cc];
__device__ __nv_bfloat16 g_Vl[(size_t)MM*Cc];
__device__ float g_KV[BHn*Dd*Dd];
__device__ float g_Ksum[BHn*Dd];
__device__ __nv_bfloat16 g_KVth[(size_t)BHn*80*64];  // [bh][v-row(80)][d], row64=Ksum
__device__ __nv_bfloat16 g_KVtl[(size_t)BHn*80*64];

// ---------------------------------------------------------------------------
__device__ __forceinline__ uint32_t smem_u32(const void* p) {
    uint32_t a;
    asm("{ .reg .u64 t; cvta.to.shared.u64 t, %1; cvt.u32.u64 %0, t; }" : "=r"(a) : "l"(p));
    return a;
}
#define SWZ128(o) ((o) ^ (((o) >> 3) & 0x70))

__device__ __forceinline__ void cpa16(uint32_t d, const void* s) {
    uint64_t gp;
    asm("cvta.to.global.u64 %0, %1;" : "=l"(gp) : "l"(s));
    asm volatile("cp.async.cg.shared.global [%0], [%1], 16;" :: "r"(d), "l"(gp) : "memory");
}
__device__ __forceinline__ void cp_commit() {
    asm volatile("cp.async.commit_group;" ::: "memory");
}
template<int N> __device__ __forceinline__ void cp_wait() {
    asm volatile("cp.async.wait_group %0;" :: "n"(N) : "memory");
}
__device__ __forceinline__ void ldm4(uint32_t* r, uint32_t a) {
    asm volatile("ldmatrix.sync.aligned.m8n8.x4.shared.b16 {%0,%1,%2,%3}, [%4];"
        : "=r"(r[0]), "=r"(r[1]), "=r"(r[2]), "=r"(r[3]) : "r"(a));
}
__device__ __forceinline__ void ldm4t(uint32_t* r, uint32_t a) {
    asm volatile("ldmatrix.sync.aligned.m8n8.x4.trans.shared.b16 {%0,%1,%2,%3}, [%4];"
        : "=r"(r[0]), "=r"(r[1]), "=r"(r[2]), "=r"(r[3]) : "r"(a));
}
__device__ __forceinline__ void mma16816(float* c, const uint32_t* a, const uint32_t* b) {
    asm volatile("mma.sync.aligned.m16n8k16.row.col.f32.bf16.bf16.f32 "
        "{%0,%1,%2,%3}, {%4,%5,%6,%7}, {%8,%9}, {%0,%1,%2,%3};"
        : "+f"(c[0]), "+f"(c[1]), "+f"(c[2]), "+f"(c[3])
        : "r"(a[0]), "r"(a[1]), "r"(a[2]), "r"(a[3]), "r"(b[0]), "r"(b[1]));
}
__device__ __forceinline__ uint32_t pack_bf16(__nv_bfloat16 a, __nv_bfloat16 b) {
    __nv_bfloat162 t(a, b);
    return *reinterpret_cast<uint32_t*>(&t);
}
__device__ __forceinline__ void split2(float v, __nv_bfloat16& h, __nv_bfloat16& l) {
    h = __float2bfloat16(v);
    l = __float2bfloat16(v - __bfloat162float(h));
}

// ---------------------------------------------------------------------------
__global__ void zero_acc_kernel() {
    int i = blockIdx.x * blockDim.x + threadIdx.x;
    if (i < BHn * Dd * Dd) g_KV[i] = 0.f;
    if (i < BHn * Dd)      g_Ksum[i] = 0.f;
}

__global__ void prep_x(const float* __restrict__ X) {
    size_t i = ((size_t)blockIdx.x * 256 + threadIdx.x) * 4;
    float4 v = *reinterpret_cast<const float4*>(X + i);
    const float* vp = &v.x;
    __nv_bfloat16 h[4], l[4];
#pragma unroll
    for (int q = 0; q < 4; q++) split2(vp[q], h[q], l[q]);
    *reinterpret_cast<uint2*>(g_Xh + i) = make_uint2(pack_bf16(h[0], h[1]), pack_bf16(h[2], h[3]));
    *reinterpret_cast<uint2*>(g_Xl + i) = make_uint2(pack_bf16(l[0], l[1]), pack_bf16(l[2], l[3]));
}

__global__ void prep_w(const float* __restrict__ Wq, const float* __restrict__ Wk,
                       const float* __restrict__ Wv) {
    const int z = blockIdx.x, n = blockIdx.y;
    const float* W = (z == 0) ? Wq : ((z == 1) ? Wk : Wv);
    __nv_bfloat16* dh = g_Wth + ((size_t)z * Cc + n) * Cc;
    __nv_bfloat16* dl = g_Wtl + ((size_t)z * Cc + n) * Cc;
    int k0 = threadIdx.x * 4;
#pragma unroll
    for (int j = 0; j < 4; j++) {
        __nv_bfloat16 h, l;
        split2(W[(size_t)(k0 + j) * Cc + n], h, l);
        dh[k0 + j] = h;
        dl[k0 + j] = l;
    }
}

// ---------------------------------------------------------------------------
// Stage 1: QKV bf16 3-pass split GEMM.
// 128-thread CTAs, warp tile 64x64, BK=32, hi/lo interleaved in 128B rows,
// 3-stage cp.async ring, 2 CTAs/SM. B processed in 32-col halves to cut
// live registers; cp.async issue interleaved with compute.
// ---------------------------------------------------------------------------
__global__ __launch_bounds__(128, 2) void qkv_gemm_tc(
    const float* __restrict__ bq, const float* __restrict__ bk,
    const float* __restrict__ bv)
{
    extern __shared__ char smem[];
    const uint32_t sbase = smem_u32(smem);
    const int tid = threadIdx.x;
    const int z = blockIdx.x >> 2;
    const int col0 = (blockIdx.x & 3) * 128;
    const int row0 = blockIdx.y * 128;
    const int lane = tid & 31, wid = tid >> 5;
    const int wm = (wid & 1) * 64;
    const int wn = (wid >> 1) * 64;

    const __nv_bfloat16* __restrict__ Bh_g = g_Wth + (size_t)z * Cc * Cc;
    const __nv_bfloat16* __restrict__ Bl_g = g_Wtl + (size_t)z * Cc * Cc;
    const float* __restrict__ bias = (z == 0) ? bq : ((z == 1) ? bk : bv);

    // --- async load: half = 0 loads A tile, half = 1 loads B tile ---
    // stage layout: A rows [hi(64B) | lo(64B)] at 0, B rows same at 16384
    const int ld_r = tid >> 3;         // source row 0..15 stride 8 -> r = ld_r + 16*i? no:
    // per half: 1024 cpa16 (128 rows x 8 chunks); each thread does 8
    auto issue_half = [&](int kidx, int buf, int half) {
        uint32_t sb = sbase + buf * QSTAGE + (uint32_t)half * 16384;
        int k0 = kidx * 32;
#pragma unroll
        for (int i = 0; i < 8; i++) {
            int idx = tid + i * 128;          // 0..1023
            int r = idx >> 3;
            int c = idx & 7;                  // 0-3 hi, 4-7 lo
            uint32_t off = SWZ128((uint32_t)(r * 128 + c * 16));
            const __nv_bfloat16* src;
            if (half == 0)
                src = ((c < 4) ? g_Xh : g_Xl) + (size_t)(row0 + r) * Cc + k0 + (c & 3) * 8;
            else
                src = ((c < 4) ? Bh_g : Bl_g) + (size_t)(col0 + r) * Cc + k0 + (c & 3) * 8;
            cpa16(sb + off, src);
        }
    };

    issue_half(0, 0, 0); issue_half(0, 0, 1); cp_commit();
    issue_half(1, 1, 0); issue_half(1, 1, 1); cp_commit();

    float acc[4][8][4];
#pragma unroll
    for (int i = 0; i < 4; i++)
#pragma unroll
        for (int j = 0; j < 8; j++)
#pragma unroll
            for (int q = 0; q < 4; q++) acc[i][j][q] = 0.f;

    // per-warp precomputed addressing (swizzle = XOR of rowxor into bits 4-6)
    const uint32_t a_k = (uint32_t)((lane >> 4) * 16);
    const int a_row_in = lane & 15;
    uint32_t a_rb[4], a_rx[4];
#pragma unroll
    for (int mf = 0; mf < 4; mf++) {
        int ar = wm + mf * 16 + a_row_in;
        a_rb[mf] = (uint32_t)(ar * 128);
        a_rx[mf] = (uint32_t)((ar & 7) * 16);
    }
    const int b_row_in = (lane & 7) + ((lane >> 4) << 3);
    const uint32_t b_k = (uint32_t)(((lane >> 3) & 1) * 16);
    uint32_t b_rb[4], b_rx[4];
#pragma unroll
    for (int g = 0; g < 4; g++) {
        int br = wn + g * 16 + b_row_in;
        b_rb[g] = (uint32_t)(br * 128) + 16384;
        b_rx[g] = (uint32_t)((br & 7) * 16);
    }

    for (int it = 0; it < QNIT; it++) {
        cp_wait<1>();
        __syncthreads();
        uint32_t sb = sbase + (it % 3) * QSTAGE;
        const bool pre = (it + 2 < QNIT);
        const int pk = it + 2;
        const int pb = (it + 2) % 3;

#pragma unroll
        for (int kk = 0; kk < 2; kk++) {
            uint32_t ah[4][4], al[4][4];
            const uint32_t kc = (uint32_t)(kk * 32) + a_k;
#pragma unroll
            for (int mf = 0; mf < 4; mf++) {
                uint32_t hi = sb + a_rb[mf] + (kc ^ a_rx[mf]);
                ldm4(ah[mf], hi);
                ldm4(al[mf], hi ^ 64u);
            }
            const uint32_t kcb = (uint32_t)(kk * 32) + b_k;
#pragma unroll
            for (int nh = 0; nh < 2; nh++) {
                uint32_t bh[2][4], bl[2][4];
#pragma unroll
                for (int gi = 0; gi < 2; gi++) {
                    int g = nh * 2 + gi;
                    uint32_t hi = sb + b_rb[g] + (kcb ^ b_rx[g]);
                    ldm4(bh[gi], hi);
                    ldm4(bl[gi], hi ^ 64u);
                }
#pragma unroll
                for (int mf = 0; mf < 4; mf++) {
#pragma unroll
                    for (int jj = 0; jj < 4; jj++) {
                        const uint32_t* bhr = &bh[jj >> 1][(jj & 1) * 2];
                        const uint32_t* blr = &bl[jj >> 1][(jj & 1) * 2];
                        float* a = acc[mf][nh * 4 + jj];
                        mma16816(a, ah[mf], bhr);
                        mma16816(a, al[mf], bhr);
                        mma16816(a, ah[mf], blr);
                    }
                }
                // interleave next-stage loads with kk=0 compute
                if (kk == 0 && pre) issue_half(pk, pb, nh);
                if (kk == 0 && nh == 1) cp_commit();
            }
        }
        if (!pre) cp_commit();  // keep group count uniform when not prefetching
    }

    // Epilogue: bias + feature map (Q,K), store bf16 hi/lo pairs
    __nv_bfloat16* outH = (z == 0) ? g_Qh : ((z == 1) ? g_Kh : g_Vh);
    __nv_bfloat16* outL = (z == 0) ? g_Ql : ((z == 1) ? g_Kl : g_Vl);
    const int gq = lane >> 2, tq = lane & 3;
#pragma unroll
    for (int mf = 0; mf < 4; mf++) {
#pragma unroll
        for (int hh = 0; hh < 2; hh++) {
            int mg = row0 + wm + mf * 16 + gq + hh * 8;
#pragma unroll
            for (int j = 0; j < 8; j++) {
                int cg = col0 + wn + j * 8 + tq * 2;
                float v0 = acc[mf][j][hh * 2 + 0] + __ldg(bias + cg);
                float v1 = acc[mf][j][hh * 2 + 1] + __ldg(bias + cg + 1);
                if (z < 2) {
                    v0 = (v0 > 0.f) ? (v0 + 1.f) : __expf(v0);
                    v1 = (v1 > 0.f) ? (v1 + 1.f) : __expf(v1);
                }
                __nv_bfloat16 h0, l0, h1, l1;
                split2(v0, h0, l0);
                split2(v1, h1, l1);
                size_t o = (size_t)mg * Cc + cg;
                *reinterpret_cast<uint32_t*>(outH + o) = pack_bf16(h0, h1);
                *reinterpret_cast<uint32_t*>(outL + o) = pack_bf16(l0, l1);
            }
        }
    }
}

// ---------------------------------------------------------------------------
// Stage 2: KV[bh] += K^T V via tensor cores, Ksum via ones-column MMA.
// ---------------------------------------------------------------------------
__global__ __launch_bounds__(128) void kv_tc() {
    extern __shared__ char smem[];
    const uint32_t sbase = smem_u32(smem);
    const int bh = blockIdx.x;
    const int b = bh >> 3, h = bh & 7;
    const int s0 = blockIdx.y * 1024;
    const int tid = threadIdx.x;
    const int lane = tid & 31, w = tid >> 5;

    const __nv_bfloat16* __restrict__ kh = g_Kh + ((size_t)(b * Ll + s0)) * Cc + h * 64;
    const __nv_bfloat16* __restrict__ kl = g_Kl + ((size_t)(b * Ll + s0)) * Cc + h * 64;
    const __nv_bfloat16* __restrict__ vh = g_Vh + ((size_t)(b * Ll + s0)) * Cc + h * 64;
    const __nv_bfloat16* __restrict__ vl = g_Vl + ((size_t)(b * Ll + s0)) * Cc + h * 64;

    auto issue = [&](int st, int buf) {
        uint32_t sb = sbase + buf * KV_STAGE;
#pragma unroll
        for (int i = 0; i < 4; i++) {
            int idx = tid + i * 128;
            int row = idx >> 3, c16 = idx & 7;
            uint32_t off = SWZ128((uint32_t)(row * 128 + c16 * 16));
            size_t src = (size_t)(st * 64 + row) * Cc + c16 * 8;
            cpa16(sb + off,         kh + src);
            cpa16(sb + 8192 + off,  kl + src);
            cpa16(sb + 16384 + off, vh + src);
            cpa16(sb + 24576 + off, vl + src);
        }
        cp_commit();
    };

    issue(0, 0);
    issue(1, 1);

    float accK[8][4], accS[4];
#pragma unroll
    for (int t = 0; t < 8; t++)
#pragma unroll
        for (int q = 0; q < 4; q++) accK[t][q] = 0.f;
#pragma unroll
    for (int q = 0; q < 4; q++) accS[q] = 0.f;

    const uint32_t ones = ((lane >> 2) == 0) ? 0x3F803F80u : 0u;
    uint32_t onef[2] = {ones, ones};

    const uint32_t a_col = (uint32_t)((w * 16 + ((lane >> 4) << 3)) * 2);

    for (int st = 0; st < 16; st++) {
        cp_wait<1>();
        __syncthreads();
        if (st + 2 < 16) issue(st + 2, (st + 2) % 3);
        else cp_commit();

        uint32_t sb = sbase + (st % 3) * KV_STAGE;
#pragma unroll
        for (int s16 = 0; s16 < 4; s16++) {
            uint32_t rowb = (uint32_t)((s16 * 16 + (lane & 15)) * 128);
            uint32_t offA = SWZ128(rowb + a_col);
            uint32_t rh[4], rl[4];
            ldm4t(rh, sb + offA);
            ldm4t(rl, sb + 8192 + offA);
            uint32_t Ah[4] = {rh[0], rh[2], rh[1], rh[3]};
            uint32_t Al[4] = {rl[0], rl[2], rl[1], rl[3]};
            uint32_t bhf[4][4], blf[4][4];
#pragma unroll
            for (int g = 0; g < 4; g++) {
                uint32_t offV = SWZ128(rowb + (uint32_t)((g * 16 + ((lane >> 4) << 3)) * 2));
                ldm4t(bhf[g], sb + 16384 + offV);
                ldm4t(blf[g], sb + 24576 + offV);
            }
#pragma unroll
            for (int t = 0; t < 8; t++) {
                const uint32_t* bhr = &bhf[t >> 1][(t & 1) * 2];
                const uint32_t* blr = &blf[t >> 1][(t & 1) * 2];
                mma16816(accK[t], Ah, bhr);
                mma16816(accK[t], Al, bhr);
                mma16816(accK[t], Ah, blr);
            }
            mma16816(accS, Ah, onef);
            mma16816(accS, Al, onef);
        }
    }

    const int d0 = w * 16 + (lane >> 2);
    float* KVp = g_KV + (size_t)bh * 4096;
#pragma unroll
    for (int t = 0; t < 8; t++) {
        int v = t * 8 + (lane & 3) * 2;
        atomicAdd(KVp + d0 * 64 + v,           accK[t][0]);
        atomicAdd(KVp + d0 * 64 + v + 1,       accK[t][1]);
        atomicAdd(KVp + (d0 + 8) * 64 + v,     accK[t][2]);
        atomicAdd(KVp + (d0 + 8) * 64 + v + 1, accK[t][3]);
    }
    if ((lane & 3) == 0) {
        atomicAdd(g_Ksum + bh * 64 + d0,     accS[0]);
        atomicAdd(g_Ksum + bh * 64 + d0 + 8, accS[2]);
    }
}

// ---------------------------------------------------------------------------
// Finalize: KVt[bh][v][d] = KV[bh][d][v] as bf16 hi/lo; row 64 = Ksum; 65-79 = 0.
// ---------------------------------------------------------------------------
__global__ void kv_finalize() {
    const int bh = blockIdx.x;
    const int v = threadIdx.x;   // 0..63
    __nv_bfloat16* oh = g_KVth + (size_t)bh * 80 * 64;
    __nv_bfloat16* ol = g_KVtl + (size_t)bh * 80 * 64;
    const float* kv = g_KV + (size_t)bh * 4096;
#pragma unroll 8
    for (int d = 0; d < 64; d++) {
        __nv_bfloat16 h, l;
        split2(kv[d * 64 + v], h, l);
        oh[v * 64 + d] = h;
        ol[v * 64 + d] = l;
    }
    __nv_bfloat16 h, l;
    split2(g_Ksum[bh * 64 + v], h, l);
    oh[64 * 64 + v] = h;
    ol[64 * 64 + v] = l;
#pragma unroll
    for (int r = 65; r < 80; r++) {
        oh[r * 64 + v] = __float2bfloat16(0.f);
        ol[r * 64 + v] = __float2bfloat16(0.f);
    }
}

// ---------------------------------------------------------------------------
// Stage 3: out = (Q @ KVext) with normalizer from column 64 (Ksum row of KVt).
// ---------------------------------------------------------------------------
__global__ __launch_bounds__(128) void out_tc(float* __restrict__ out) {
    extern __shared__ char smem[];
    const uint32_t sbase = smem_u32(smem);
    const int bh = blockIdx.x;
    const int b = bh >> 3, h = bh & 7;
    const int l0 = blockIdx.y * 128;
    const int tid = threadIdx.x;
    const int lane = tid & 31, w = tid >> 5;

    {
        const __nv_bfloat16* qh = g_Qh + ((size_t)(b * Ll + l0)) * Cc + h * 64;
        const __nv_bfloat16* ql = g_Ql + ((size_t)(b * Ll + l0)) * Cc + h * 64;
#pragma unroll
        for (int i = 0; i < 8; i++) {
            int idx = tid + i * 128;
            int row = idx >> 3, c16 = idx & 7;
            uint32_t off = SWZ128((uint32_t)(row * 128 + c16 * 16));
            size_t src = (size_t)row * Cc + c16 * 8;
            cpa16(sbase + off, qh + src);
            cpa16(sbase + 16384 + off, ql + src);
        }
        const __nv_bfloat16* bhp = g_KVth + (size_t)bh * 80 * 64;
        const __nv_bfloat16* blp = g_KVtl + (size_t)bh * 80 * 64;
#pragma unroll
        for (int i = 0; i < 5; i++) {
            int idx = tid + i * 128;
            int row = idx >> 3, c16 = idx & 7;
            uint32_t off = SWZ128((uint32_t)(row * 128 + c16 * 16));
            size_t src = (size_t)row * 64 + c16 * 8;
            cpa16(sbase + 32768 + off, bhp + src);
            cpa16(sbase + 43008 + off, blp + src);
        }
        cp_commit();
        cp_wait<0>();
        __syncthreads();
    }

    float acc[2][9][4];
#pragma unroll
    for (int im = 0; im < 2; im++)
#pragma unroll
        for (int t = 0; t < 9; t++)
#pragma unroll
            for (int q = 0; q < 4; q++) acc[im][t][q] = 0.f;

    const uint32_t a_k = (uint32_t)((lane >> 4) * 16);
    const int brow = (lane & 7) + ((lane >> 4) << 3);
    const uint32_t b_k = (uint32_t)(((lane >> 3) & 1) * 16);

#pragma unroll
    for (int ks = 0; ks < 4; ks++) {
        uint32_t aH[2][4], aL[2][4];
#pragma unroll
        for (int im = 0; im < 2; im++) {
            int ar = w * 32 + im * 16 + (lane & 15);
            uint32_t ka = ((uint32_t)(ks * 32) + a_k) ^ ((uint32_t)((ar & 7) * 16));
            ldm4(aH[im], sbase + (uint32_t)ar * 128 + ka);
            ldm4(aL[im], sbase + 16384 + (uint32_t)ar * 128 + ka);
        }
        uint32_t bH[5][4], bL[5][4];
#pragma unroll
        for (int g = 0; g < 5; g++) {
            int br = g * 16 + brow;
            uint32_t kb = ((uint32_t)(ks * 32) + b_k) ^ ((uint32_t)((br & 7) * 16));
            ldm4(bH[g], sbase + 32768 + (uint32_t)br * 128 + kb);
            ldm4(bL[g], sbase + 43008 + (uint32_t)br * 128 + kb);
        }
#pragma unroll
        for (int im = 0; im < 2; im++) {
#pragma unroll
            for (int t = 0; t < 9; t++) {
                const uint32_t* bhr = &bH[t >> 1][(t & 1) * 2];
                const uint32_t* blr = &bL[t >> 1][(t & 1) * 2];
                mma16816(acc[im][t], aH[im], bhr);
                mma16816(acc[im][t], aL[im], bhr);
                mma16816(acc[im][t], aH[im], blr);
            }
        }
    }

#pragma unroll
    for (int im = 0; im < 2; im++) {
        float den0 = __shfl_sync(0xffffffffu, acc[im][8][0], lane & ~3);
        float den1 = __shfl_sync(0xffffffffu, acc[im][8][2], lane & ~3);
        float z0 = 1.f / (den0 + 1e-6f);
        float z1 = 1.f / (den1 + 1e-6f);
        int r0 = w * 32 + im * 16 + (lane >> 2);
        float* o0 = out + ((size_t)(b * Ll + l0 + r0)) * Cc + h * 64 + (lane & 3) * 2;
        float* o1 = out + ((size_t)(b * Ll + l0 + r0 + 8)) * Cc + h * 64 + (lane & 3) * 2;
#pragma unroll
        for (int t = 0; t < 8; t++) {
            *reinterpret_cast<float2*>(o0 + t * 8) =
                make_float2(acc[im][t][0] * z0, acc[im][t][1] * z0);
            *reinterpret_cast<float2*>(o1 + t * 8) =
                make_float2(acc[im][t][2] * z1, acc[im][t][3] * z1);
        }
    }
}

// ---------------------------------------------------------------------------
extern "C" void kernel_launch(void* const* d_in, const int* in_sizes, int n_in,
                              void* d_out, int out_size) {
    const float* x  = (const float*)d_in[0];
    const float* Wq = (const float*)d_in[1];
    const float* bq = (const float*)d_in[2];
    const float* Wk = (const float*)d_in[3];
    const float* bk = (const float*)d_in[4];
    const float* Wv = (const float*)d_in[5];
    const float* bv = (const float*)d_in[6];
    float* out = (float*)d_out;

    cudaFuncSetAttribute(qkv_gemm_tc, cudaFuncAttributeMaxDynamicSharedMemorySize, QSMEM);
    cudaFuncSetAttribute(kv_tc, cudaFuncAttributeMaxDynamicSharedMemorySize, KV_SMEM);
    cudaFuncSetAttribute(out_tc, cudaFuncAttributeMaxDynamicSharedMemorySize, OUT_SMEM);

    zero_acc_kernel<<<512, 256>>>();
    prep_x<<<(int)(((size_t)MM * Cc) / 1024), 256>>>(x);
    prep_w<<<dim3(3, Cc), 128>>>(Wq, Wk, Wv);
    qkv_gemm_tc<<<dim3(12, MM / 128), 128, QSMEM>>>(bq, bk, bv);
    kv_tc<<<dim3(BHn, 16), 128, KV_SMEM>>>();
    kv_finalize<<<BHn, 64>>>();
    out_tc<<<dim3(BHn, Ll / 128), 128, OUT_SMEM>>>(out);
}

// round 7
// speedup vs baseline: 3.5472x; 1.0069x over previous
#include <cuda_runtime.h>
#include <cuda_bf16.h>
#include <cstdint>
#include <math.h>

#define Bb 4
#define Ll 16384
#define Cc 512
#define Hh 8
#define Dd 64
#define MM (Bb*Ll)      // 65536
#define BHn (Bb*Hh)     // 32

// Stage-1 tiling: 128x128 tile, BK=32, hi/lo interleaved rows, 3 stages, 2 CTA/SM
#define QSTAGE 32768
#define QSMEM (3*QSTAGE)
#define QNIT 16          // 512/32

// kv_tc smem: stage = Kh 8K | Kl 8K | Vh 8K | Vl 8K = 32K, 3 stages
#define KV_STAGE 32768
#define KV_SMEM (3*KV_STAGE)
// out_tc smem: Qh 16K | Ql 16K | Bh 10K | Bl 10K
#define OUT_SMEM (16384*2 + 10240*2)

// Scratch
__device__ __nv_bfloat16 g_Xh[(size_t)MM*Cc];
__device__ __nv_bfloat16 g_Xl[(size_t)MM*Cc];
__device__ __nv_bfloat16 g_Wth[3*(size_t)Cc*Cc];  // W^T hi, [z][n][k]
__device__ __nv_bfloat16 g_Wtl[3*(size_t)Cc*Cc];  // W^T lo
__device__ __nv_bfloat16 g_Qh[(size_t)MM*Cc];
__device__ __nv_bfloat16 g_Ql[(size_t)MM*Cc];
__device__ __nv_bfloat16 g_Kh[(size_t)MM*Cc];
__device__ __nv_bfloat16 g_Kl[(size_t)MM*Cc];
__device__ __nv_bfloat16 g_Vh[(size_t)MM*Cc];
__device__ __nv_bfloat16 g_Vl[(size_t)MM*Cc];
__device__ float g_KV[BHn*Dd*Dd];
__device__ float g_Ksum[BHn*Dd];
__device__ __nv_bfloat16 g_KVth[(size_t)BHn*80*64];  // [bh][v-row(80)][d], row64=Ksum
__device__ __nv_bfloat16 g_KVtl[(size_t)BHn*80*64];

// ---------------------------------------------------------------------------
__device__ __forceinline__ uint32_t smem_u32(const void* p) {
    uint32_t a;
    asm("{ .reg .u64 t; cvta.to.shared.u64 t, %1; cvt.u32.u64 %0, t; }" : "=r"(a) : "l"(p));
    return a;
}
#define SWZ128(o) ((o) ^ (((o) >> 3) & 0x70))

__device__ __forceinline__ void cpa16(uint32_t d, const void* s) {
    uint64_t gp;
    asm("cvta.to.global.u64 %0, %1;" : "=l"(gp) : "l"(s));
    asm volatile("cp.async.cg.shared.global [%0], [%1], 16;" :: "r"(d), "l"(gp) : "memory");
}
__device__ __forceinline__ void cp_commit() {
    asm volatile("cp.async.commit_group;" ::: "memory");
}
template<int N> __device__ __forceinline__ void cp_wait() {
    asm volatile("cp.async.wait_group %0;" :: "n"(N) : "memory");
}
__device__ __forceinline__ void ldm4(uint32_t* r, uint32_t a) {
    asm volatile("ldmatrix.sync.aligned.m8n8.x4.shared.b16 {%0,%1,%2,%3}, [%4];"
        : "=r"(r[0]), "=r"(r[1]), "=r"(r[2]), "=r"(r[3]) : "r"(a));
}
__device__ __forceinline__ void ldm4t(uint32_t* r, uint32_t a) {
    asm volatile("ldmatrix.sync.aligned.m8n8.x4.trans.shared.b16 {%0,%1,%2,%3}, [%4];"
        : "=r"(r[0]), "=r"(r[1]), "=r"(r[2]), "=r"(r[3]) : "r"(a));
}
__device__ __forceinline__ void mma16816(float* c, const uint32_t* a, const uint32_t* b) {
    asm volatile("mma.sync.aligned.m16n8k16.row.col.f32.bf16.bf16.f32 "
        "{%0,%1,%2,%3}, {%4,%5,%6,%7}, {%8,%9}, {%0,%1,%2,%3};"
        : "+f"(c[0]), "+f"(c[1]), "+f"(c[2]), "+f"(c[3])
        : "r"(a[0]), "r"(a[1]), "r"(a[2]), "r"(a[3]), "r"(b[0]), "r"(b[1]));
}
__device__ __forceinline__ uint32_t pack_bf16(__nv_bfloat16 a, __nv_bfloat16 b) {
    __nv_bfloat162 t(a, b);
    return *reinterpret_cast<uint32_t*>(&t);
}
__device__ __forceinline__ void split2(float v, __nv_bfloat16& h, __nv_bfloat16& l) {
    h = __float2bfloat16(v);
    l = __float2bfloat16(v - __bfloat162float(h));
}

// ---------------------------------------------------------------------------
__global__ void zero_acc_kernel() {
    int i = blockIdx.x * blockDim.x + threadIdx.x;
    if (i < BHn * Dd * Dd) g_KV[i] = 0.f;
    if (i < BHn * Dd)      g_Ksum[i] = 0.f;
}

__global__ void prep_x(const float* __restrict__ X) {
    size_t i = ((size_t)blockIdx.x * 256 + threadIdx.x) * 4;
    float4 v = *reinterpret_cast<const float4*>(X + i);
    const float* vp = &v.x;
    __nv_bfloat16 h[4], l[4];
#pragma unroll
    for (int q = 0; q < 4; q++) split2(vp[q], h[q], l[q]);
    *reinterpret_cast<uint2*>(g_Xh + i) = make_uint2(pack_bf16(h[0], h[1]), pack_bf16(h[2], h[3]));
    *reinterpret_cast<uint2*>(g_Xl + i) = make_uint2(pack_bf16(l[0], l[1]), pack_bf16(l[2], l[3]));
}

__global__ void prep_w(const float* __restrict__ Wq, const float* __restrict__ Wk,
                       const float* __restrict__ Wv) {
    const int z = blockIdx.x, n = blockIdx.y;
    const float* W = (z == 0) ? Wq : ((z == 1) ? Wk : Wv);
    __nv_bfloat16* dh = g_Wth + ((size_t)z * Cc + n) * Cc;
    __nv_bfloat16* dl = g_Wtl + ((size_t)z * Cc + n) * Cc;
    int k0 = threadIdx.x * 4;
#pragma unroll
    for (int j = 0; j < 4; j++) {
        __nv_bfloat16 h, l;
        split2(W[(size_t)(k0 + j) * Cc + n], h, l);
        dh[k0 + j] = h;
        dl[k0 + j] = l;
    }
}

// ---------------------------------------------------------------------------
// Stage 1: QKV bf16 3-pass split GEMM.
// 128-thread CTAs, warp tile 64x64, BK=32, hi/lo interleaved in 128B rows,
// 3-stage cp.async ring, 2 CTAs/SM. Pass-major MMA ordering: dependent MMAs
// on the same accumulator are 16 apart.
// ---------------------------------------------------------------------------
__global__ __launch_bounds__(128, 2) void qkv_gemm_tc(
    const float* __restrict__ bq, const float* __restrict__ bk,
    const float* __restrict__ bv)
{
    extern __shared__ char smem[];
    const uint32_t sbase = smem_u32(smem);
    const int tid = threadIdx.x;
    const int z = blockIdx.x >> 2;
    const int col0 = (blockIdx.x & 3) * 128;
    const int row0 = blockIdx.y * 128;
    const int lane = tid & 31, wid = tid >> 5;
    const int wm = (wid & 1) * 64;
    const int wn = (wid >> 1) * 64;

    const __nv_bfloat16* __restrict__ Bh_g = g_Wth + (size_t)z * Cc * Cc;
    const __nv_bfloat16* __restrict__ Bl_g = g_Wtl + (size_t)z * Cc * Cc;
    const float* __restrict__ bias = (z == 0) ? bq : ((z == 1) ? bk : bv);

    // stage layout: A rows [hi(64B) | lo(64B)] at 0, B rows same at 16384
    auto issue_half = [&](int kidx, int buf, int half) {
        uint32_t sb = sbase + buf * QSTAGE + (uint32_t)half * 16384;
        int k0 = kidx * 32;
#pragma unroll
        for (int i = 0; i < 8; i++) {
            int idx = tid + i * 128;          // 0..1023
            int r = idx >> 3;
            int c = idx & 7;                  // 0-3 hi, 4-7 lo
            uint32_t off = SWZ128((uint32_t)(r * 128 + c * 16));
            const __nv_bfloat16* src;
            if (half == 0)
                src = ((c < 4) ? g_Xh : g_Xl) + (size_t)(row0 + r) * Cc + k0 + (c & 3) * 8;
            else
                src = ((c < 4) ? Bh_g : Bl_g) + (size_t)(col0 + r) * Cc + k0 + (c & 3) * 8;
            cpa16(sb + off, src);
        }
    };

    issue_half(0, 0, 0); issue_half(0, 0, 1); cp_commit();
    issue_half(1, 1, 0); issue_half(1, 1, 1); cp_commit();

    float acc[4][8][4];
#pragma unroll
    for (int i = 0; i < 4; i++)
#pragma unroll
        for (int j = 0; j < 8; j++)
#pragma unroll
            for (int q = 0; q < 4; q++) acc[i][j][q] = 0.f;

    // per-warp precomputed addressing (swizzle = XOR of rowxor into bits 4-6)
    const uint32_t a_k = (uint32_t)((lane >> 4) * 16);
    const int a_row_in = lane & 15;
    uint32_t a_rb[4], a_rx[4];
#pragma unroll
    for (int mf = 0; mf < 4; mf++) {
        int ar = wm + mf * 16 + a_row_in;
        a_rb[mf] = (uint32_t)(ar * 128);
        a_rx[mf] = (uint32_t)((ar & 7) * 16);
    }
    const int b_row_in = (lane & 7) + ((lane >> 4) << 3);
    const uint32_t b_k = (uint32_t)(((lane >> 3) & 1) * 16);
    uint32_t b_rb[4], b_rx[4];
#pragma unroll
    for (int g = 0; g < 4; g++) {
        int br = wn + g * 16 + b_row_in;
        b_rb[g] = (uint32_t)(br * 128) + 16384;
        b_rx[g] = (uint32_t)((br & 7) * 16);
    }

    for (int it = 0; it < QNIT; it++) {
        cp_wait<1>();
        __syncthreads();
        uint32_t sb = sbase + (it % 3) * QSTAGE;
        const bool pre = (it + 2 < QNIT);
        const int pk = it + 2;
        const int pb = (it + 2) % 3;

#pragma unroll
        for (int kk = 0; kk < 2; kk++) {
            uint32_t ah[4][4], al[4][4];
            const uint32_t kc = (uint32_t)(kk * 32) + a_k;
#pragma unroll
            for (int mf = 0; mf < 4; mf++) {
                uint32_t hi = sb + a_rb[mf] + (kc ^ a_rx[mf]);
                ldm4(ah[mf], hi);
                ldm4(al[mf], hi ^ 64u);
            }
            const uint32_t kcb = (uint32_t)(kk * 32) + b_k;
#pragma unroll
            for (int nh = 0; nh < 2; nh++) {
                uint32_t bh[2][4], bl[2][4];
#pragma unroll
                for (int gi = 0; gi < 2; gi++) {
                    int g = nh * 2 + gi;
                    uint32_t hi = sb + b_rb[g] + (kcb ^ b_rx[g]);
                    ldm4(bh[gi], hi);
                    ldm4(bl[gi], hi ^ 64u);
                }
                // pass-major: all 16 MMAs of a pass hit distinct accumulators
#pragma unroll
                for (int mf = 0; mf < 4; mf++)
#pragma unroll
                    for (int jj = 0; jj < 4; jj++)
                        mma16816(acc[mf][nh * 4 + jj], ah[mf], &bh[jj >> 1][(jj & 1) * 2]);
#pragma unroll
                for (int mf = 0; mf < 4; mf++)
#pragma unroll
                    for (int jj = 0; jj < 4; jj++)
                        mma16816(acc[mf][nh * 4 + jj], al[mf], &bh[jj >> 1][(jj & 1) * 2]);
#pragma unroll
                for (int mf = 0; mf < 4; mf++)
#pragma unroll
                    for (int jj = 0; jj < 4; jj++)
                        mma16816(acc[mf][nh * 4 + jj], ah[mf], &bl[jj >> 1][(jj & 1) * 2]);
                // interleave next-stage loads with kk=0 compute
                if (kk == 0 && pre) issue_half(pk, pb, nh);
                if (kk == 0 && nh == 1) cp_commit();
            }
        }
        if (!pre) cp_commit();  // keep group count uniform when not prefetching
    }

    // Epilogue: bias + feature map (Q,K), store bf16 hi/lo pairs
    __nv_bfloat16* outH = (z == 0) ? g_Qh : ((z == 1) ? g_Kh : g_Vh);
    __nv_bfloat16* outL = (z == 0) ? g_Ql : ((z == 1) ? g_Kl : g_Vl);
    const int gq = lane >> 2, tq = lane & 3;
#pragma unroll
    for (int mf = 0; mf < 4; mf++) {
#pragma unroll
        for (int hh = 0; hh < 2; hh++) {
            int mg = row0 + wm + mf * 16 + gq + hh * 8;
#pragma unroll
            for (int j = 0; j < 8; j++) {
                int cg = col0 + wn + j * 8 + tq * 2;
                float v0 = acc[mf][j][hh * 2 + 0] + __ldg(bias + cg);
                float v1 = acc[mf][j][hh * 2 + 1] + __ldg(bias + cg + 1);
                if (z < 2) {
                    v0 = (v0 > 0.f) ? (v0 + 1.f) : __expf(v0);
                    v1 = (v1 > 0.f) ? (v1 + 1.f) : __expf(v1);
                }
                __nv_bfloat16 h0, l0, h1, l1;
                split2(v0, h0, l0);
                split2(v1, h1, l1);
                size_t o = (size_t)mg * Cc + cg;
                *reinterpret_cast<uint32_t*>(outH + o) = pack_bf16(h0, h1);
                *reinterpret_cast<uint32_t*>(outL + o) = pack_bf16(l0, l1);
            }
        }
    }
}

// ---------------------------------------------------------------------------
// Stage 2: KV[bh] += K^T V via tensor cores, Ksum via ones-column MMA.
// ---------------------------------------------------------------------------
__global__ __launch_bounds__(128) void kv_tc() {
    extern __shared__ char smem[];
    const uint32_t sbase = smem_u32(smem);
    const int bh = blockIdx.x;
    const int b = bh >> 3, h = bh & 7;
    const int s0 = blockIdx.y * 1024;
    const int tid = threadIdx.x;
    const int lane = tid & 31, w = tid >> 5;

    const __nv_bfloat16* __restrict__ kh = g_Kh + ((size_t)(b * Ll + s0)) * Cc + h * 64;
    const __nv_bfloat16* __restrict__ kl = g_Kl + ((size_t)(b * Ll + s0)) * Cc + h * 64;
    const __nv_bfloat16* __restrict__ vh = g_Vh + ((size_t)(b * Ll + s0)) * Cc + h * 64;
    const __nv_bfloat16* __restrict__ vl = g_Vl + ((size_t)(b * Ll + s0)) * Cc + h * 64;

    auto issue = [&](int st, int buf) {
        uint32_t sb = sbase + buf * KV_STAGE;
#pragma unroll
        for (int i = 0; i < 4; i++) {
            int idx = tid + i * 128;
            int row = idx >> 3, c16 = idx & 7;
            uint32_t off = SWZ128((uint32_t)(row * 128 + c16 * 16));
            size_t src = (size_t)(st * 64 + row) * Cc + c16 * 8;
            cpa16(sb + off,         kh + src);
            cpa16(sb + 8192 + off,  kl + src);
            cpa16(sb + 16384 + off, vh + src);
            cpa16(sb + 24576 + off, vl + src);
        }
        cp_commit();
    };

    issue(0, 0);
    issue(1, 1);

    float accK[8][4], accS[4];
#pragma unroll
    for (int t = 0; t < 8; t++)
#pragma unroll
        for (int q = 0; q < 4; q++) accK[t][q] = 0.f;
#pragma unroll
    for (int q = 0; q < 4; q++) accS[q] = 0.f;

    const uint32_t ones = ((lane >> 2) == 0) ? 0x3F803F80u : 0u;
    uint32_t onef[2] = {ones, ones};

    const uint32_t a_col = (uint32_t)((w * 16 + ((lane >> 4) << 3)) * 2);

    for (int st = 0; st < 16; st++) {
        cp_wait<1>();
        __syncthreads();
        if (st + 2 < 16) issue(st + 2, (st + 2) % 3);
        else cp_commit();

        uint32_t sb = sbase + (st % 3) * KV_STAGE;
#pragma unroll
        for (int s16 = 0; s16 < 4; s16++) {
            uint32_t rowb = (uint32_t)((s16 * 16 + (lane & 15)) * 128);
            uint32_t offA = SWZ128(rowb + a_col);
            uint32_t rh[4], rl[4];
            ldm4t(rh, sb + offA);
            ldm4t(rl, sb + 8192 + offA);
            uint32_t Ah[4] = {rh[0], rh[2], rh[1], rh[3]};
            uint32_t Al[4] = {rl[0], rl[2], rl[1], rl[3]};
            uint32_t bhf[4][4], blf[4][4];
#pragma unroll
            for (int g = 0; g < 4; g++) {
                uint32_t offV = SWZ128(rowb + (uint32_t)((g * 16 + ((lane >> 4) << 3)) * 2));
                ldm4t(bhf[g], sb + 16384 + offV);
                ldm4t(blf[g], sb + 24576 + offV);
            }
#pragma unroll
            for (int t = 0; t < 8; t++)
                mma16816(accK[t], Ah, &bhf[t >> 1][(t & 1) * 2]);
#pragma unroll
            for (int t = 0; t < 8; t++)
                mma16816(accK[t], Al, &bhf[t >> 1][(t & 1) * 2]);
#pragma unroll
            for (int t = 0; t < 8; t++)
                mma16816(accK[t], Ah, &blf[t >> 1][(t & 1) * 2]);
            mma16816(accS, Ah, onef);
            mma16816(accS, Al, onef);
        }
    }

    const int d0 = w * 16 + (lane >> 2);
    float* KVp = g_KV + (size_t)bh * 4096;
#pragma unroll
    for (int t = 0; t < 8; t++) {
        int v = t * 8 + (lane & 3) * 2;
        atomicAdd(KVp + d0 * 64 + v,           accK[t][0]);
        atomicAdd(KVp + d0 * 64 + v + 1,       accK[t][1]);
        atomicAdd(KVp + (d0 + 8) * 64 + v,     accK[t][2]);
        atomicAdd(KVp + (d0 + 8) * 64 + v + 1, accK[t][3]);
    }
    if ((lane & 3) == 0) {
        atomicAdd(g_Ksum + bh * 64 + d0,     accS[0]);
        atomicAdd(g_Ksum + bh * 64 + d0 + 8, accS[2]);
    }
}

// ---------------------------------------------------------------------------
// Finalize: KVt[bh][v][d] = KV[bh][d][v] as bf16 hi/lo; row 64 = Ksum; 65-79 = 0.
// ---------------------------------------------------------------------------
__global__ void kv_finalize() {
    const int bh = blockIdx.x;
    const int v = threadIdx.x;   // 0..63
    __nv_bfloat16* oh = g_KVth + (size_t)bh * 80 * 64;
    __nv_bfloat16* ol = g_KVtl + (size_t)bh * 80 * 64;
    const float* kv = g_KV + (size_t)bh * 4096;
#pragma unroll 8
    for (int d = 0; d < 64; d++) {
        __nv_bfloat16 h, l;
        split2(kv[d * 64 + v], h, l);
        oh[v * 64 + d] = h;
        ol[v * 64 + d] = l;
    }
    __nv_bfloat16 h, l;
    split2(g_Ksum[bh * 64 + v], h, l);
    oh[64 * 64 + v] = h;
    ol[64 * 64 + v] = l;
#pragma unroll
    for (int r = 65; r < 80; r++) {
        oh[r * 64 + v] = __float2bfloat16(0.f);
        ol[r * 64 + v] = __float2bfloat16(0.f);
    }
}

// ---------------------------------------------------------------------------
// Stage 3: out = (Q @ KVext) with normalizer from column 64 (Ksum row of KVt).
// ---------------------------------------------------------------------------
__global__ __launch_bounds__(128) void out_tc(float* __restrict__ out) {
    extern __shared__ char smem[];
    const uint32_t sbase = smem_u32(smem);
    const int bh = blockIdx.x;
    const int b = bh >> 3, h = bh & 7;
    const int l0 = blockIdx.y * 128;
    const int tid = threadIdx.x;
    const int lane = tid & 31, w = tid >> 5;

    {
        const __nv_bfloat16* qh = g_Qh + ((size_t)(b * Ll + l0)) * Cc + h * 64;
        const __nv_bfloat16* ql = g_Ql + ((size_t)(b * Ll + l0)) * Cc + h * 64;
#pragma unroll
        for (int i = 0; i < 8; i++) {
            int idx = tid + i * 128;
            int row = idx >> 3, c16 = idx & 7;
            uint32_t off = SWZ128((uint32_t)(row * 128 + c16 * 16));
            size_t src = (size_t)row * Cc + c16 * 8;
            cpa16(sbase + off, qh + src);
            cpa16(sbase + 16384 + off, ql + src);
        }
        const __nv_bfloat16* bhp = g_KVth + (size_t)bh * 80 * 64;
        const __nv_bfloat16* blp = g_KVtl + (size_t)bh * 80 * 64;
#pragma unroll
        for (int i = 0; i < 5; i++) {
            int idx = tid + i * 128;
            int row = idx >> 3, c16 = idx & 7;
            uint32_t off = SWZ128((uint32_t)(row * 128 + c16 * 16));
            size_t src = (size_t)row * 64 + c16 * 8;
            cpa16(sbase + 32768 + off, bhp + src);
            cpa16(sbase + 43008 + off, blp + src);
        }
        cp_commit();
        cp_wait<0>();
        __syncthreads();
    }

    float acc[2][9][4];
#pragma unroll
    for (int im = 0; im < 2; im++)
#pragma unroll
        for (int t = 0; t < 9; t++)
#pragma unroll
            for (int q = 0; q < 4; q++) acc[im][t][q] = 0.f;

    const uint32_t a_k = (uint32_t)((lane >> 4) * 16);
    const int brow = (lane & 7) + ((lane >> 4) << 3);
    const uint32_t b_k = (uint32_t)(((lane >> 3) & 1) * 16);

#pragma unroll
    for (int ks = 0; ks < 4; ks++) {
        uint32_t aH[2][4], aL[2][4];
#pragma unroll
        for (int im = 0; im < 2; im++) {
            int ar = w * 32 + im * 16 + (lane & 15);
            uint32_t ka = ((uint32_t)(ks * 32) + a_k) ^ ((uint32_t)((ar & 7) * 16));
            ldm4(aH[im], sbase + (uint32_t)ar * 128 + ka);
            ldm4(aL[im], sbase + 16384 + (uint32_t)ar * 128 + ka);
        }
        uint32_t bH[5][4], bL[5][4];
#pragma unroll
        for (int g = 0; g < 5; g++) {
            int br = g * 16 + brow;
            uint32_t kb = ((uint32_t)(ks * 32) + b_k) ^ ((uint32_t)((br & 7) * 16));
            ldm4(bH[g], sbase + 32768 + (uint32_t)br * 128 + kb);
            ldm4(bL[g], sbase + 43008 + (uint32_t)br * 128 + kb);
        }
#pragma unroll
        for (int im = 0; im < 2; im++)
#pragma unroll
            for (int t = 0; t < 9; t++)
                mma16816(acc[im][t], aH[im], &bH[t >> 1][(t & 1) * 2]);
#pragma unroll
        for (int im = 0; im < 2; im++)
#pragma unroll
            for (int t = 0; t < 9; t++)
                mma16816(acc[im][t], aL[im], &bH[t >> 1][(t & 1) * 2]);
#pragma unroll
        for (int im = 0; im < 2; im++)
#pragma unroll
            for (int t = 0; t < 9; t++)
                mma16816(acc[im][t], aH[im], &bL[t >> 1][(t & 1) * 2]);
    }

#pragma unroll
    for (int im = 0; im < 2; im++) {
        float den0 = __shfl_sync(0xffffffffu, acc[im][8][0], lane & ~3);
        float den1 = __shfl_sync(0xffffffffu, acc[im][8][2], lane & ~3);
        float z0 = 1.f / (den0 + 1e-6f);
        float z1 = 1.f / (den1 + 1e-6f);
        int r0 = w * 32 + im * 16 + (lane >> 2);
        float* o0 = out + ((size_t)(b * Ll + l0 + r0)) * Cc + h * 64 + (lane & 3) * 2;
        float* o1 = out + ((size_t)(b * Ll + l0 + r0 + 8)) * Cc + h * 64 + (lane & 3) * 2;
#pragma unroll
        for (int t = 0; t < 8; t++) {
            *reinterpret_cast<float2*>(o0 + t * 8) =
                make_float2(acc[im][t][0] * z0, acc[im][t][1] * z0);
            *reinterpret_cast<float2*>(o1 + t * 8) =
                make_float2(acc[im][t][2] * z1, acc[im][t][3] * z1);
        }
    }
}

// ---------------------------------------------------------------------------
extern "C" void kernel_launch(void* const* d_in, const int* in_sizes, int n_in,
                              void* d_out, int out_size) {
    const float* x  = (const float*)d_in[0];
    const float* Wq = (const float*)d_in[1];
    const float* bq = (const float*)d_in[2];
    const float* Wk = (const float*)d_in[3];
    const float* bk = (const float*)d_in[4];
    const float* Wv = (const float*)d_in[5];
    const float* bv = (const float*)d_in[6];
    float* out = (float*)d_out;

    cudaFuncSetAttribute(qkv_gemm_tc, cudaFuncAttributeMaxDynamicSharedMemorySize, QSMEM);
    cudaFuncSetAttribute(kv_tc, cudaFuncAttributeMaxDynamicSharedMemorySize, KV_SMEM);
    cudaFuncSetAttribute(out_tc, cudaFuncAttributeMaxDynamicSharedMemorySize, OUT_SMEM);

    zero_acc_kernel<<<512, 256>>>();
    prep_x<<<(int)(((size_t)MM * Cc) / 1024), 256>>>(x);
    prep_w<<<dim3(3, Cc), 128>>>(Wq, Wk, Wv);
    qkv_gemm_tc<<<dim3(12, MM / 128), 128, QSMEM>>>(bq, bk, bv);
    kv_tc<<<dim3(BHn, 16), 128, KV_SMEM>>>();
    kv_finalize<<<BHn, 64>>>();
    out_tc<<<dim3(BHn, Ll / 128), 128, OUT_SMEM>>>(out);
}

// round 8
// speedup vs baseline: 4.4680x; 1.2596x over previous
#include <cuda_runtime.h>
#include <cuda_bf16.h>
#include <cuda_fp16.h>
#include <cstdint>
#include <math.h>

#define Bb 4
#define Ll 16384
#define Cc 512
#define Hh 8
#define Dd 64
#define MM (Bb*Ll)      // 65536
#define BHn (Bb*Hh)     // 32

// Stage-1 tiling: 128x128 tile, BK=32, A hi/lo interleaved rows, 3 stages, 2 CTA/SM
#define QSTAGE 32768
#define QSMEM (3*QSTAGE)
#define QNIT 16          // 512/32

// kv_tc smem: stage = Kh 8K | Kl 8K | Vh 8K | Vl 8K = 32K, 3 stages
#define KV_STAGE 32768
#define KV_SMEM (3*KV_STAGE)
// out_tc smem: Qh 16K | Ql 16K | Bh 10K | Bl 10K
#define OUT_SMEM (16384*2 + 10240*2)

// Scratch
__device__ __half g_Xh[(size_t)MM*Cc];            // X hi (fp16)
__device__ __half g_Xl[(size_t)MM*Cc];            // X lo (fp16)
__device__ __half g_Wth[3*(size_t)Cc*Cc];         // W^T hi (fp16), [z][n][k]
__device__ __nv_bfloat16 g_Qh[(size_t)MM*Cc];
__device__ __nv_bfloat16 g_Ql[(size_t)MM*Cc];
__device__ __nv_bfloat16 g_Kh[(size_t)MM*Cc];
__device__ __nv_bfloat16 g_Kl[(size_t)MM*Cc];
__device__ __nv_bfloat16 g_Vh[(size_t)MM*Cc];
__device__ __nv_bfloat16 g_Vl[(size_t)MM*Cc];
__device__ float g_KV[BHn*Dd*Dd];
__device__ float g_Ksum[BHn*Dd];
__device__ __nv_bfloat16 g_KVth[(size_t)BHn*80*64];  // [bh][v-row(80)][d], row64=Ksum
__device__ __nv_bfloat16 g_KVtl[(size_t)BHn*80*64];

// ---------------------------------------------------------------------------
__device__ __forceinline__ uint32_t smem_u32(const void* p) {
    uint32_t a;
    asm("{ .reg .u64 t; cvta.to.shared.u64 t, %1; cvt.u32.u64 %0, t; }" : "=r"(a) : "l"(p));
    return a;
}
#define SWZ128(o) ((o) ^ (((o) >> 3) & 0x70))

__device__ __forceinline__ void cpa16(uint32_t d, const void* s) {
    uint64_t gp;
    asm("cvta.to.global.u64 %0, %1;" : "=l"(gp) : "l"(s));
    asm volatile("cp.async.cg.shared.global [%0], [%1], 16;" :: "r"(d), "l"(gp) : "memory");
}
__device__ __forceinline__ void cp_commit() {
    asm volatile("cp.async.commit_group;" ::: "memory");
}
template<int N> __device__ __forceinline__ void cp_wait() {
    asm volatile("cp.async.wait_group %0;" :: "n"(N) : "memory");
}
__device__ __forceinline__ void ldm4(uint32_t* r, uint32_t a) {
    asm volatile("ldmatrix.sync.aligned.m8n8.x4.shared.b16 {%0,%1,%2,%3}, [%4];"
        : "=r"(r[0]), "=r"(r[1]), "=r"(r[2]), "=r"(r[3]) : "r"(a));
}
__device__ __forceinline__ void ldm4t(uint32_t* r, uint32_t a) {
    asm volatile("ldmatrix.sync.aligned.m8n8.x4.trans.shared.b16 {%0,%1,%2,%3}, [%4];"
        : "=r"(r[0]), "=r"(r[1]), "=r"(r[2]), "=r"(r[3]) : "r"(a));
}
__device__ __forceinline__ void mma16816(float* c, const uint32_t* a, const uint32_t* b) {
    asm volatile("mma.sync.aligned.m16n8k16.row.col.f32.bf16.bf16.f32 "
        "{%0,%1,%2,%3}, {%4,%5,%6,%7}, {%8,%9}, {%0,%1,%2,%3};"
        : "+f"(c[0]), "+f"(c[1]), "+f"(c[2]), "+f"(c[3])
        : "r"(a[0]), "r"(a[1]), "r"(a[2]), "r"(a[3]), "r"(b[0]), "r"(b[1]));
}
__device__ __forceinline__ void mma16816h(float* c, const uint32_t* a, const uint32_t* b) {
    asm volatile("mma.sync.aligned.m16n8k16.row.col.f32.f16.f16.f32 "
        "{%0,%1,%2,%3}, {%4,%5,%6,%7}, {%8,%9}, {%0,%1,%2,%3};"
        : "+f"(c[0]), "+f"(c[1]), "+f"(c[2]), "+f"(c[3])
        : "r"(a[0]), "r"(a[1]), "r"(a[2]), "r"(a[3]), "r"(b[0]), "r"(b[1]));
}
__device__ __forceinline__ uint32_t pack_bf16(__nv_bfloat16 a, __nv_bfloat16 b) {
    __nv_bfloat162 t(a, b);
    return *reinterpret_cast<uint32_t*>(&t);
}
__device__ __forceinline__ uint32_t pack_h16(__half a, __half b) {
    __half2 t(a, b);
    return *reinterpret_cast<uint32_t*>(&t);
}
__device__ __forceinline__ void split2(float v, __nv_bfloat16& h, __nv_bfloat16& l) {
    h = __float2bfloat16(v);
    l = __float2bfloat16(v - __bfloat162float(h));
}
__device__ __forceinline__ void split2h(float v, __half& h, __half& l) {
    h = __float2half(v);
    l = __float2half(v - __half2float(h));
}

// ---------------------------------------------------------------------------
__global__ void zero_acc_kernel() {
    int i = blockIdx.x * blockDim.x + threadIdx.x;
    if (i < BHn * Dd * Dd) g_KV[i] = 0.f;
    if (i < BHn * Dd)      g_Ksum[i] = 0.f;
}

__global__ void prep_x(const float* __restrict__ X) {
    size_t i = ((size_t)blockIdx.x * 256 + threadIdx.x) * 4;
    float4 v = *reinterpret_cast<const float4*>(X + i);
    const float* vp = &v.x;
    __half h[4], l[4];
#pragma unroll
    for (int q = 0; q < 4; q++) split2h(vp[q], h[q], l[q]);
    *reinterpret_cast<uint2*>(g_Xh + i) = make_uint2(pack_h16(h[0], h[1]), pack_h16(h[2], h[3]));
    *reinterpret_cast<uint2*>(g_Xl + i) = make_uint2(pack_h16(l[0], l[1]), pack_h16(l[2], l[3]));
}

__global__ void prep_w(const float* __restrict__ Wq, const float* __restrict__ Wk,
                       const float* __restrict__ Wv) {
    const int z = blockIdx.x, n = blockIdx.y;
    const float* W = (z == 0) ? Wq : ((z == 1) ? Wk : Wv);
    __half* dh = g_Wth + ((size_t)z * Cc + n) * Cc;
    int k0 = threadIdx.x * 4;
#pragma unroll
    for (int j = 0; j < 4; j++)
        dh[k0 + j] = __float2half(W[(size_t)(k0 + j) * Cc + n]);
}

// ---------------------------------------------------------------------------
// Stage 1: QKV fp16 2-pass split GEMM: out = (Xh + Xl) @ Wh.
// 128-thread CTAs, warp tile 64x64, BK=32, A hi/lo in 128B rows, B hi only,
// 3-stage cp.async ring, 2 CTAs/SM.
// ---------------------------------------------------------------------------
__global__ __launch_bounds__(128, 2) void qkv_gemm_tc(
    const float* __restrict__ bq, const float* __restrict__ bk,
    const float* __restrict__ bv)
{
    extern __shared__ char smem[];
    const uint32_t sbase = smem_u32(smem);
    const int tid = threadIdx.x;
    const int z = blockIdx.x >> 2;
    const int col0 = (blockIdx.x & 3) * 128;
    const int row0 = blockIdx.y * 128;
    const int lane = tid & 31, wid = tid >> 5;
    const int wm = (wid & 1) * 64;
    const int wn = (wid >> 1) * 64;

    const __half* __restrict__ Bh_g = g_Wth + (size_t)z * Cc * Cc;
    const float* __restrict__ bias = (z == 0) ? bq : ((z == 1) ? bk : bv);

    // stage layout: A rows [hi(64B) | lo(64B)] at 0; B rows [hi(64B) | unused] at 16384
    auto issue_half = [&](int kidx, int buf, int half) {
        uint32_t sb = sbase + buf * QSTAGE + (uint32_t)half * 16384;
        int k0 = kidx * 32;
        if (half == 0) {
#pragma unroll
            for (int i = 0; i < 8; i++) {
                int idx = tid + i * 128;          // 0..1023
                int r = idx >> 3;
                int c = idx & 7;                  // 0-3 hi, 4-7 lo
                uint32_t off = SWZ128((uint32_t)(r * 128 + c * 16));
                const __half* src = ((c < 4) ? g_Xh : g_Xl)
                                    + (size_t)(row0 + r) * Cc + k0 + (c & 3) * 8;
                cpa16(sb + off, src);
            }
        } else {
#pragma unroll
            for (int i = 0; i < 4; i++) {
                int idx = tid + i * 128;          // 0..511
                int r = idx >> 2;
                int c = idx & 3;                  // hi only
                uint32_t off = SWZ128((uint32_t)(r * 128 + c * 16));
                cpa16(sb + off, Bh_g + (size_t)(col0 + r) * Cc + k0 + c * 8);
            }
        }
    };

    issue_half(0, 0, 0); issue_half(0, 0, 1); cp_commit();
    issue_half(1, 1, 0); issue_half(1, 1, 1); cp_commit();

    float acc[4][8][4];
#pragma unroll
    for (int i = 0; i < 4; i++)
#pragma unroll
        for (int j = 0; j < 8; j++)
#pragma unroll
            for (int q = 0; q < 4; q++) acc[i][j][q] = 0.f;

    // per-warp precomputed addressing (swizzle = XOR of rowxor into bits 4-6)
    const uint32_t a_k = (uint32_t)((lane >> 4) * 16);
    const int a_row_in = lane & 15;
    uint32_t a_rb[4], a_rx[4];
#pragma unroll
    for (int mf = 0; mf < 4; mf++) {
        int ar = wm + mf * 16 + a_row_in;
        a_rb[mf] = (uint32_t)(ar * 128);
        a_rx[mf] = (uint32_t)((ar & 7) * 16);
    }
    const int b_row_in = (lane & 7) + ((lane >> 4) << 3);
    const uint32_t b_k = (uint32_t)(((lane >> 3) & 1) * 16);
    uint32_t b_rb[4], b_rx[4];
#pragma unroll
    for (int g = 0; g < 4; g++) {
        int br = wn + g * 16 + b_row_in;
        b_rb[g] = (uint32_t)(br * 128) + 16384;
        b_rx[g] = (uint32_t)((br & 7) * 16);
    }

    for (int it = 0; it < QNIT; it++) {
        cp_wait<1>();
        __syncthreads();
        uint32_t sb = sbase + (it % 3) * QSTAGE;
        const bool pre = (it + 2 < QNIT);
        const int pk = it + 2;
        const int pb = (it + 2) % 3;

#pragma unroll
        for (int kk = 0; kk < 2; kk++) {
            uint32_t ah[4][4], al[4][4];
            const uint32_t kc = (uint32_t)(kk * 32) + a_k;
#pragma unroll
            for (int mf = 0; mf < 4; mf++) {
                uint32_t hi = sb + a_rb[mf] + (kc ^ a_rx[mf]);
                ldm4(ah[mf], hi);
                ldm4(al[mf], hi ^ 64u);
            }
            const uint32_t kcb = (uint32_t)(kk * 32) + b_k;
#pragma unroll
            for (int nh = 0; nh < 2; nh++) {
                uint32_t bh[2][4];
#pragma unroll
                for (int gi = 0; gi < 2; gi++) {
                    int g = nh * 2 + gi;
                    ldm4(bh[gi], sb + b_rb[g] + (kcb ^ b_rx[g]));
                }
                // pass-major: 16 MMAs per pass, distinct accumulators
#pragma unroll
                for (int mf = 0; mf < 4; mf++)
#pragma unroll
                    for (int jj = 0; jj < 4; jj++)
                        mma16816h(acc[mf][nh * 4 + jj], ah[mf], &bh[jj >> 1][(jj & 1) * 2]);
#pragma unroll
                for (int mf = 0; mf < 4; mf++)
#pragma unroll
                    for (int jj = 0; jj < 4; jj++)
                        mma16816h(acc[mf][nh * 4 + jj], al[mf], &bh[jj >> 1][(jj & 1) * 2]);
                // interleave next-stage loads with kk=0 compute
                if (kk == 0 && pre) issue_half(pk, pb, nh);
                if (kk == 0 && nh == 1) cp_commit();
            }
        }
        if (!pre) cp_commit();  // keep group count uniform when not prefetching
    }

    // Epilogue: bias + feature map (Q,K), store bf16 hi/lo pairs
    __nv_bfloat16* outH = (z == 0) ? g_Qh : ((z == 1) ? g_Kh : g_Vh);
    __nv_bfloat16* outL = (z == 0) ? g_Ql : ((z == 1) ? g_Kl : g_Vl);
    const int gq = lane >> 2, tq = lane & 3;
#pragma unroll
    for (int mf = 0; mf < 4; mf++) {
#pragma unroll
        for (int hh = 0; hh < 2; hh++) {
            int mg = row0 + wm + mf * 16 + gq + hh * 8;
#pragma unroll
            for (int j = 0; j < 8; j++) {
                int cg = col0 + wn + j * 8 + tq * 2;
                float v0 = acc[mf][j][hh * 2 + 0] + __ldg(bias + cg);
                float v1 = acc[mf][j][hh * 2 + 1] + __ldg(bias + cg + 1);
                if (z < 2) {
                    v0 = (v0 > 0.f) ? (v0 + 1.f) : __expf(v0);
                    v1 = (v1 > 0.f) ? (v1 + 1.f) : __expf(v1);
                }
                __nv_bfloat16 h0, l0, h1, l1;
                split2(v0, h0, l0);
                split2(v1, h1, l1);
                size_t o = (size_t)mg * Cc + cg;
                *reinterpret_cast<uint32_t*>(outH + o) = pack_bf16(h0, h1);
                *reinterpret_cast<uint32_t*>(outL + o) = pack_bf16(l0, l1);
            }
        }
    }
}

// ---------------------------------------------------------------------------
// Stage 2: KV[bh] += K^T V via tensor cores, Ksum via ones-column MMA.
// ---------------------------------------------------------------------------
__global__ __launch_bounds__(128) void kv_tc() {
    extern __shared__ char smem[];
    const uint32_t sbase = smem_u32(smem);
    const int bh = blockIdx.x;
    const int b = bh >> 3, h = bh & 7;
    const int s0 = blockIdx.y * 1024;
    const int tid = threadIdx.x;
    const int lane = tid & 31, w = tid >> 5;

    const __nv_bfloat16* __restrict__ kh = g_Kh + ((size_t)(b * Ll + s0)) * Cc + h * 64;
    const __nv_bfloat16* __restrict__ kl = g_Kl + ((size_t)(b * Ll + s0)) * Cc + h * 64;
    const __nv_bfloat16* __restrict__ vh = g_Vh + ((size_t)(b * Ll + s0)) * Cc + h * 64;
    const __nv_bfloat16* __restrict__ vl = g_Vl + ((size_t)(b * Ll + s0)) * Cc + h * 64;

    auto issue = [&](int st, int buf) {
        uint32_t sb = sbase + buf * KV_STAGE;
#pragma unroll
        for (int i = 0; i < 4; i++) {
            int idx = tid + i * 128;
            int row = idx >> 3, c16 = idx & 7;
            uint32_t off = SWZ128((uint32_t)(row * 128 + c16 * 16));
            size_t src = (size_t)(st * 64 + row) * Cc + c16 * 8;
            cpa16(sb + off,         kh + src);
            cpa16(sb + 8192 + off,  kl + src);
            cpa16(sb + 16384 + off, vh + src);
            cpa16(sb + 24576 + off, vl + src);
        }
        cp_commit();
    };

    issue(0, 0);
    issue(1, 1);

    float accK[8][4], accS[4];
#pragma unroll
    for (int t = 0; t < 8; t++)
#pragma unroll
        for (int q = 0; q < 4; q++) accK[t][q] = 0.f;
#pragma unroll
    for (int q = 0; q < 4; q++) accS[q] = 0.f;

    const uint32_t ones = ((lane >> 2) == 0) ? 0x3F803F80u : 0u;
    uint32_t onef[2] = {ones, ones};

    const uint32_t a_col = (uint32_t)((w * 16 + ((lane >> 4) << 3)) * 2);

    for (int st = 0; st < 16; st++) {
        cp_wait<1>();
        __syncthreads();
        if (st + 2 < 16) issue(st + 2, (st + 2) % 3);
        else cp_commit();

        uint32_t sb = sbase + (st % 3) * KV_STAGE;
#pragma unroll
        for (int s16 = 0; s16 < 4; s16++) {
            uint32_t rowb = (uint32_t)((s16 * 16 + (lane & 15)) * 128);
            uint32_t offA = SWZ128(rowb + a_col);
            uint32_t rh[4], rl[4];
            ldm4t(rh, sb + offA);
            ldm4t(rl, sb + 8192 + offA);
            uint32_t Ah[4] = {rh[0], rh[2], rh[1], rh[3]};
            uint32_t Al[4] = {rl[0], rl[2], rl[1], rl[3]};
            uint32_t bhf[4][4], blf[4][4];
#pragma unroll
            for (int g = 0; g < 4; g++) {
                uint32_t offV = SWZ128(rowb + (uint32_t)((g * 16 + ((lane >> 4) << 3)) * 2));
                ldm4t(bhf[g], sb + 16384 + offV);
                ldm4t(blf[g], sb + 24576 + offV);
            }
#pragma unroll
            for (int t = 0; t < 8; t++)
                mma16816(accK[t], Ah, &bhf[t >> 1][(t & 1) * 2]);
#pragma unroll
            for (int t = 0; t < 8; t++)
                mma16816(accK[t], Al, &bhf[t >> 1][(t & 1) * 2]);
#pragma unroll
            for (int t = 0; t < 8; t++)
                mma16816(accK[t], Ah, &blf[t >> 1][(t & 1) * 2]);
            mma16816(accS, Ah, onef);
            mma16816(accS, Al, onef);
        }
    }

    const int d0 = w * 16 + (lane >> 2);
    float* KVp = g_KV + (size_t)bh * 4096;
#pragma unroll
    for (int t = 0; t < 8; t++) {
        int v = t * 8 + (lane & 3) * 2;
        atomicAdd(KVp + d0 * 64 + v,           accK[t][0]);
        atomicAdd(KVp + d0 * 64 + v + 1,       accK[t][1]);
        atomicAdd(KVp + (d0 + 8) * 64 + v,     accK[t][2]);
        atomicAdd(KVp + (d0 + 8) * 64 + v + 1, accK[t][3]);
    }
    if ((lane & 3) == 0) {
        atomicAdd(g_Ksum + bh * 64 + d0,     accS[0]);
        atomicAdd(g_Ksum + bh * 64 + d0 + 8, accS[2]);
    }
}

// ---------------------------------------------------------------------------
// Finalize: KVt[bh][v][d] = KV[bh][d][v] as bf16 hi/lo; row 64 = Ksum; 65-79 = 0.
// ---------------------------------------------------------------------------
__global__ void kv_finalize() {
    const int bh = blockIdx.x;
    const int v = threadIdx.x;   // 0..63
    __nv_bfloat16* oh = g_KVth + (size_t)bh * 80 * 64;
    __nv_bfloat16* ol = g_KVtl + (size_t)bh * 80 * 64;
    const float* kv = g_KV + (size_t)bh * 4096;
#pragma unroll 8
    for (int d = 0; d < 64; d++) {
        __nv_bfloat16 h, l;
        split2(kv[d * 64 + v], h, l);
        oh[v * 64 + d] = h;
        ol[v * 64 + d] = l;
    }
    __nv_bfloat16 h, l;
    split2(g_Ksum[bh * 64 + v], h, l);
    oh[64 * 64 + v] = h;
    ol[64 * 64 + v] = l;
#pragma unroll
    for (int r = 65; r < 80; r++) {
        oh[r * 64 + v] = __float2bfloat16(0.f);
        ol[r * 64 + v] = __float2bfloat16(0.f);
    }
}

// ---------------------------------------------------------------------------
// Stage 3: out = (Q @ KVext) with normalizer from column 64 (Ksum row of KVt).
// ---------------------------------------------------------------------------
__global__ __launch_bounds__(128) void out_tc(float* __restrict__ out) {
    extern __shared__ char smem[];
    const uint32_t sbase = smem_u32(smem);
    const int bh = blockIdx.x;
    const int b = bh >> 3, h = bh & 7;
    const int l0 = blockIdx.y * 128;
    const int tid = threadIdx.x;
    const int lane = tid & 31, w = tid >> 5;

    {
        const __nv_bfloat16* qh = g_Qh + ((size_t)(b * Ll + l0)) * Cc + h * 64;
        const __nv_bfloat16* ql = g_Ql + ((size_t)(b * Ll + l0)) * Cc + h * 64;
#pragma unroll
        for (int i = 0; i < 8; i++) {
            int idx = tid + i * 128;
            int row = idx >> 3, c16 = idx & 7;
            uint32_t off = SWZ128((uint32_t)(row * 128 + c16 * 16));
            size_t src = (size_t)row * Cc + c16 * 8;
            cpa16(sbase + off, qh + src);
            cpa16(sbase + 16384 + off, ql + src);
        }
        const __nv_bfloat16* bhp = g_KVth + (size_t)bh * 80 * 64;
        const __nv_bfloat16* blp = g_KVtl + (size_t)bh * 80 * 64;
#pragma unroll
        for (int i = 0; i < 5; i++) {
            int idx = tid + i * 128;
            int row = idx >> 3, c16 = idx & 7;
            uint32_t off = SWZ128((uint32_t)(row * 128 + c16 * 16));
            size_t src = (size_t)row * 64 + c16 * 8;
            cpa16(sbase + 32768 + off, bhp + src);
            cpa16(sbase + 43008 + off, blp + src);
        }
        cp_commit();
        cp_wait<0>();
        __syncthreads();
    }

    float acc[2][9][4];
#pragma unroll
    for (int im = 0; im < 2; im++)
#pragma unroll
        for (int t = 0; t < 9; t++)
#pragma unroll
            for (int q = 0; q < 4; q++) acc[im][t][q] = 0.f;

    const uint32_t a_k = (uint32_t)((lane >> 4) * 16);
    const int brow = (lane & 7) + ((lane >> 4) << 3);
    const uint32_t b_k = (uint32_t)(((lane >> 3) & 1) * 16);

#pragma unroll
    for (int ks = 0; ks < 4; ks++) {
        uint32_t aH[2][4], aL[2][4];
#pragma unroll
        for (int im = 0; im < 2; im++) {
            int ar = w * 32 + im * 16 + (lane & 15);
            uint32_t ka = ((uint32_t)(ks * 32) + a_k) ^ ((uint32_t)((ar & 7) * 16));
            ldm4(aH[im], sbase + (uint32_t)ar * 128 + ka);
            ldm4(aL[im], sbase + 16384 + (uint32_t)ar * 128 + ka);
        }
        uint32_t bH[5][4], bL[5][4];
#pragma unroll
        for (int g = 0; g < 5; g++) {
            int br = g * 16 + brow;
            uint32_t kb = ((uint32_t)(ks * 32) + b_k) ^ ((uint32_t)((br & 7) * 16));
            ldm4(bH[g], sbase + 32768 + (uint32_t)br * 128 + kb);
            ldm4(bL[g], sbase + 43008 + (uint32_t)br * 128 + kb);
        }
#pragma unroll
        for (int im = 0; im < 2; im++)
#pragma unroll
            for (int t = 0; t < 9; t++)
                mma16816(acc[im][t], aH[im], &bH[t >> 1][(t & 1) * 2]);
#pragma unroll
        for (int im = 0; im < 2; im++)
#pragma unroll
            for (int t = 0; t < 9; t++)
                mma16816(acc[im][t], aL[im], &bH[t >> 1][(t & 1) * 2]);
#pragma unroll
        for (int im = 0; im < 2; im++)
#pragma unroll
            for (int t = 0; t < 9; t++)
                mma16816(acc[im][t], aH[im], &bL[t >> 1][(t & 1) * 2]);
    }

#pragma unroll
    for (int im = 0; im < 2; im++) {
        float den0 = __shfl_sync(0xffffffffu, acc[im][8][0], lane & ~3);
        float den1 = __shfl_sync(0xffffffffu, acc[im][8][2], lane & ~3);
        float z0 = 1.f / (den0 + 1e-6f);
        float z1 = 1.f / (den1 + 1e-6f);
        int r0 = w * 32 + im * 16 + (lane >> 2);
        float* o0 = out + ((size_t)(b * Ll + l0 + r0)) * Cc + h * 64 + (lane & 3) * 2;
        float* o1 = out + ((size_t)(b * Ll + l0 + r0 + 8)) * Cc + h * 64 + (lane & 3) * 2;
#pragma unroll
        for (int t = 0; t < 8; t++) {
            *reinterpret_cast<float2*>(o0 + t * 8) =
                make_float2(acc[im][t][0] * z0, acc[im][t][1] * z0);
            *reinterpret_cast<float2*>(o1 + t * 8) =
                make_float2(acc[im][t][2] * z1, acc[im][t][3] * z1);
        }
    }
}

// ---------------------------------------------------------------------------
extern "C" void kernel_launch(void* const* d_in, const int* in_sizes, int n_in,
                              void* d_out, int out_size) {
    const float* x  = (const float*)d_in[0];
    const float* Wq = (const float*)d_in[1];
    const float* bq = (const float*)d_in[2];
    const float* Wk = (const float*)d_in[3];
    const float* bk = (const float*)d_in[4];
    const float* Wv = (const float*)d_in[5];
    const float* bv = (const float*)d_in[6];
    float* out = (float*)d_out;

    cudaFuncSetAttribute(qkv_gemm_tc, cudaFuncAttributeMaxDynamicSharedMemorySize, QSMEM);
    cudaFuncSetAttribute(kv_tc, cudaFuncAttributeMaxDynamicSharedMemorySize, KV_SMEM);
    cudaFuncSetAttribute(out_tc, cudaFuncAttributeMaxDynamicSharedMemorySize, OUT_SMEM);

    zero_acc_kernel<<<512, 256>>>();
    prep_x<<<(int)(((size_t)MM * Cc) / 1024), 256>>>(x);
    prep_w<<<dim3(3, Cc), 128>>>(Wq, Wk, Wv);
    qkv_gemm_tc<<<dim3(12, MM / 128), 128, QSMEM>>>(bq, bk, bv);
    kv_tc<<<dim3(BHn, 16), 128, KV_SMEM>>>();
    kv_finalize<<<BHn, 64>>>();
    out_tc<<<dim3(BHn, Ll / 128), 128, OUT_SMEM>>>(out);
}

// round 9
// speedup vs baseline: 6.3642x; 1.4244x over previous
#include <cuda_runtime.h>
#include <cuda_bf16.h>
#include <cuda_fp16.h>
#include <cstdint>
#include <math.h>

#define Bb 4
#define Ll 16384
#define Cc 512
#define Hh 8
#define Dd 64
#define MM (Bb*Ll)      // 65536
#define BHn (Bb*Hh)     // 32

// Stage-1: 128x128 tile, BK=64 (128B fp16 rows), 3 stages, 2 CTA/SM
#define QSTAGE 32768     // A 16K | B 16K
#define QSMEM (3*QSTAGE)
#define QNIT 8           // 512/64

// kv_tc smem: stage = Kh 8K | Kl 8K | Vh 8K | Vl 8K = 32K, 3 stages
#define KV_STAGE 32768
#define KV_SMEM (3*KV_STAGE)
// out_tc smem: Qh 16K | Ql 16K | Bh 10K | Bl 10K
#define OUT_SMEM (16384*2 + 10240*2)

// Scratch
__device__ __half g_Xh[(size_t)MM*Cc];            // X (fp16)
__device__ __half g_Wth[3*(size_t)Cc*Cc];         // W^T (fp16), [z][n][k]
__device__ __nv_bfloat16 g_Qh[(size_t)MM*Cc];
__device__ __nv_bfloat16 g_Ql[(size_t)MM*Cc];
__device__ __nv_bfloat16 g_Kh[(size_t)MM*Cc];
__device__ __nv_bfloat16 g_Kl[(size_t)MM*Cc];
__device__ __nv_bfloat16 g_Vh[(size_t)MM*Cc];
__device__ __nv_bfloat16 g_Vl[(size_t)MM*Cc];
__device__ float g_KV[BHn*Dd*Dd];
__device__ float g_Ksum[BHn*Dd];
__device__ __nv_bfloat16 g_KVth[(size_t)BHn*80*64];  // [bh][v-row(80)][d], row64=Ksum
__device__ __nv_bfloat16 g_KVtl[(size_t)BHn*80*64];

// ---------------------------------------------------------------------------
__device__ __forceinline__ uint32_t smem_u32(const void* p) {
    uint32_t a;
    asm("{ .reg .u64 t; cvta.to.shared.u64 t, %1; cvt.u32.u64 %0, t; }" : "=r"(a) : "l"(p));
    return a;
}
#define SWZ128(o) ((o) ^ (((o) >> 3) & 0x70))

__device__ __forceinline__ void cpa16(uint32_t d, const void* s) {
    uint64_t gp;
    asm("cvta.to.global.u64 %0, %1;" : "=l"(gp) : "l"(s));
    asm volatile("cp.async.cg.shared.global [%0], [%1], 16;" :: "r"(d), "l"(gp) : "memory");
}
__device__ __forceinline__ void cp_commit() {
    asm volatile("cp.async.commit_group;" ::: "memory");
}
template<int N> __device__ __forceinline__ void cp_wait() {
    asm volatile("cp.async.wait_group %0;" :: "n"(N) : "memory");
}
__device__ __forceinline__ void ldm4(uint32_t* r, uint32_t a) {
    asm volatile("ldmatrix.sync.aligned.m8n8.x4.shared.b16 {%0,%1,%2,%3}, [%4];"
        : "=r"(r[0]), "=r"(r[1]), "=r"(r[2]), "=r"(r[3]) : "r"(a));
}
__device__ __forceinline__ void ldm4t(uint32_t* r, uint32_t a) {
    asm volatile("ldmatrix.sync.aligned.m8n8.x4.trans.shared.b16 {%0,%1,%2,%3}, [%4];"
        : "=r"(r[0]), "=r"(r[1]), "=r"(r[2]), "=r"(r[3]) : "r"(a));
}
__device__ __forceinline__ void mma16816(float* c, const uint32_t* a, const uint32_t* b) {
    asm volatile("mma.sync.aligned.m16n8k16.row.col.f32.bf16.bf16.f32 "
        "{%0,%1,%2,%3}, {%4,%5,%6,%7}, {%8,%9}, {%0,%1,%2,%3};"
        : "+f"(c[0]), "+f"(c[1]), "+f"(c[2]), "+f"(c[3])
        : "r"(a[0]), "r"(a[1]), "r"(a[2]), "r"(a[3]), "r"(b[0]), "r"(b[1]));
}
__device__ __forceinline__ void mma16816h(float* c, const uint32_t* a, const uint32_t* b) {
    asm volatile("mma.sync.aligned.m16n8k16.row.col.f32.f16.f16.f32 "
        "{%0,%1,%2,%3}, {%4,%5,%6,%7}, {%8,%9}, {%0,%1,%2,%3};"
        : "+f"(c[0]), "+f"(c[1]), "+f"(c[2]), "+f"(c[3])
        : "r"(a[0]), "r"(a[1]), "r"(a[2]), "r"(a[3]), "r"(b[0]), "r"(b[1]));
}
__device__ __forceinline__ uint32_t pack_bf16(__nv_bfloat16 a, __nv_bfloat16 b) {
    __nv_bfloat162 t(a, b);
    return *reinterpret_cast<uint32_t*>(&t);
}
__device__ __forceinline__ uint32_t pack_h16(__half a, __half b) {
    __half2 t(a, b);
    return *reinterpret_cast<uint32_t*>(&t);
}
__device__ __forceinline__ void split2(float v, __nv_bfloat16& h, __nv_bfloat16& l) {
    h = __float2bfloat16(v);
    l = __float2bfloat16(v - __bfloat162float(h));
}

// ---------------------------------------------------------------------------
__global__ void zero_acc_kernel() {
    int i = blockIdx.x * blockDim.x + threadIdx.x;
    if (i < BHn * Dd * Dd) g_KV[i] = 0.f;
    if (i < BHn * Dd)      g_Ksum[i] = 0.f;
}

__global__ void prep_x(const float* __restrict__ X) {
    size_t i = ((size_t)blockIdx.x * 256 + threadIdx.x) * 4;
    float4 v = *reinterpret_cast<const float4*>(X + i);
    *reinterpret_cast<uint2*>(g_Xh + i) = make_uint2(
        pack_h16(__float2half(v.x), __float2half(v.y)),
        pack_h16(__float2half(v.z), __float2half(v.w)));
}

__global__ void prep_w(const float* __restrict__ Wq, const float* __restrict__ Wk,
                       const float* __restrict__ Wv) {
    const int z = blockIdx.x, n = blockIdx.y;
    const float* W = (z == 0) ? Wq : ((z == 1) ? Wk : Wv);
    __half* dh = g_Wth + ((size_t)z * Cc + n) * Cc;
    int k0 = threadIdx.x * 4;
#pragma unroll
    for (int j = 0; j < 4; j++)
        dh[k0 + j] = __float2half(W[(size_t)(k0 + j) * Cc + n]);
}

// ---------------------------------------------------------------------------
// Stage 1: QKV plain fp16 GEMM: out = Xh @ Wh (fp32 accum).
// 128-thread CTAs, warp tile 64x64, BK=64 (one SW128 row), 3-stage ring,
// 2 CTAs/SM, 8 k-iterations.
// ---------------------------------------------------------------------------
__global__ __launch_bounds__(128, 2) void qkv_gemm_tc(
    const float* __restrict__ bq, const float* __restrict__ bk,
    const float* __restrict__ bv)
{
    extern __shared__ char smem[];
    const uint32_t sbase = smem_u32(smem);
    const int tid = threadIdx.x;
    const int z = blockIdx.x >> 2;
    const int col0 = (blockIdx.x & 3) * 128;
    const int row0 = blockIdx.y * 128;
    const int lane = tid & 31, wid = tid >> 5;
    const int wm = (wid & 1) * 64;
    const int wn = (wid >> 1) * 64;

    const __half* __restrict__ Bh_g = g_Wth + (size_t)z * Cc * Cc;
    const float* __restrict__ bias = (z == 0) ? bq : ((z == 1) ? bk : bv);

    // stage layout: A tile (128 rows x 128B) at 0, B tile at 16384
    auto issue_half = [&](int kidx, int buf, int half) {
        uint32_t sb = sbase + buf * QSTAGE + (uint32_t)half * 16384;
        int k0 = kidx * 64;
#pragma unroll
        for (int i = 0; i < 8; i++) {
            int idx = tid + i * 128;          // 0..1023
            int r = idx >> 3;
            int c = idx & 7;
            uint32_t off = SWZ128((uint32_t)(r * 128 + c * 16));
            const __half* src = (half == 0)
                ? g_Xh  + (size_t)(row0 + r) * Cc + k0 + c * 8
                : Bh_g  + (size_t)(col0 + r) * Cc + k0 + c * 8;
            cpa16(sb + off, src);
        }
    };

    issue_half(0, 0, 0); issue_half(0, 0, 1); cp_commit();
    issue_half(1, 1, 0); issue_half(1, 1, 1); cp_commit();

    float acc[4][8][4];
#pragma unroll
    for (int i = 0; i < 4; i++)
#pragma unroll
        for (int j = 0; j < 8; j++)
#pragma unroll
            for (int q = 0; q < 4; q++) acc[i][j][q] = 0.f;

    // per-warp precomputed addressing
    const uint32_t a_k = (uint32_t)((lane >> 4) * 16);
    uint32_t a_rb[4], a_rx[4];
#pragma unroll
    for (int mf = 0; mf < 4; mf++) {
        int ar = wm + mf * 16 + (lane & 15);
        a_rb[mf] = (uint32_t)(ar * 128);
        a_rx[mf] = (uint32_t)((ar & 7) * 16);
    }
    const int b_row_in = (lane & 7) + ((lane >> 4) << 3);
    const uint32_t b_k = (uint32_t)(((lane >> 3) & 1) * 16);
    uint32_t b_rb[4], b_rx[4];
#pragma unroll
    for (int g = 0; g < 4; g++) {
        int br = wn + g * 16 + b_row_in;
        b_rb[g] = (uint32_t)(br * 128) + 16384;
        b_rx[g] = (uint32_t)((br & 7) * 16);
    }

    for (int it = 0; it < QNIT; it++) {
        cp_wait<1>();
        __syncthreads();
        uint32_t sb = sbase + (it % 3) * QSTAGE;
        const bool pre = (it + 2 < QNIT);
        const int pk = it + 2;
        const int pb = (it + 2) % 3;

#pragma unroll
        for (int ks = 0; ks < 4; ks++) {
            const uint32_t kc = (uint32_t)(ks * 32);
            uint32_t ah[4][4];
#pragma unroll
            for (int mf = 0; mf < 4; mf++)
                ldm4(ah[mf], sb + a_rb[mf] + ((kc + a_k) ^ a_rx[mf]));
            uint32_t bh[4][4];
#pragma unroll
            for (int g = 0; g < 4; g++)
                ldm4(bh[g], sb + b_rb[g] + ((kc + b_k) ^ b_rx[g]));
#pragma unroll
            for (int mf = 0; mf < 4; mf++)
#pragma unroll
                for (int jj = 0; jj < 8; jj++)
                    mma16816h(acc[mf][jj], ah[mf], &bh[jj >> 1][(jj & 1) * 2]);
            // interleave next-stage cp.async with compute
            if (pre && ks < 2) issue_half(pk, pb, ks);
            if (ks == 1) cp_commit();
        }
    }

    // Epilogue: bias + feature map (Q,K), store bf16 hi/lo pairs
    __nv_bfloat16* outH = (z == 0) ? g_Qh : ((z == 1) ? g_Kh : g_Vh);
    __nv_bfloat16* outL = (z == 0) ? g_Ql : ((z == 1) ? g_Kl : g_Vl);
    const int gq = lane >> 2, tq = lane & 3;
#pragma unroll
    for (int mf = 0; mf < 4; mf++) {
#pragma unroll
        for (int hh = 0; hh < 2; hh++) {
            int mg = row0 + wm + mf * 16 + gq + hh * 8;
#pragma unroll
            for (int j = 0; j < 8; j++) {
                int cg = col0 + wn + j * 8 + tq * 2;
                float v0 = acc[mf][j][hh * 2 + 0] + __ldg(bias + cg);
                float v1 = acc[mf][j][hh * 2 + 1] + __ldg(bias + cg + 1);
                if (z < 2) {
                    v0 = (v0 > 0.f) ? (v0 + 1.f) : __expf(v0);
                    v1 = (v1 > 0.f) ? (v1 + 1.f) : __expf(v1);
                }
                __nv_bfloat16 h0, l0, h1, l1;
                split2(v0, h0, l0);
                split2(v1, h1, l1);
                size_t o = (size_t)mg * Cc + cg;
                *reinterpret_cast<uint32_t*>(outH + o) = pack_bf16(h0, h1);
                *reinterpret_cast<uint32_t*>(outL + o) = pack_bf16(l0, l1);
            }
        }
    }
}

// ---------------------------------------------------------------------------
// Stage 2: KV[bh] += K^T V via tensor cores, Ksum via ones-column MMA.
// ---------------------------------------------------------------------------
__global__ __launch_bounds__(128) void kv_tc() {
    extern __shared__ char smem[];
    const uint32_t sbase = smem_u32(smem);
    const int bh = blockIdx.x;
    const int b = bh >> 3, h = bh & 7;
    const int s0 = blockIdx.y * 1024;
    const int tid = threadIdx.x;
    const int lane = tid & 31, w = tid >> 5;

    const __nv_bfloat16* __restrict__ kh = g_Kh + ((size_t)(b * Ll + s0)) * Cc + h * 64;
    const __nv_bfloat16* __restrict__ kl = g_Kl + ((size_t)(b * Ll + s0)) * Cc + h * 64;
    const __nv_bfloat16* __restrict__ vh = g_Vh + ((size_t)(b * Ll + s0)) * Cc + h * 64;
    const __nv_bfloat16* __restrict__ vl = g_Vl + ((size_t)(b * Ll + s0)) * Cc + h * 64;

    auto issue = [&](int st, int buf) {
        uint32_t sb = sbase + buf * KV_STAGE;
#pragma unroll
        for (int i = 0; i < 4; i++) {
            int idx = tid + i * 128;
            int row = idx >> 3, c16 = idx & 7;
            uint32_t off = SWZ128((uint32_t)(row * 128 + c16 * 16));
            size_t src = (size_t)(st * 64 + row) * Cc + c16 * 8;
            cpa16(sb + off,         kh + src);
            cpa16(sb + 8192 + off,  kl + src);
            cpa16(sb + 16384 + off, vh + src);
            cpa16(sb + 24576 + off, vl + src);
        }
        cp_commit();
    };

    issue(0, 0);
    issue(1, 1);

    float accK[8][4], accS[4];
#pragma unroll
    for (int t = 0; t < 8; t++)
#pragma unroll
        for (int q = 0; q < 4; q++) accK[t][q] = 0.f;
#pragma unroll
    for (int q = 0; q < 4; q++) accS[q] = 0.f;

    const uint32_t ones = ((lane >> 2) == 0) ? 0x3F803F80u : 0u;
    uint32_t onef[2] = {ones, ones};

    const uint32_t a_col = (uint32_t)((w * 16 + ((lane >> 4) << 3)) * 2);

    for (int st = 0; st < 16; st++) {
        cp_wait<1>();
        __syncthreads();
        if (st + 2 < 16) issue(st + 2, (st + 2) % 3);
        else cp_commit();

        uint32_t sb = sbase + (st % 3) * KV_STAGE;
#pragma unroll
        for (int s16 = 0; s16 < 4; s16++) {
            uint32_t rowb = (uint32_t)((s16 * 16 + (lane & 15)) * 128);
            uint32_t offA = SWZ128(rowb + a_col);
            uint32_t rh[4], rl[4];
            ldm4t(rh, sb + offA);
            ldm4t(rl, sb + 8192 + offA);
            uint32_t Ah[4] = {rh[0], rh[2], rh[1], rh[3]};
            uint32_t Al[4] = {rl[0], rl[2], rl[1], rl[3]};
            uint32_t bhf[4][4], blf[4][4];
#pragma unroll
            for (int g = 0; g < 4; g++) {
                uint32_t offV = SWZ128(rowb + (uint32_t)((g * 16 + ((lane >> 4) << 3)) * 2));
                ldm4t(bhf[g], sb + 16384 + offV);
                ldm4t(blf[g], sb + 24576 + offV);
            }
#pragma unroll
            for (int t = 0; t < 8; t++)
                mma16816(accK[t], Ah, &bhf[t >> 1][(t & 1) * 2]);
#pragma unroll
            for (int t = 0; t < 8; t++)
                mma16816(accK[t], Al, &bhf[t >> 1][(t & 1) * 2]);
#pragma unroll
            for (int t = 0; t < 8; t++)
                mma16816(accK[t], Ah, &blf[t >> 1][(t & 1) * 2]);
            mma16816(accS, Ah, onef);
            mma16816(accS, Al, onef);
        }
    }

    const int d0 = w * 16 + (lane >> 2);
    float* KVp = g_KV + (size_t)bh * 4096;
#pragma unroll
    for (int t = 0; t < 8; t++) {
        int v = t * 8 + (lane & 3) * 2;
        atomicAdd(KVp + d0 * 64 + v,           accK[t][0]);
        atomicAdd(KVp + d0 * 64 + v + 1,       accK[t][1]);
        atomicAdd(KVp + (d0 + 8) * 64 + v,     accK[t][2]);
        atomicAdd(KVp + (d0 + 8) * 64 + v + 1, accK[t][3]);
    }
    if ((lane & 3) == 0) {
        atomicAdd(g_Ksum + bh * 64 + d0,     accS[0]);
        atomicAdd(g_Ksum + bh * 64 + d0 + 8, accS[2]);
    }
}

// ---------------------------------------------------------------------------
// Finalize: KVt[bh][v][d] = KV[bh][d][v] as bf16 hi/lo; row 64 = Ksum; 65-79 = 0.
// ---------------------------------------------------------------------------
__global__ void kv_finalize() {
    const int bh = blockIdx.x;
    const int v = threadIdx.x;   // 0..63
    __nv_bfloat16* oh = g_KVth + (size_t)bh * 80 * 64;
    __nv_bfloat16* ol = g_KVtl + (size_t)bh * 80 * 64;
    const float* kv = g_KV + (size_t)bh * 4096;
#pragma unroll 8
    for (int d = 0; d < 64; d++) {
        __nv_bfloat16 h, l;
        split2(kv[d * 64 + v], h, l);
        oh[v * 64 + d] = h;
        ol[v * 64 + d] = l;
    }
    __nv_bfloat16 h, l;
    split2(g_Ksum[bh * 64 + v], h, l);
    oh[64 * 64 + v] = h;
    ol[64 * 64 + v] = l;
#pragma unroll
    for (int r = 65; r < 80; r++) {
        oh[r * 64 + v] = __float2bfloat16(0.f);
        ol[r * 64 + v] = __float2bfloat16(0.f);
    }
}

// ---------------------------------------------------------------------------
// Stage 3: out = (Q @ KVext) with normalizer from column 64 (Ksum row of KVt).
// ---------------------------------------------------------------------------
__global__ __launch_bounds__(128) void out_tc(float* __restrict__ out) {
    extern __shared__ char smem[];
    const uint32_t sbase = smem_u32(smem);
    const int bh = blockIdx.x;
    const int b = bh >> 3, h = bh & 7;
    const int l0 = blockIdx.y * 128;
    const int tid = threadIdx.x;
    const int lane = tid & 31, w = tid >> 5;

    {
        const __nv_bfloat16* qh = g_Qh + ((size_t)(b * Ll + l0)) * Cc + h * 64;
        const __nv_bfloat16* ql = g_Ql + ((size_t)(b * Ll + l0)) * Cc + h * 64;
#pragma unroll
        for (int i = 0; i < 8; i++) {
            int idx = tid + i * 128;
            int row = idx >> 3, c16 = idx & 7;
            uint32_t off = SWZ128((uint32_t)(row * 128 + c16 * 16));
            size_t src = (size_t)row * Cc + c16 * 8;
            cpa16(sbase + off, qh + src);
            cpa16(sbase + 16384 + off, ql + src);
        }
        const __nv_bfloat16* bhp = g_KVth + (size_t)bh * 80 * 64;
        const __nv_bfloat16* blp = g_KVtl + (size_t)bh * 80 * 64;
#pragma unroll
        for (int i = 0; i < 5; i++) {
            int idx = tid + i * 128;
            int row = idx >> 3, c16 = idx & 7;
            uint32_t off = SWZ128((uint32_t)(row * 128 + c16 * 16));
            size_t src = (size_t)row * 64 + c16 * 8;
            cpa16(sbase + 32768 + off, bhp + src);
            cpa16(sbase + 43008 + off, blp + src);
        }
        cp_commit();
        cp_wait<0>();
        __syncthreads();
    }

    float acc[2][9][4];
#pragma unroll
    for (int im = 0; im < 2; im++)
#pragma unroll
        for (int t = 0; t < 9; t++)
#pragma unroll
            for (int q = 0; q < 4; q++) acc[im][t][q] = 0.f;

    const uint32_t a_k = (uint32_t)((lane >> 4) * 16);
    const int brow = (lane & 7) + ((lane >> 4) << 3);
    const uint32_t b_k = (uint32_t)(((lane >> 3) & 1) * 16);

#pragma unroll
    for (int ks = 0; ks < 4; ks++) {
        uint32_t aH[2][4], aL[2][4];
#pragma unroll
        for (int im = 0; im < 2; im++) {
            int ar = w * 32 + im * 16 + (lane & 15);
            uint32_t ka = ((uint32_t)(ks * 32) + a_k) ^ ((uint32_t)((ar & 7) * 16));
            ldm4(aH[im], sbase + (uint32_t)ar * 128 + ka);
            ldm4(aL[im], sbase + 16384 + (uint32_t)ar * 128 + ka);
        }
        uint32_t bH[5][4], bL[5][4];
#pragma unroll
        for (int g = 0; g < 5; g++) {
            int br = g * 16 + brow;
            uint32_t kb = ((uint32_t)(ks * 32) + b_k) ^ ((uint32_t)((br & 7) * 16));
            ldm4(bH[g], sbase + 32768 + (uint32_t)br * 128 + kb);
            ldm4(bL[g], sbase + 43008 + (uint32_t)br * 128 + kb);
        }
#pragma unroll
        for (int im = 0; im < 2; im++)
#pragma unroll
            for (int t = 0; t < 9; t++)
                mma16816(acc[im][t], aH[im], &bH[t >> 1][(t & 1) * 2]);
#pragma unroll
        for (int im = 0; im < 2; im++)
#pragma unroll
            for (int t = 0; t < 9; t++)
                mma16816(acc[im][t], aL[im], &bH[t >> 1][(t & 1) * 2]);
#pragma unroll
        for (int im = 0; im < 2; im++)
#pragma unroll
            for (int t = 0; t < 9; t++)
                mma16816(acc[im][t], aH[im], &bL[t >> 1][(t & 1) * 2]);
    }

#pragma unroll
    for (int im = 0; im < 2; im++) {
        float den0 = __shfl_sync(0xffffffffu, acc[im][8][0], lane & ~3);
        float den1 = __shfl_sync(0xffffffffu, acc[im][8][2], lane & ~3);
        float z0 = 1.f / (den0 + 1e-6f);
        float z1 = 1.f / (den1 + 1e-6f);
        int r0 = w * 32 + im * 16 + (lane >> 2);
        float* o0 = out + ((size_t)(b * Ll + l0 + r0)) * Cc + h * 64 + (lane & 3) * 2;
        float* o1 = out + ((size_t)(b * Ll + l0 + r0 + 8)) * Cc + h * 64 + (lane & 3) * 2;
#pragma unroll
        for (int t = 0; t < 8; t++) {
            *reinterpret_cast<float2*>(o0 + t * 8) =
                make_float2(acc[im][t][0] * z0, acc[im][t][1] * z0);
            *reinterpret_cast<float2*>(o1 + t * 8) =
                make_float2(acc[im][t][2] * z1, acc[im][t][3] * z1);
        }
    }
}

// ---------------------------------------------------------------------------
extern "C" void kernel_launch(void* const* d_in, const int* in_sizes, int n_in,
                              void* d_out, int out_size) {
    const float* x  = (const float*)d_in[0];
    const float* Wq = (const float*)d_in[1];
    const float* bq = (const float*)d_in[2];
    const float* Wk = (const float*)d_in[3];
    const float* bk = (const float*)d_in[4];
    const float* Wv = (const float*)d_in[5];
    const float* bv = (const float*)d_in[6];
    float* out = (float*)d_out;

    cudaFuncSetAttribute(qkv_gemm_tc, cudaFuncAttributeMaxDynamicSharedMemorySize, QSMEM);
    cudaFuncSetAttribute(kv_tc, cudaFuncAttributeMaxDynamicSharedMemorySize, KV_SMEM);
    cudaFuncSetAttribute(out_tc, cudaFuncAttributeMaxDynamicSharedMemorySize, OUT_SMEM);

    zero_acc_kernel<<<512, 256>>>();
    prep_x<<<(int)(((size_t)MM * Cc) / 1024), 256>>>(x);
    prep_w<<<dim3(3, Cc), 128>>>(Wq, Wk, Wv);
    qkv_gemm_tc<<<dim3(12, MM / 128), 128, QSMEM>>>(bq, bk, bv);
    kv_tc<<<dim3(BHn, 16), 128, KV_SMEM>>>();
    kv_finalize<<<BHn, 64>>>();
    out_tc<<<dim3(BHn, Ll / 128), 128, OUT_SMEM>>>(out);
}

// round 10
// speedup vs baseline: 6.8812x; 1.0812x over previous
#include <cuda_runtime.h>
#include <cuda_bf16.h>
#include <cuda_fp16.h>
#include <cstdint>
#include <math.h>

#define Bb 4
#define Ll 16384
#define Cc 512
#define Hh 8
#define Dd 64
#define MM (Bb*Ll)      // 65536
#define BHn (Bb*Hh)     // 32

// Stage-1: 128x128 tile, BK=64 (128B fp16 rows), 3 stages, 2 CTA/SM
#define QSTAGE 32768     // A 16K | B 16K
#define QSMEM (3*QSTAGE)
#define QNIT 8           // 512/64

// kv_tc smem: stage = K 8K | Vh 8K | Vl 8K = 24K, 3 stages
#define KV_STAGE 24576
#define KV_SMEM (3*KV_STAGE)
// out_tc smem: Q 16K | Bh 10K | Bl 10K
#define OUT_SMEM (16384 + 2*10240)

// Scratch (all fp16)
__device__ __half g_Xh[(size_t)MM*Cc];            // X
__device__ __half g_Wth[3*(size_t)Cc*Cc];         // W^T, [z][n][k]
__device__ __half g_Q [(size_t)MM*Cc];            // feature-mapped Q (single)
__device__ __half g_K [(size_t)MM*Cc];            // feature-mapped K (single)
__device__ __half g_Vh[(size_t)MM*Cc];            // V hi
__device__ __half g_Vl[(size_t)MM*Cc];            // V lo
__device__ float g_KV[BHn*Dd*Dd];
__device__ float g_Ksum[BHn*Dd];
__device__ __half g_KVth[(size_t)BHn*80*64];      // [bh][v-row(80)][d], row64=Ksum
__device__ __half g_KVtl[(size_t)BHn*80*64];

// ---------------------------------------------------------------------------
__device__ __forceinline__ uint32_t smem_u32(const void* p) {
    uint32_t a;
    asm("{ .reg .u64 t; cvta.to.shared.u64 t, %1; cvt.u32.u64 %0, t; }" : "=r"(a) : "l"(p));
    return a;
}
#define SWZ128(o) ((o) ^ (((o) >> 3) & 0x70))

__device__ __forceinline__ void cpa16(uint32_t d, const void* s) {
    uint64_t gp;
    asm("cvta.to.global.u64 %0, %1;" : "=l"(gp) : "l"(s));
    asm volatile("cp.async.cg.shared.global [%0], [%1], 16;" :: "r"(d), "l"(gp) : "memory");
}
__device__ __forceinline__ void cp_commit() {
    asm volatile("cp.async.commit_group;" ::: "memory");
}
template<int N> __device__ __forceinline__ void cp_wait() {
    asm volatile("cp.async.wait_group %0;" :: "n"(N) : "memory");
}
__device__ __forceinline__ void ldm4(uint32_t* r, uint32_t a) {
    asm volatile("ldmatrix.sync.aligned.m8n8.x4.shared.b16 {%0,%1,%2,%3}, [%4];"
        : "=r"(r[0]), "=r"(r[1]), "=r"(r[2]), "=r"(r[3]) : "r"(a));
}
__device__ __forceinline__ void ldm4t(uint32_t* r, uint32_t a) {
    asm volatile("ldmatrix.sync.aligned.m8n8.x4.trans.shared.b16 {%0,%1,%2,%3}, [%4];"
        : "=r"(r[0]), "=r"(r[1]), "=r"(r[2]), "=r"(r[3]) : "r"(a));
}
__device__ __forceinline__ void mma16816h(float* c, const uint32_t* a, const uint32_t* b) {
    asm volatile("mma.sync.aligned.m16n8k16.row.col.f32.f16.f16.f32 "
        "{%0,%1,%2,%3}, {%4,%5,%6,%7}, {%8,%9}, {%0,%1,%2,%3};"
        : "+f"(c[0]), "+f"(c[1]), "+f"(c[2]), "+f"(c[3])
        : "r"(a[0]), "r"(a[1]), "r"(a[2]), "r"(a[3]), "r"(b[0]), "r"(b[1]));
}
__device__ __forceinline__ uint32_t pack_h16(__half a, __half b) {
    __half2 t(a, b);
    return *reinterpret_cast<uint32_t*>(&t);
}
__device__ __forceinline__ void split2h(float v, __half& h, __half& l) {
    h = __float2half(v);
    l = __float2half(v - __half2float(h));
}

// ---------------------------------------------------------------------------
__global__ void zero_acc_kernel() {
    int i = blockIdx.x * blockDim.x + threadIdx.x;
    if (i < BHn * Dd * Dd) g_KV[i] = 0.f;
    if (i < BHn * Dd)      g_Ksum[i] = 0.f;
}

__global__ void prep_x(const float* __restrict__ X) {
    size_t i = ((size_t)blockIdx.x * 256 + threadIdx.x) * 4;
    float4 v = *reinterpret_cast<const float4*>(X + i);
    *reinterpret_cast<uint2*>(g_Xh + i) = make_uint2(
        pack_h16(__float2half(v.x), __float2half(v.y)),
        pack_h16(__float2half(v.z), __float2half(v.w)));
}

__global__ void prep_w(const float* __restrict__ Wq, const float* __restrict__ Wk,
                       const float* __restrict__ Wv) {
    const int z = blockIdx.x, n = blockIdx.y;
    const float* W = (z == 0) ? Wq : ((z == 1) ? Wk : Wv);
    __half* dh = g_Wth + ((size_t)z * Cc + n) * Cc;
    int k0 = threadIdx.x * 4;
#pragma unroll
    for (int j = 0; j < 4; j++)
        dh[k0 + j] = __float2half(W[(size_t)(k0 + j) * Cc + n]);
}

// ---------------------------------------------------------------------------
// Stage 1: QKV fp16 GEMM: out = Xh @ Wh (fp32 accum).
// 128-thread CTAs, warp tile 64x64, BK=64, 3-stage ring, 2 CTAs/SM.
// ---------------------------------------------------------------------------
__global__ __launch_bounds__(128, 2) void qkv_gemm_tc(
    const float* __restrict__ bq, const float* __restrict__ bk,
    const float* __restrict__ bv)
{
    extern __shared__ char smem[];
    const uint32_t sbase = smem_u32(smem);
    const int tid = threadIdx.x;
    const int z = blockIdx.x >> 2;
    const int col0 = (blockIdx.x & 3) * 128;
    const int row0 = blockIdx.y * 128;
    const int lane = tid & 31, wid = tid >> 5;
    const int wm = (wid & 1) * 64;
    const int wn = (wid >> 1) * 64;

    const __half* __restrict__ Bh_g = g_Wth + (size_t)z * Cc * Cc;
    const float* __restrict__ bias = (z == 0) ? bq : ((z == 1) ? bk : bv);

    auto issue_half = [&](int kidx, int buf, int half) {
        uint32_t sb = sbase + buf * QSTAGE + (uint32_t)half * 16384;
        int k0 = kidx * 64;
#pragma unroll
        for (int i = 0; i < 8; i++) {
            int idx = tid + i * 128;
            int r = idx >> 3;
            int c = idx & 7;
            uint32_t off = SWZ128((uint32_t)(r * 128 + c * 16));
            const __half* src = (half == 0)
                ? g_Xh  + (size_t)(row0 + r) * Cc + k0 + c * 8
                : Bh_g  + (size_t)(col0 + r) * Cc + k0 + c * 8;
            cpa16(sb + off, src);
        }
    };

    issue_half(0, 0, 0); issue_half(0, 0, 1); cp_commit();
    issue_half(1, 1, 0); issue_half(1, 1, 1); cp_commit();

    float acc[4][8][4];
#pragma unroll
    for (int i = 0; i < 4; i++)
#pragma unroll
        for (int j = 0; j < 8; j++)
#pragma unroll
            for (int q = 0; q < 4; q++) acc[i][j][q] = 0.f;

    const uint32_t a_k = (uint32_t)((lane >> 4) * 16);
    uint32_t a_rb[4], a_rx[4];
#pragma unroll
    for (int mf = 0; mf < 4; mf++) {
        int ar = wm + mf * 16 + (lane & 15);
        a_rb[mf] = (uint32_t)(ar * 128);
        a_rx[mf] = (uint32_t)((ar & 7) * 16);
    }
    const int b_row_in = (lane & 7) + ((lane >> 4) << 3);
    const uint32_t b_k = (uint32_t)(((lane >> 3) & 1) * 16);
    uint32_t b_rb[4], b_rx[4];
#pragma unroll
    for (int g = 0; g < 4; g++) {
        int br = wn + g * 16 + b_row_in;
        b_rb[g] = (uint32_t)(br * 128) + 16384;
        b_rx[g] = (uint32_t)((br & 7) * 16);
    }

    for (int it = 0; it < QNIT; it++) {
        cp_wait<1>();
        __syncthreads();
        uint32_t sb = sbase + (it % 3) * QSTAGE;
        const bool pre = (it + 2 < QNIT);
        const int pk = it + 2;
        const int pb = (it + 2) % 3;

#pragma unroll
        for (int ks = 0; ks < 4; ks++) {
            const uint32_t kc = (uint32_t)(ks * 32);
            uint32_t ah[4][4];
#pragma unroll
            for (int mf = 0; mf < 4; mf++)
                ldm4(ah[mf], sb + a_rb[mf] + ((kc + a_k) ^ a_rx[mf]));
            uint32_t bh[4][4];
#pragma unroll
            for (int g = 0; g < 4; g++)
                ldm4(bh[g], sb + b_rb[g] + ((kc + b_k) ^ b_rx[g]));
#pragma unroll
            for (int mf = 0; mf < 4; mf++)
#pragma unroll
                for (int jj = 0; jj < 8; jj++)
                    mma16816h(acc[mf][jj], ah[mf], &bh[jj >> 1][(jj & 1) * 2]);
            if (pre && ks < 2) issue_half(pk, pb, ks);
            if (ks == 1) cp_commit();
        }
    }

    // Epilogue: bias + feature map (Q,K single fp16); V stored fp16 hi/lo
    const int gq = lane >> 2, tq = lane & 3;
#pragma unroll
    for (int mf = 0; mf < 4; mf++) {
#pragma unroll
        for (int hh = 0; hh < 2; hh++) {
            int mg = row0 + wm + mf * 16 + gq + hh * 8;
#pragma unroll
            for (int j = 0; j < 8; j++) {
                int cg = col0 + wn + j * 8 + tq * 2;
                float v0 = acc[mf][j][hh * 2 + 0] + __ldg(bias + cg);
                float v1 = acc[mf][j][hh * 2 + 1] + __ldg(bias + cg + 1);
                size_t o = (size_t)mg * Cc + cg;
                if (z < 2) {
                    v0 = (v0 > 0.f) ? (v0 + 1.f) : __expf(v0);
                    v1 = (v1 > 0.f) ? (v1 + 1.f) : __expf(v1);
                    __half* outp = (z == 0) ? g_Q : g_K;
                    *reinterpret_cast<uint32_t*>(outp + o) =
                        pack_h16(__float2half(v0), __float2half(v1));
                } else {
                    __half h0, l0, h1, l1;
                    split2h(v0, h0, l0);
                    split2h(v1, h1, l1);
                    *reinterpret_cast<uint32_t*>(g_Vh + o) = pack_h16(h0, h1);
                    *reinterpret_cast<uint32_t*>(g_Vl + o) = pack_h16(l0, l1);
                }
            }
        }
    }
}

// ---------------------------------------------------------------------------
// Stage 2: KV[bh] += K^T (Vh+Vl) via fp16 tensor cores; Ksum via ones MMA.
// ---------------------------------------------------------------------------
__global__ __launch_bounds__(128) void kv_tc() {
    extern __shared__ char smem[];
    const uint32_t sbase = smem_u32(smem);
    const int bh = blockIdx.x;
    const int b = bh >> 3, h = bh & 7;
    const int s0 = blockIdx.y * 1024;
    const int tid = threadIdx.x;
    const int lane = tid & 31, w = tid >> 5;

    const __half* __restrict__ kf = g_K  + ((size_t)(b * Ll + s0)) * Cc + h * 64;
    const __half* __restrict__ vh = g_Vh + ((size_t)(b * Ll + s0)) * Cc + h * 64;
    const __half* __restrict__ vl = g_Vl + ((size_t)(b * Ll + s0)) * Cc + h * 64;

    auto issue = [&](int st, int buf) {
        uint32_t sb = sbase + buf * KV_STAGE;
#pragma unroll
        for (int i = 0; i < 4; i++) {
            int idx = tid + i * 128;
            int row = idx >> 3, c16 = idx & 7;
            uint32_t off = SWZ128((uint32_t)(row * 128 + c16 * 16));
            size_t src = (size_t)(st * 64 + row) * Cc + c16 * 8;
            cpa16(sb + off,         kf + src);
            cpa16(sb + 8192 + off,  vh + src);
            cpa16(sb + 16384 + off, vl + src);
        }
        cp_commit();
    };

    issue(0, 0);
    issue(1, 1);

    float accK[8][4], accS[4];
#pragma unroll
    for (int t = 0; t < 8; t++)
#pragma unroll
        for (int q = 0; q < 4; q++) accK[t][q] = 0.f;
#pragma unroll
    for (int q = 0; q < 4; q++) accS[q] = 0.f;

    const uint32_t ones = ((lane >> 2) == 0) ? 0x3C003C00u : 0u;  // fp16 1.0 pair
    uint32_t onef[2] = {ones, ones};

    const uint32_t a_col = (uint32_t)((w * 16 + ((lane >> 4) << 3)) * 2);

    for (int st = 0; st < 16; st++) {
        cp_wait<1>();
        __syncthreads();
        if (st + 2 < 16) issue(st + 2, (st + 2) % 3);
        else cp_commit();

        uint32_t sb = sbase + (st % 3) * KV_STAGE;
#pragma unroll
        for (int s16 = 0; s16 < 4; s16++) {
            uint32_t rowb = (uint32_t)((s16 * 16 + (lane & 15)) * 128);
            uint32_t offA = SWZ128(rowb + a_col);
            uint32_t rk[4];
            ldm4t(rk, sb + offA);
            uint32_t Ah[4] = {rk[0], rk[2], rk[1], rk[3]};
            uint32_t bhf[4][4], blf[4][4];
#pragma unroll
            for (int g = 0; g < 4; g++) {
                uint32_t offV = SWZ128(rowb + (uint32_t)((g * 16 + ((lane >> 4) << 3)) * 2));
                ldm4t(bhf[g], sb + 8192 + offV);
                ldm4t(blf[g], sb + 16384 + offV);
            }
#pragma unroll
            for (int t = 0; t < 8; t++)
                mma16816h(accK[t], Ah, &bhf[t >> 1][(t & 1) * 2]);
#pragma unroll
            for (int t = 0; t < 8; t++)
                mma16816h(accK[t], Ah, &blf[t >> 1][(t & 1) * 2]);
            mma16816h(accS, Ah, onef);
        }
    }

    const int d0 = w * 16 + (lane >> 2);
    float* KVp = g_KV + (size_t)bh * 4096;
#pragma unroll
    for (int t = 0; t < 8; t++) {
        int v = t * 8 + (lane & 3) * 2;
        atomicAdd(KVp + d0 * 64 + v,           accK[t][0]);
        atomicAdd(KVp + d0 * 64 + v + 1,       accK[t][1]);
        atomicAdd(KVp + (d0 + 8) * 64 + v,     accK[t][2]);
        atomicAdd(KVp + (d0 + 8) * 64 + v + 1, accK[t][3]);
    }
    if ((lane & 3) == 0) {
        atomicAdd(g_Ksum + bh * 64 + d0,     accS[0]);
        atomicAdd(g_Ksum + bh * 64 + d0 + 8, accS[2]);
    }
}

// ---------------------------------------------------------------------------
// Finalize: KVt[bh][v][d] = KV[bh][d][v] as fp16 hi/lo; row 64 = Ksum; 65-79 = 0.
// ---------------------------------------------------------------------------
__global__ void kv_finalize() {
    const int bh = blockIdx.x;
    const int v = threadIdx.x;   // 0..63
    __half* oh = g_KVth + (size_t)bh * 80 * 64;
    __half* ol = g_KVtl + (size_t)bh * 80 * 64;
    const float* kv = g_KV + (size_t)bh * 4096;
#pragma unroll 8
    for (int d = 0; d < 64; d++) {
        __half h, l;
        split2h(kv[d * 64 + v], h, l);
        oh[v * 64 + d] = h;
        ol[v * 64 + d] = l;
    }
    __half h, l;
    split2h(g_Ksum[bh * 64 + v], h, l);
    oh[64 * 64 + v] = h;
    ol[64 * 64 + v] = l;
#pragma unroll
    for (int r = 65; r < 80; r++) {
        oh[r * 64 + v] = __float2half(0.f);
        ol[r * 64 + v] = __float2half(0.f);
    }
}

// ---------------------------------------------------------------------------
// Stage 3: out = (Q @ (KVh+KVl)) with normalizer from column 64.
// ---------------------------------------------------------------------------
__global__ __launch_bounds__(128) void out_tc(float* __restrict__ out) {
    extern __shared__ char smem[];
    const uint32_t sbase = smem_u32(smem);
    const int bh = blockIdx.x;
    const int b = bh >> 3, h = bh & 7;
    const int l0 = blockIdx.y * 128;
    const int tid = threadIdx.x;
    const int lane = tid & 31, w = tid >> 5;

    {
        const __half* qf = g_Q + ((size_t)(b * Ll + l0)) * Cc + h * 64;
#pragma unroll
        for (int i = 0; i < 8; i++) {
            int idx = tid + i * 128;
            int row = idx >> 3, c16 = idx & 7;
            uint32_t off = SWZ128((uint32_t)(row * 128 + c16 * 16));
            cpa16(sbase + off, qf + (size_t)row * Cc + c16 * 8);
        }
        const __half* bhp = g_KVth + (size_t)bh * 80 * 64;
        const __half* blp = g_KVtl + (size_t)bh * 80 * 64;
#pragma unroll
        for (int i = 0; i < 5; i++) {
            int idx = tid + i * 128;
            int row = idx >> 3, c16 = idx & 7;
            uint32_t off = SWZ128((uint32_t)(row * 128 + c16 * 16));
            size_t src = (size_t)row * 64 + c16 * 8;
            cpa16(sbase + 16384 + off, bhp + src);
            cpa16(sbase + 26624 + off, blp + src);
        }
        cp_commit();
        cp_wait<0>();
        __syncthreads();
    }

    float acc[2][9][4];
#pragma unroll
    for (int im = 0; im < 2; im++)
#pragma unroll
        for (int t = 0; t < 9; t++)
#pragma unroll
            for (int q = 0; q < 4; q++) acc[im][t][q] = 0.f;

    const uint32_t a_k = (uint32_t)((lane >> 4) * 16);
    const int brow = (lane & 7) + ((lane >> 4) << 3);
    const uint32_t b_k = (uint32_t)(((lane >> 3) & 1) * 16);

#pragma unroll
    for (int ks = 0; ks < 4; ks++) {
        uint32_t aH[2][4];
#pragma unroll
        for (int im = 0; im < 2; im++) {
            int ar = w * 32 + im * 16 + (lane & 15);
            uint32_t ka = ((uint32_t)(ks * 32) + a_k) ^ ((uint32_t)((ar & 7) * 16));
            ldm4(aH[im], sbase + (uint32_t)ar * 128 + ka);
        }
        uint32_t bH[5][4], bL[5][4];
#pragma unroll
        for (int g = 0; g < 5; g++) {
            int br = g * 16 + brow;
            uint32_t kb = ((uint32_t)(ks * 32) + b_k) ^ ((uint32_t)((br & 7) * 16));
            ldm4(bH[g], sbase + 16384 + (uint32_t)br * 128 + kb);
            ldm4(bL[g], sbase + 26624 + (uint32_t)br * 128 + kb);
        }
#pragma unroll
        for (int im = 0; im < 2; im++)
#pragma unroll
            for (int t = 0; t < 9; t++)
                mma16816h(acc[im][t], aH[im], &bH[t >> 1][(t & 1) * 2]);
#pragma unroll
        for (int im = 0; im < 2; im++)
#pragma unroll
            for (int t = 0; t < 9; t++)
                mma16816h(acc[im][t], aH[im], &bL[t >> 1][(t & 1) * 2]);
    }

#pragma unroll
    for (int im = 0; im < 2; im++) {
        float den0 = __shfl_sync(0xffffffffu, acc[im][8][0], lane & ~3);
        float den1 = __shfl_sync(0xffffffffu, acc[im][8][2], lane & ~3);
        float z0 = 1.f / (den0 + 1e-6f);
        float z1 = 1.f / (den1 + 1e-6f);
        int r0 = w * 32 + im * 16 + (lane >> 2);
        float* o0 = out + ((size_t)(b * Ll + l0 + r0)) * Cc + h * 64 + (lane & 3) * 2;
        float* o1 = out + ((size_t)(b * Ll + l0 + r0 + 8)) * Cc + h * 64 + (lane & 3) * 2;
#pragma unroll
        for (int t = 0; t < 8; t++) {
            *reinterpret_cast<float2*>(o0 + t * 8) =
                make_float2(acc[im][t][0] * z0, acc[im][t][1] * z0);
            *reinterpret_cast<float2*>(o1 + t * 8) =
                make_float2(acc[im][t][2] * z1, acc[im][t][3] * z1);
        }
    }
}

// ---------------------------------------------------------------------------
extern "C" void kernel_launch(void* const* d_in, const int* in_sizes, int n_in,
                              void* d_out, int out_size) {
    const float* x  = (const float*)d_in[0];
    const float* Wq = (const float*)d_in[1];
    const float* bq = (const float*)d_in[2];
    const float* Wk = (const float*)d_in[3];
    const float* bk = (const float*)d_in[4];
    const float* Wv = (const float*)d_in[5];
    const float* bv = (const float*)d_in[6];
    float* out = (float*)d_out;

    cudaFuncSetAttribute(qkv_gemm_tc, cudaFuncAttributeMaxDynamicSharedMemorySize, QSMEM);
    cudaFuncSetAttribute(kv_tc, cudaFuncAttributeMaxDynamicSharedMemorySize, KV_SMEM);
    cudaFuncSetAttribute(out_tc, cudaFuncAttributeMaxDynamicSharedMemorySize, OUT_SMEM);

    zero_acc_kernel<<<512, 256>>>();
    prep_x<<<(int)(((size_t)MM * Cc) / 1024), 256>>>(x);
    prep_w<<<dim3(3, Cc), 128>>>(Wq, Wk, Wv);
    qkv_gemm_tc<<<dim3(12, MM / 128), 128, QSMEM>>>(bq, bk, bv);
    kv_tc<<<dim3(BHn, 16), 128, KV_SMEM>>>();
    kv_finalize<<<BHn, 64>>>();
    out_tc<<<dim3(BHn, Ll / 128), 128, OUT_SMEM>>>(out);
}

// round 11
// speedup vs baseline: 7.9462x; 1.1548x over previous
#include <cuda_runtime.h>
#include <cuda_fp16.h>
#include <cstdint>
#include <math.h>

#define Bb 4
#define Ll 16384
#define Cc 512
#define Hh 8
#define Dd 64
#define MM (Bb*Ll)      // 65536
#define BHn (Bb*Hh)     // 32

// Stage-1: 128x128 tile, BK=64, 3 stages, 2 CTA/SM, 256 threads (warp tile 32x64)
#define QSTAGE 32768     // A 16K | B 16K
#define QSMEM (3*QSTAGE)
#define QNIT 8           // 512/64

// kv_tc smem: stage = K 8K | V 8K = 16K, 3 stages
#define KV_STAGE 16384
#define KV_SMEM (3*KV_STAGE)
// out_tc smem: Q 16K | B 10K
#define OUT_SMEM (16384 + 10240)

// Scratch (all fp16)
__device__ __half g_Xh[(size_t)MM*Cc];            // X
__device__ __half g_Wth[3*(size_t)Cc*Cc];         // W^T, [z][n][k]
__device__ __half g_Q [(size_t)MM*Cc];            // feature-mapped Q
__device__ __half g_K [(size_t)MM*Cc];            // feature-mapped K
__device__ __half g_V [(size_t)MM*Cc];            // V
__device__ float g_KV[BHn*Dd*Dd];
__device__ float g_Ksum[BHn*Dd];
__device__ __half g_KVt[(size_t)BHn*80*64];       // [bh][v-row(80)][d], row64=Ksum

// ---------------------------------------------------------------------------
__device__ __forceinline__ uint32_t smem_u32(const void* p) {
    uint32_t a;
    asm("{ .reg .u64 t; cvta.to.shared.u64 t, %1; cvt.u32.u64 %0, t; }" : "=r"(a) : "l"(p));
    return a;
}
#define SWZ128(o) ((o) ^ (((o) >> 3) & 0x70))

__device__ __forceinline__ void cpa16(uint32_t d, const void* s) {
    uint64_t gp;
    asm("cvta.to.global.u64 %0, %1;" : "=l"(gp) : "l"(s));
    asm volatile("cp.async.cg.shared.global [%0], [%1], 16;" :: "r"(d), "l"(gp) : "memory");
}
__device__ __forceinline__ void cp_commit() {
    asm volatile("cp.async.commit_group;" ::: "memory");
}
template<int N> __device__ __forceinline__ void cp_wait() {
    asm volatile("cp.async.wait_group %0;" :: "n"(N) : "memory");
}
__device__ __forceinline__ void ldm4(uint32_t* r, uint32_t a) {
    asm volatile("ldmatrix.sync.aligned.m8n8.x4.shared.b16 {%0,%1,%2,%3}, [%4];"
        : "=r"(r[0]), "=r"(r[1]), "=r"(r[2]), "=r"(r[3]) : "r"(a));
}
__device__ __forceinline__ void ldm4t(uint32_t* r, uint32_t a) {
    asm volatile("ldmatrix.sync.aligned.m8n8.x4.trans.shared.b16 {%0,%1,%2,%3}, [%4];"
        : "=r"(r[0]), "=r"(r[1]), "=r"(r[2]), "=r"(r[3]) : "r"(a));
}
__device__ __forceinline__ void mma16816h(float* c, const uint32_t* a, const uint32_t* b) {
    asm volatile("mma.sync.aligned.m16n8k16.row.col.f32.f16.f16.f32 "
        "{%0,%1,%2,%3}, {%4,%5,%6,%7}, {%8,%9}, {%0,%1,%2,%3};"
        : "+f"(c[0]), "+f"(c[1]), "+f"(c[2]), "+f"(c[3])
        : "r"(a[0]), "r"(a[1]), "r"(a[2]), "r"(a[3]), "r"(b[0]), "r"(b[1]));
}
__device__ __forceinline__ uint32_t pack_h16(__half a, __half b) {
    __half2 t(a, b);
    return *reinterpret_cast<uint32_t*>(&t);
}

// ---------------------------------------------------------------------------
__global__ void zero_acc_kernel() {
    int i = blockIdx.x * blockDim.x + threadIdx.x;
    if (i < BHn * Dd * Dd) g_KV[i] = 0.f;
    if (i < BHn * Dd)      g_Ksum[i] = 0.f;
}

__global__ void prep_x(const float* __restrict__ X) {
    size_t i = ((size_t)blockIdx.x * 256 + threadIdx.x) * 4;
    float4 v = *reinterpret_cast<const float4*>(X + i);
    *reinterpret_cast<uint2*>(g_Xh + i) = make_uint2(
        pack_h16(__float2half(v.x), __float2half(v.y)),
        pack_h16(__float2half(v.z), __float2half(v.w)));
}

__global__ void prep_w(const float* __restrict__ Wq, const float* __restrict__ Wk,
                       const float* __restrict__ Wv) {
    const int z = blockIdx.x, n = blockIdx.y;
    const float* W = (z == 0) ? Wq : ((z == 1) ? Wk : Wv);
    __half* dh = g_Wth + ((size_t)z * Cc + n) * Cc;
    int k0 = threadIdx.x * 4;
#pragma unroll
    for (int j = 0; j < 4; j++)
        dh[k0 + j] = __float2half(W[(size_t)(k0 + j) * Cc + n]);
}

// ---------------------------------------------------------------------------
// Stage 1: QKV fp16 GEMM: out = X @ W (fp32 accum).
// 256-thread CTAs, warp grid 4m x 2n, warp tile 32x64, BK=64, 3-stage ring,
// 2 CTAs/SM (16 warps/SM = 4 warps/SMSP across 2 barrier domains).
// ---------------------------------------------------------------------------
__global__ __launch_bounds__(256, 2) void qkv_gemm_tc(
    const float* __restrict__ bq, const float* __restrict__ bk,
    const float* __restrict__ bv)
{
    extern __shared__ char smem[];
    const uint32_t sbase = smem_u32(smem);
    const int tid = threadIdx.x;
    const int z = blockIdx.x >> 2;
    const int col0 = (blockIdx.x & 3) * 128;
    const int row0 = blockIdx.y * 128;
    const int lane = tid & 31, wid = tid >> 5;
    const int wm = (wid & 3) * 32;
    const int wn = (wid >> 2) * 64;

    const __half* __restrict__ Bh_g = g_Wth + (size_t)z * Cc * Cc;
    const float* __restrict__ bias = (z == 0) ? bq : ((z == 1) ? bk : bv);

    auto issue_half = [&](int kidx, int buf, int half) {
        uint32_t sb = sbase + buf * QSTAGE + (uint32_t)half * 16384;
        int k0 = kidx * 64;
#pragma unroll
        for (int i = 0; i < 4; i++) {
            int idx = tid + i * 256;          // 0..1023
            int r = idx >> 3;
            int c = idx & 7;
            uint32_t off = SWZ128((uint32_t)(r * 128 + c * 16));
            const __half* src = (half == 0)
                ? g_Xh  + (size_t)(row0 + r) * Cc + k0 + c * 8
                : Bh_g  + (size_t)(col0 + r) * Cc + k0 + c * 8;
            cpa16(sb + off, src);
        }
    };

    issue_half(0, 0, 0); issue_half(0, 0, 1); cp_commit();
    issue_half(1, 1, 0); issue_half(1, 1, 1); cp_commit();

    float acc[2][8][4];
#pragma unroll
    for (int i = 0; i < 2; i++)
#pragma unroll
        for (int j = 0; j < 8; j++)
#pragma unroll
            for (int q = 0; q < 4; q++) acc[i][j][q] = 0.f;

    const uint32_t a_k = (uint32_t)((lane >> 4) * 16);
    uint32_t a_rb[2], a_rx[2];
#pragma unroll
    for (int mf = 0; mf < 2; mf++) {
        int ar = wm + mf * 16 + (lane & 15);
        a_rb[mf] = (uint32_t)(ar * 128);
        a_rx[mf] = (uint32_t)((ar & 7) * 16);
    }
    const int b_row_in = (lane & 7) + ((lane >> 4) << 3);
    const uint32_t b_k = (uint32_t)(((lane >> 3) & 1) * 16);
    uint32_t b_rb[4], b_rx[4];
#pragma unroll
    for (int g = 0; g < 4; g++) {
        int br = wn + g * 16 + b_row_in;
        b_rb[g] = (uint32_t)(br * 128) + 16384;
        b_rx[g] = (uint32_t)((br & 7) * 16);
    }

    for (int it = 0; it < QNIT; it++) {
        cp_wait<1>();
        __syncthreads();
        uint32_t sb = sbase + (it % 3) * QSTAGE;
        const bool pre = (it + 2 < QNIT);
        const int pk = it + 2;
        const int pb = (it + 2) % 3;

#pragma unroll
        for (int ks = 0; ks < 4; ks++) {
            const uint32_t kc = (uint32_t)(ks * 32);
            uint32_t ah[2][4];
#pragma unroll
            for (int mf = 0; mf < 2; mf++)
                ldm4(ah[mf], sb + a_rb[mf] + ((kc + a_k) ^ a_rx[mf]));
            uint32_t bh[4][4];
#pragma unroll
            for (int g = 0; g < 4; g++)
                ldm4(bh[g], sb + b_rb[g] + ((kc + b_k) ^ b_rx[g]));
#pragma unroll
            for (int mf = 0; mf < 2; mf++)
#pragma unroll
                for (int jj = 0; jj < 8; jj++)
                    mma16816h(acc[mf][jj], ah[mf], &bh[jj >> 1][(jj & 1) * 2]);
            if (pre && ks < 2) issue_half(pk, pb, ks);
            if (ks == 1) cp_commit();
        }
    }

    // Epilogue: bias + feature map (Q,K); all outputs single fp16
    __half* outp = (z == 0) ? g_Q : ((z == 1) ? g_K : g_V);
    const int gq = lane >> 2, tq = lane & 3;
#pragma unroll
    for (int mf = 0; mf < 2; mf++) {
#pragma unroll
        for (int hh = 0; hh < 2; hh++) {
            int mg = row0 + wm + mf * 16 + gq + hh * 8;
#pragma unroll
            for (int j = 0; j < 8; j++) {
                int cg = col0 + wn + j * 8 + tq * 2;
                float v0 = acc[mf][j][hh * 2 + 0] + __ldg(bias + cg);
                float v1 = acc[mf][j][hh * 2 + 1] + __ldg(bias + cg + 1);
                if (z < 2) {
                    v0 = (v0 > 0.f) ? (v0 + 1.f) : __expf(v0);
                    v1 = (v1 > 0.f) ? (v1 + 1.f) : __expf(v1);
                }
                *reinterpret_cast<uint32_t*>(outp + (size_t)mg * Cc + cg) =
                    pack_h16(__float2half(v0), __float2half(v1));
            }
        }
    }
}

// ---------------------------------------------------------------------------
// Stage 2: KV[bh] += K^T V via fp16 tensor cores; Ksum via ones MMA.
// ---------------------------------------------------------------------------
__global__ __launch_bounds__(128) void kv_tc() {
    extern __shared__ char smem[];
    const uint32_t sbase = smem_u32(smem);
    const int bh = blockIdx.x;
    const int b = bh >> 3, h = bh & 7;
    const int s0 = blockIdx.y * 1024;
    const int tid = threadIdx.x;
    const int lane = tid & 31, w = tid >> 5;

    const __half* __restrict__ kf = g_K + ((size_t)(b * Ll + s0)) * Cc + h * 64;
    const __half* __restrict__ vf = g_V + ((size_t)(b * Ll + s0)) * Cc + h * 64;

    auto issue = [&](int st, int buf) {
        uint32_t sb = sbase + buf * KV_STAGE;
#pragma unroll
        for (int i = 0; i < 8; i++) {
            int idx = tid + i * 128;          // 0..1023
            int mat = idx >> 9;
            int row = (idx >> 3) & 63, c16 = idx & 7;
            uint32_t off = SWZ128((uint32_t)(row * 128 + c16 * 16)) + (uint32_t)mat * 8192;
            size_t src = (size_t)(st * 64 + row) * Cc + c16 * 8;
            cpa16(sb + off, (mat ? vf : kf) + src);
        }
        cp_commit();
    };

    issue(0, 0);
    issue(1, 1);

    float accK[8][4], accS[4];
#pragma unroll
    for (int t = 0; t < 8; t++)
#pragma unroll
        for (int q = 0; q < 4; q++) accK[t][q] = 0.f;
#pragma unroll
    for (int q = 0; q < 4; q++) accS[q] = 0.f;

    const uint32_t ones = ((lane >> 2) == 0) ? 0x3C003C00u : 0u;  // fp16 1.0 pair
    uint32_t onef[2] = {ones, ones};

    const uint32_t a_col = (uint32_t)((w * 16 + ((lane >> 4) << 3)) * 2);

    for (int st = 0; st < 16; st++) {
        cp_wait<1>();
        __syncthreads();
        if (st + 2 < 16) issue(st + 2, (st + 2) % 3);
        else cp_commit();

        uint32_t sb = sbase + (st % 3) * KV_STAGE;
#pragma unroll
        for (int s16 = 0; s16 < 4; s16++) {
            uint32_t rowb = (uint32_t)((s16 * 16 + (lane & 15)) * 128);
            uint32_t offA = SWZ128(rowb + a_col);
            uint32_t rk[4];
            ldm4t(rk, sb + offA);
            uint32_t Ah[4] = {rk[0], rk[2], rk[1], rk[3]};
            uint32_t bvf[4][4];
#pragma unroll
            for (int g = 0; g < 4; g++) {
                uint32_t offV = SWZ128(rowb + (uint32_t)((g * 16 + ((lane >> 4) << 3)) * 2));
                ldm4t(bvf[g], sb + 8192 + offV);
            }
#pragma unroll
            for (int t = 0; t < 8; t++)
                mma16816h(accK[t], Ah, &bvf[t >> 1][(t & 1) * 2]);
            mma16816h(accS, Ah, onef);
        }
    }

    const int d0 = w * 16 + (lane >> 2);
    float* KVp = g_KV + (size_t)bh * 4096;
#pragma unroll
    for (int t = 0; t < 8; t++) {
        int v = t * 8 + (lane & 3) * 2;
        atomicAdd(KVp + d0 * 64 + v,           accK[t][0]);
        atomicAdd(KVp + d0 * 64 + v + 1,       accK[t][1]);
        atomicAdd(KVp + (d0 + 8) * 64 + v,     accK[t][2]);
        atomicAdd(KVp + (d0 + 8) * 64 + v + 1, accK[t][3]);
    }
    if ((lane & 3) == 0) {
        atomicAdd(g_Ksum + bh * 64 + d0,     accS[0]);
        atomicAdd(g_Ksum + bh * 64 + d0 + 8, accS[2]);
    }
}

// ---------------------------------------------------------------------------
// Finalize: KVt[bh][v][d] = KV[bh][d][v] fp16; row 64 = Ksum; rows 65-79 = 0.
// ---------------------------------------------------------------------------
__global__ void kv_finalize() {
    const int bh = blockIdx.x;
    const int v = threadIdx.x;   // 0..63
    __half* oh = g_KVt + (size_t)bh * 80 * 64;
    const float* kv = g_KV + (size_t)bh * 4096;
#pragma unroll 8
    for (int d = 0; d < 64; d++)
        oh[v * 64 + d] = __float2half(kv[d * 64 + v]);
    oh[64 * 64 + v] = __float2half(g_Ksum[bh * 64 + v]);
#pragma unroll
    for (int r = 65; r < 80; r++)
        oh[r * 64 + v] = __float2half(0.f);
}

// ---------------------------------------------------------------------------
// Stage 3: out = (Q @ KVt) with normalizer from column 64.
// ---------------------------------------------------------------------------
__global__ __launch_bounds__(128) void out_tc(float* __restrict__ out) {
    extern __shared__ char smem[];
    const uint32_t sbase = smem_u32(smem);
    const int bh = blockIdx.x;
    const int b = bh >> 3, h = bh & 7;
    const int l0 = blockIdx.y * 128;
    const int tid = threadIdx.x;
    const int lane = tid & 31, w = tid >> 5;

    {
        const __half* qf = g_Q + ((size_t)(b * Ll + l0)) * Cc + h * 64;
#pragma unroll
        for (int i = 0; i < 8; i++) {
            int idx = tid + i * 128;
            int row = idx >> 3, c16 = idx & 7;
            uint32_t off = SWZ128((uint32_t)(row * 128 + c16 * 16));
            cpa16(sbase + off, qf + (size_t)row * Cc + c16 * 8);
        }
        const __half* bhp = g_KVt + (size_t)bh * 80 * 64;
#pragma unroll
        for (int i = 0; i < 5; i++) {
            int idx = tid + i * 128;
            int row = idx >> 3, c16 = idx & 7;
            uint32_t off = SWZ128((uint32_t)(row * 128 + c16 * 16));
            cpa16(sbase + 16384 + off, bhp + (size_t)row * 64 + c16 * 8);
        }
        cp_commit();
        cp_wait<0>();
        __syncthreads();
    }

    float acc[2][9][4];
#pragma unroll
    for (int im = 0; im < 2; im++)
#pragma unroll
        for (int t = 0; t < 9; t++)
#pragma unroll
            for (int q = 0; q < 4; q++) acc[im][t][q] = 0.f;

    const uint32_t a_k = (uint32_t)((lane >> 4) * 16);
    const int brow = (lane & 7) + ((lane >> 4) << 3);
    const uint32_t b_k = (uint32_t)(((lane >> 3) & 1) * 16);

#pragma unroll
    for (int ks = 0; ks < 4; ks++) {
        uint32_t aH[2][4];
#pragma unroll
        for (int im = 0; im < 2; im++) {
            int ar = w * 32 + im * 16 + (lane & 15);
            uint32_t ka = ((uint32_t)(ks * 32) + a_k) ^ ((uint32_t)((ar & 7) * 16));
            ldm4(aH[im], sbase + (uint32_t)ar * 128 + ka);
        }
        uint32_t bH[5][4];
#pragma unroll
        for (int g = 0; g < 5; g++) {
            int br = g * 16 + brow;
            uint32_t kb = ((uint32_t)(ks * 32) + b_k) ^ ((uint32_t)((br & 7) * 16));
            ldm4(bH[g], sbase + 16384 + (uint32_t)br * 128 + kb);
        }
#pragma unroll
        for (int im = 0; im < 2; im++)
#pragma unroll
            for (int t = 0; t < 9; t++)
                mma16816h(acc[im][t], aH[im], &bH[t >> 1][(t & 1) * 2]);
    }

#pragma unroll
    for (int im = 0; im < 2; im++) {
        float den0 = __shfl_sync(0xffffffffu, acc[im][8][0], lane & ~3);
        float den1 = __shfl_sync(0xffffffffu, acc[im][8][2], lane & ~3);
        float z0 = 1.f / (den0 + 1e-6f);
        float z1 = 1.f / (den1 + 1e-6f);
        int r0 = w * 32 + im * 16 + (lane >> 2);
        float* o0 = out + ((size_t)(b * Ll + l0 + r0)) * Cc + h * 64 + (lane & 3) * 2;
        float* o1 = out + ((size_t)(b * Ll + l0 + r0 + 8)) * Cc + h * 64 + (lane & 3) * 2;
#pragma unroll
        for (int t = 0; t < 8; t++) {
            *reinterpret_cast<float2*>(o0 + t * 8) =
                make_float2(acc[im][t][0] * z0, acc[im][t][1] * z0);
            *reinterpret_cast<float2*>(o1 + t * 8) =
                make_float2(acc[im][t][2] * z1, acc[im][t][3] * z1);
        }
    }
}

// ---------------------------------------------------------------------------
extern "C" void kernel_launch(void* const* d_in, const int* in_sizes, int n_in,
                              void* d_out, int out_size) {
    const float* x  = (const float*)d_in[0];
    const float* Wq = (const float*)d_in[1];
    const float* bq = (const float*)d_in[2];
    const float* Wk = (const float*)d_in[3];
    const float* bk = (const float*)d_in[4];
    const float* Wv = (const float*)d_in[5];
    const float* bv = (const float*)d_in[6];
    float* out = (float*)d_out;

    cudaFuncSetAttribute(qkv_gemm_tc, cudaFuncAttributeMaxDynamicSharedMemorySize, QSMEM);
    cudaFuncSetAttribute(kv_tc, cudaFuncAttributeMaxDynamicSharedMemorySize, KV_SMEM);
    cudaFuncSetAttribute(out_tc, cudaFuncAttributeMaxDynamicSharedMemorySize, OUT_SMEM);

    zero_acc_kernel<<<512, 256>>>();
    prep_x<<<(int)(((size_t)MM * Cc) / 1024), 256>>>(x);
    prep_w<<<dim3(3, Cc), 128>>>(Wq, Wk, Wv);
    qkv_gemm_tc<<<dim3(12, MM / 128), 256, QSMEM>>>(bq, bk, bv);
    kv_tc<<<dim3(BHn, 16), 128, KV_SMEM>>>();
    kv_finalize<<<BHn, 64>>>();
    out_tc<<<dim3(BHn, Ll / 128), 128, OUT_SMEM>>>(out);
}